// round 1
// baseline (speedup 1.0000x reference)
#include <cuda_runtime.h>
#include <cstdint>
#include <cstddef>

#define BSZ 2
#define SEQ 2048
#define DIM 2048
#define NH 32
#define NKV 8
#define HD 64
#define QKV_N ((NH + 2*NKV)*HD)   // 3072

// ---------------- scratch (static device globals; no allocation) -----------
__device__ float g_qkv[(size_t)BSZ*SEQ*QKV_N];     // [4096, 3072]
__device__ float g_q  [(size_t)BSZ*NH *SEQ*HD];    // [b,h,s,d]
__device__ float g_k  [(size_t)BSZ*NKV*SEQ*HD];    // [b,kv,s,d]
__device__ float g_v  [(size_t)BSZ*NKV*SEQ*HD];    // [b,kv,s,d]
__device__ float g_ao [(size_t)BSZ*SEQ*DIM];       // [4096, 2048] = [b,s,h*d]

// ---------------- GEMM: C[M,N] = A[M,K] * B[N,K]^T (both row-major) --------
#define BM 128
#define BN 128
#define BK 16
#define SSTR (BM + 4)

__global__ __launch_bounds__(256)
void gemm_nt_kernel(const float* __restrict__ A, const float* __restrict__ B,
                    float* __restrict__ C, int M, int N, int K)
{
    __shared__ float As[BK][SSTR];
    __shared__ float Bs[BK][SSTR];

    const int t    = threadIdx.x;
    const int bm   = blockIdx.y * BM;
    const int bn   = blockIdx.x * BN;
    const int wid  = t >> 5, lane = t & 31;
    const int wy   = wid & 3,  wx  = wid >> 2;     // 4 row-warps x 2 col-warps
    const int ly   = lane >> 3, lx = lane & 7;
    const int ra   = wy * 32 + ly * 8;             // row offset of 8-row strip
    const int cb   = wx * 64 + lx * 8;             // col offset of 8-col strip

    const int row0 = t >> 2;                       // 0..63 (plus +64 2nd pass)
    const int k4   = (t & 3) * 4;

    float acc[8][8];
#pragma unroll
    for (int i = 0; i < 8; ++i)
#pragma unroll
        for (int j = 0; j < 8; ++j) acc[i][j] = 0.f;

    for (int k0 = 0; k0 < K; k0 += BK) {
#pragma unroll
        for (int i = 0; i < 2; ++i) {
            int row = row0 + i * 64;
            float4 va = *(const float4*)&A[(size_t)(bm + row) * K + k0 + k4];
            As[k4+0][row] = va.x; As[k4+1][row] = va.y;
            As[k4+2][row] = va.z; As[k4+3][row] = va.w;
            float4 vb = *(const float4*)&B[(size_t)(bn + row) * K + k0 + k4];
            Bs[k4+0][row] = vb.x; Bs[k4+1][row] = vb.y;
            Bs[k4+2][row] = vb.z; Bs[k4+3][row] = vb.w;
        }
        __syncthreads();
#pragma unroll
        for (int k = 0; k < BK; ++k) {
            float a[8], b[8];
            *(float4*)&a[0] = *(const float4*)&As[k][ra];
            *(float4*)&a[4] = *(const float4*)&As[k][ra + 4];
            *(float4*)&b[0] = *(const float4*)&Bs[k][cb];
            *(float4*)&b[4] = *(const float4*)&Bs[k][cb + 4];
#pragma unroll
            for (int i = 0; i < 8; ++i)
#pragma unroll
                for (int j = 0; j < 8; ++j)
                    acc[i][j] = fmaf(a[i], b[j], acc[i][j]);
        }
        __syncthreads();
    }

#pragma unroll
    for (int i = 0; i < 8; ++i) {
        float* crow = &C[(size_t)(bm + ra + i) * N + bn + cb];
        *(float4*)&crow[0] = make_float4(acc[i][0], acc[i][1], acc[i][2], acc[i][3]);
        *(float4*)&crow[4] = make_float4(acc[i][4], acc[i][5], acc[i][6], acc[i][7]);
    }
}

// ---------------- RoPE scatter + V transpose --------------------------------
__global__ void rope_q_kernel(const float* __restrict__ fc)
{
    int gid = blockIdx.x * 256 + threadIdx.x;     // ((b*S+s)*NH+h)*32+p, exact
    int p = gid & 31;
    int h = (gid >> 5) & 31;
    int s = (gid >> 10) & 2047;
    int b = gid >> 21;
    const float* src = g_qkv + (size_t)(b * SEQ + s) * QKV_N + h * HD + 2 * p;
    float x0 = src[0], x1 = src[1];
    float c  = fc[s * HD + 2 * p];
    float sn = fc[s * HD + 2 * p + 1];
    float* dst = g_q + (((size_t)(b * NH + h)) * SEQ + s) * HD + 2 * p;
    dst[0] = x0 * c - x1 * sn;
    dst[1] = x1 * c + x0 * sn;
}

__global__ void rope_k_kernel(const float* __restrict__ fc)
{
    int gid = blockIdx.x * 256 + threadIdx.x;     // ((b*S+s)*NKV+kv)*32+p
    int p  = gid & 31;
    int kv = (gid >> 5) & 7;
    int s  = (gid >> 8) & 2047;
    int b  = gid >> 19;
    const float* src = g_qkv + (size_t)(b * SEQ + s) * QKV_N + DIM + kv * HD + 2 * p;
    float x0 = src[0], x1 = src[1];
    float c  = fc[s * HD + 2 * p];
    float sn = fc[s * HD + 2 * p + 1];
    float* dst = g_k + (((size_t)(b * NKV + kv)) * SEQ + s) * HD + 2 * p;
    dst[0] = x0 * c - x1 * sn;
    dst[1] = x1 * c + x0 * sn;
}

__global__ void copy_v_kernel()
{
    int gid = blockIdx.x * 256 + threadIdx.x;     // float4 granularity
    int d4 = gid & 15;
    int kv = (gid >> 4) & 7;
    int s  = (gid >> 7) & 2047;
    int b  = gid >> 18;
    const float* src = g_qkv + (size_t)(b * SEQ + s) * QKV_N + DIM + NKV * HD + kv * HD + d4 * 4;
    float* dst = g_v + (((size_t)(b * NKV + kv)) * SEQ + s) * HD + d4 * 4;
    *(float4*)dst = *(const float4*)src;
}

// ---------------- flash attention (64x64 tiles, online softmax) -------------
__global__ __launch_bounds__(256)
void flash_kernel()
{
    __shared__ float sQ [64 * 64];   // d-major: sQ[d*64 + r], pre-scaled
    __shared__ float sKP[64 * 64];   // phase 1: K d-major sKP[d*64+c]; phase 2: P r-major
    __shared__ float sV [64 * 64];   // sV[c*64 + d]

    const int t  = threadIdx.x;
    const int qb = blockIdx.x;                    // 0..31
    const int h  = blockIdx.y;                    // 0..31
    const int b  = blockIdx.z;                    // 0..1
    const int kvh = h >> 2;                       // GQA: rep=4
    const int ty = t >> 4, tx = t & 15;           // 16x16 threads, 4x4 each

    // load Q tile once (transposed, scaled by 1/sqrt(64))
    {
        const int r  = t >> 2;
        const int f0 = t & 3;
        const float* qrow = g_q + (((size_t)(b * NH + h)) * SEQ + qb * 64 + r) * HD;
#pragma unroll
        for (int it = 0; it < 4; ++it) {
            int d = (f0 + it * 4) * 4;
            float4 v = *(const float4*)&qrow[d];
            sQ[(d + 0) * 64 + r] = v.x * 0.125f;
            sQ[(d + 1) * 64 + r] = v.y * 0.125f;
            sQ[(d + 2) * 64 + r] = v.z * 0.125f;
            sQ[(d + 3) * 64 + r] = v.w * 0.125f;
        }
    }

    float m[4], l[4], o[4][4];
#pragma unroll
    for (int i = 0; i < 4; ++i) {
        m[i] = -1e30f; l[i] = 0.f;
#pragma unroll
        for (int j = 0; j < 4; ++j) o[i][j] = 0.f;
    }

    const float* Kbase = g_k + ((size_t)(b * NKV + kvh)) * SEQ * HD;
    const float* Vbase = g_v + ((size_t)(b * NKV + kvh)) * SEQ * HD;

    for (int jb = 0; jb <= qb; ++jb) {
        __syncthreads();   // prior iter done reading sKP (as P) and sV
        {
            const int r  = t >> 2;
            const int f0 = t & 3;
            const float* krow = Kbase + (size_t)(jb * 64 + r) * HD;
            const float* vrow = Vbase + (size_t)(jb * 64 + r) * HD;
#pragma unroll
            for (int it = 0; it < 4; ++it) {
                int d = (f0 + it * 4) * 4;
                float4 kvv = *(const float4*)&krow[d];
                sKP[(d + 0) * 64 + r] = kvv.x;
                sKP[(d + 1) * 64 + r] = kvv.y;
                sKP[(d + 2) * 64 + r] = kvv.z;
                sKP[(d + 3) * 64 + r] = kvv.w;
                *(float4*)&sV[r * 64 + d] = *(const float4*)&vrow[d];
            }
        }
        __syncthreads();

        // S = Q K^T (4x4 per thread, rank-1 over d)
        float s[4][4];
#pragma unroll
        for (int i = 0; i < 4; ++i)
#pragma unroll
            for (int j = 0; j < 4; ++j) s[i][j] = 0.f;

#pragma unroll 16
        for (int d = 0; d < 64; ++d) {
            float a[4], bb[4];
            *(float4*)a  = *(const float4*)&sQ [d * 64 + ty * 4];
            *(float4*)bb = *(const float4*)&sKP[d * 64 + tx * 4];
#pragma unroll
            for (int i = 0; i < 4; ++i)
#pragma unroll
                for (int j = 0; j < 4; ++j)
                    s[i][j] = fmaf(a[i], bb[j], s[i][j]);
        }
        __syncthreads();   // all K reads done before P overwrites sKP

        if (jb == qb) {
#pragma unroll
            for (int i = 0; i < 4; ++i)
#pragma unroll
                for (int j = 0; j < 4; ++j)
                    if (tx * 4 + j > ty * 4 + i) s[i][j] = -1e30f;
        }

        // online softmax (row = ty*4+i, owned by the 16 tx-threads of this ty)
#pragma unroll
        for (int i = 0; i < 4; ++i) {
            float mt = fmaxf(fmaxf(s[i][0], s[i][1]), fmaxf(s[i][2], s[i][3]));
            mt = fmaxf(mt, __shfl_xor_sync(0xffffffffu, mt, 8, 16));
            mt = fmaxf(mt, __shfl_xor_sync(0xffffffffu, mt, 4, 16));
            mt = fmaxf(mt, __shfl_xor_sync(0xffffffffu, mt, 2, 16));
            mt = fmaxf(mt, __shfl_xor_sync(0xffffffffu, mt, 1, 16));
            float mn    = fmaxf(m[i], mt);
            float alpha = __expf(m[i] - mn);
            m[i] = mn;
            float rs = 0.f;
#pragma unroll
            for (int j = 0; j < 4; ++j) {
                float p = __expf(s[i][j] - mn);
                s[i][j] = p;
                rs += p;
            }
            l[i] = l[i] * alpha + rs;
#pragma unroll
            for (int j = 0; j < 4; ++j) o[i][j] *= alpha;
        }

        // write P (row-major) into sKP
#pragma unroll
        for (int i = 0; i < 4; ++i)
            *(float4*)&sKP[(ty * 4 + i) * 64 + tx * 4] =
                make_float4(s[i][0], s[i][1], s[i][2], s[i][3]);
        __syncthreads();

        // O += P V (rank-1 over c)
#pragma unroll 8
        for (int c = 0; c < 64; ++c) {
            float4 v = *(const float4*)&sV[c * 64 + tx * 4];
            float a0 = sKP[(ty * 4 + 0) * 64 + c];
            float a1 = sKP[(ty * 4 + 1) * 64 + c];
            float a2 = sKP[(ty * 4 + 2) * 64 + c];
            float a3 = sKP[(ty * 4 + 3) * 64 + c];
            o[0][0] = fmaf(a0, v.x, o[0][0]); o[0][1] = fmaf(a0, v.y, o[0][1]);
            o[0][2] = fmaf(a0, v.z, o[0][2]); o[0][3] = fmaf(a0, v.w, o[0][3]);
            o[1][0] = fmaf(a1, v.x, o[1][0]); o[1][1] = fmaf(a1, v.y, o[1][1]);
            o[1][2] = fmaf(a1, v.z, o[1][2]); o[1][3] = fmaf(a1, v.w, o[1][3]);
            o[2][0] = fmaf(a2, v.x, o[2][0]); o[2][1] = fmaf(a2, v.y, o[2][1]);
            o[2][2] = fmaf(a2, v.z, o[2][2]); o[2][3] = fmaf(a2, v.w, o[2][3]);
            o[3][0] = fmaf(a3, v.x, o[3][0]); o[3][1] = fmaf(a3, v.y, o[3][1]);
            o[3][2] = fmaf(a3, v.z, o[3][2]); o[3][3] = fmaf(a3, v.w, o[3][3]);
        }
    }

    // finalize: reduce l over the 16 tx-threads, divide, write [b,s,h*d]
#pragma unroll
    for (int i = 0; i < 4; ++i) {
        float ls = l[i];
        ls += __shfl_xor_sync(0xffffffffu, ls, 8, 16);
        ls += __shfl_xor_sync(0xffffffffu, ls, 4, 16);
        ls += __shfl_xor_sync(0xffffffffu, ls, 2, 16);
        ls += __shfl_xor_sync(0xffffffffu, ls, 1, 16);
        float inv = 1.f / ls;
        int srow = qb * 64 + ty * 4 + i;
        float* dst = g_ao + ((size_t)(b * SEQ + srow)) * DIM + h * HD + tx * 4;
        *(float4*)dst = make_float4(o[i][0] * inv, o[i][1] * inv,
                                    o[i][2] * inv, o[i][3] * inv);
    }
}

// ---------------- launcher ---------------------------------------------------
extern "C" void kernel_launch(void* const* d_in, const int* in_sizes, int n_in,
                              void* d_out, int out_size)
{
    const float* x     = (const float*)d_in[0];   // [2,2048,2048]
    const float* fc    = (const float*)d_in[1];   // [2048,32,2]
    // d_in[2] = mask (causal, hardcoded)
    const float* wqkv  = (const float*)d_in[3];   // [3072,2048]
    const float* wo    = (const float*)d_in[4];   // [2048,2048]
    float* out = (float*)d_out;                   // [2,2048,2048]

    void *p_qkv, *p_ao;
    cudaGetSymbolAddress(&p_qkv, g_qkv);
    cudaGetSymbolAddress(&p_ao,  g_ao);

    const int M = BSZ * SEQ;                      // 4096

    // 1) QKV projection: [4096,3072] = x @ wqkv^T
    gemm_nt_kernel<<<dim3(QKV_N / BN, M / BM), 256>>>(x, wqkv, (float*)p_qkv,
                                                      M, QKV_N, DIM);
    // 2) RoPE + layout scatter
    rope_q_kernel<<<(BSZ * SEQ * NH  * 32) / 256, 256>>>(fc);
    rope_k_kernel<<<(BSZ * SEQ * NKV * 32) / 256, 256>>>(fc);
    copy_v_kernel<<<(BSZ * SEQ * NKV * 16) / 256, 256>>>();
    // 3) causal flash attention -> g_ao laid out [b,s,h*d]
    flash_kernel<<<dim3(SEQ / 64, NH, BSZ), 256>>>();
    // 4) output projection: out = g_ao @ wo^T
    gemm_nt_kernel<<<dim3(DIM / BN, M / BM), 256>>>((const float*)p_ao, wo, out,
                                                    M, DIM, DIM);
}

// round 3
// speedup vs baseline: 1.5021x; 1.5021x over previous
#include <cuda_runtime.h>
#include <cuda_bf16.h>
#include <cstdint>
#include <cstddef>

#define BSZ 2
#define SEQ 2048
#define DIM 2048
#define NH 32
#define NKV 8
#define HD 64
#define QKV_N ((NH + 2*NKV)*HD)   // 3072

// ---------------- scratch (static device globals; no allocation) -----------
__device__ float g_qkv[(size_t)BSZ*SEQ*QKV_N];     // [4096, 3072]
__device__ float g_q  [(size_t)BSZ*NH *SEQ*HD];    // [b,h,s,d]
__device__ float g_k  [(size_t)BSZ*NKV*SEQ*HD];    // [b,kv,s,d]
__device__ float g_v  [(size_t)BSZ*NKV*SEQ*HD];    // [b,kv,s,d]
__device__ float g_ao [(size_t)BSZ*SEQ*DIM];       // [4096, 2048] = [b,s,h*d]

// bf16 split operands
__device__ __nv_bfloat16 g_xh [(size_t)BSZ*SEQ*DIM];
__device__ __nv_bfloat16 g_xl [(size_t)BSZ*SEQ*DIM];
__device__ __nv_bfloat16 g_wqh[(size_t)QKV_N*DIM];
__device__ __nv_bfloat16 g_wql[(size_t)QKV_N*DIM];
__device__ __nv_bfloat16 g_aoh[(size_t)BSZ*SEQ*DIM];
__device__ __nv_bfloat16 g_aol[(size_t)BSZ*SEQ*DIM];
__device__ __nv_bfloat16 g_woh[(size_t)DIM*DIM];
__device__ __nv_bfloat16 g_wol[(size_t)DIM*DIM];

// ---------------- small PTX helpers (sm_80-baseline ISA only) ---------------
__device__ __forceinline__ uint32_t smem_to_u32(const void* p) {
    uint32_t a;
    asm("{ .reg .u64 t; cvta.to.shared.u64 t, %1; cvt.u32.u64 %0, t; }"
        : "=r"(a) : "l"(p));
    return a;
}
__device__ __forceinline__ void cp_async16(uint32_t dst, const void* src) {
    asm volatile("cp.async.cg.shared.global [%0], [%1], 16;"
                 :: "r"(dst), "l"(src) : "memory");
}
#define CP_COMMIT() asm volatile("cp.async.commit_group;" ::: "memory")
#define CP_WAIT1()  asm volatile("cp.async.wait_group 1;" ::: "memory")
#define CP_WAIT0()  asm volatile("cp.async.wait_group 0;" ::: "memory")

// D += A(16x16 bf16) * B(16x8 bf16), fp32 accum
__device__ __forceinline__ void mma16816(float* d, const uint32_t* a,
                                         const uint32_t* b) {
    asm volatile(
        "mma.sync.aligned.m16n8k16.row.col.f32.bf16.bf16.f32 "
        "{%0,%1,%2,%3}, {%4,%5,%6,%7}, {%8,%9}, {%0,%1,%2,%3};"
        : "+f"(d[0]), "+f"(d[1]), "+f"(d[2]), "+f"(d[3])
        : "r"(a[0]), "r"(a[1]), "r"(a[2]), "r"(a[3]), "r"(b[0]), "r"(b[1]));
}

// ---------------- float -> (hi,lo) bf16 split -------------------------------
__global__ void split4_kernel(const float* __restrict__ src,
                              __nv_bfloat16* __restrict__ hi,
                              __nv_bfloat16* __restrict__ lo, int n4)
{
    int i = blockIdx.x * 256 + threadIdx.x;
    if (i >= n4) return;
    float4 v = ((const float4*)src)[i];
    __nv_bfloat16 h0 = __float2bfloat16(v.x);
    __nv_bfloat16 h1 = __float2bfloat16(v.y);
    __nv_bfloat16 h2 = __float2bfloat16(v.z);
    __nv_bfloat16 h3 = __float2bfloat16(v.w);
    __nv_bfloat16 l0 = __float2bfloat16(v.x - __bfloat162float(h0));
    __nv_bfloat16 l1 = __float2bfloat16(v.y - __bfloat162float(h1));
    __nv_bfloat16 l2 = __float2bfloat16(v.z - __bfloat162float(h2));
    __nv_bfloat16 l3 = __float2bfloat16(v.w - __bfloat162float(h3));
    ((__nv_bfloat162*)hi)[2*i]   = __nv_bfloat162(h0, h1);
    ((__nv_bfloat162*)hi)[2*i+1] = __nv_bfloat162(h2, h3);
    ((__nv_bfloat162*)lo)[2*i]   = __nv_bfloat162(l0, l1);
    ((__nv_bfloat162*)lo)[2*i+1] = __nv_bfloat162(l2, l3);
}

// ---------------- HMMA GEMM: C[M,N] = A[M,K] * B[N,K]^T ---------------------
// A,B as (hi,lo) bf16 splits. Tile 128x128x32, 8 warps (2m x 4n, 64x32 each),
// cp.async double buffer. smem tiles padded to 40 bf16/row (conflict-free).
#define GSTR 40
#define TILE_ELEMS (128 * GSTR)                 // per tile (bf16)
#define TILE_BYTES (TILE_ELEMS * 2)             // 10240
#define GT_SMEM_BYTES (2 * 4 * TILE_BYTES)      // 81920

__global__ __launch_bounds__(256)
void gemm_hmma_kernel(const __nv_bfloat16* __restrict__ Ah,
                      const __nv_bfloat16* __restrict__ Al,
                      const __nv_bfloat16* __restrict__ Bh,
                      const __nv_bfloat16* __restrict__ Bl,
                      float* __restrict__ C, int M, int N, int K)
{
    extern __shared__ __nv_bfloat16 sm[];
    const uint32_t sbase = smem_to_u32(sm);
    const int t    = threadIdx.x;
    const int wid  = t >> 5, lane = t & 31;
    const int bm   = blockIdx.y * 128, bn = blockIdx.x * 128;
    const int wm   = (wid & 1) * 64;           // warp m offset
    const int wn   = (wid >> 1) * 32;          // warp n offset
    const int lr   = lane >> 2;                // 0..7
    const int lc   = lane & 3;                 // 0..3

    // cp.async: 512 16B-chunks per tile; thread does chunks t and t+256
    const int r0 = t >> 2,  c0 = t & 3;        // chunk t
    const int r1 = (t + 256) >> 2, c1 = t & 3; // chunk t+256 (c same: +256 = +64 rows)

    float acc[4][4][4];
#pragma unroll
    for (int mi = 0; mi < 4; ++mi)
#pragma unroll
        for (int ni = 0; ni < 4; ++ni)
#pragma unroll
            for (int q = 0; q < 4; ++q) acc[mi][ni][q] = 0.f;

    const int nch = K / 32;

    auto load_chunk = [&](int buf, int kc) {
        const __nv_bfloat16* g[4];
        g[0] = Ah + (size_t)bm * K + kc * 32;
        g[1] = Al + (size_t)bm * K + kc * 32;
        g[2] = Bh + (size_t)bn * K + kc * 32;
        g[3] = Bl + (size_t)bn * K + kc * 32;
#pragma unroll
        for (int tile = 0; tile < 4; ++tile) {
            uint32_t sd = sbase + (buf * 4 + tile) * TILE_BYTES;
            cp_async16(sd + r0 * (GSTR*2) + c0 * 16, g[tile] + (size_t)r0 * K + c0 * 8);
            cp_async16(sd + r1 * (GSTR*2) + c1 * 16, g[tile] + (size_t)r1 * K + c1 * 8);
        }
    };

    load_chunk(0, 0);
    CP_COMMIT();

    for (int c = 0; c < nch; ++c) {
        const int buf = c & 1;
        if (c + 1 < nch) { load_chunk(buf ^ 1, c + 1); CP_COMMIT(); CP_WAIT1(); }
        else             { CP_WAIT0(); }
        __syncthreads();

        const __nv_bfloat16* sAh = sm + (buf * 4 + 0) * TILE_ELEMS;
        const __nv_bfloat16* sAl = sm + (buf * 4 + 1) * TILE_ELEMS;
        const __nv_bfloat16* sBh = sm + (buf * 4 + 2) * TILE_ELEMS;
        const __nv_bfloat16* sBl = sm + (buf * 4 + 3) * TILE_ELEMS;

#pragma unroll
        for (int ks = 0; ks < 2; ++ks) {
            const int k0 = ks * 16;
            uint32_t ah[4][4], al[4][4], bh[4][2], bl[4][2];
#pragma unroll
            for (int mi = 0; mi < 4; ++mi) {
                const int r = wm + mi * 16 + lr;
                ah[mi][0] = *(const uint32_t*)&sAh[(r    ) * GSTR + k0 + lc * 2];
                ah[mi][1] = *(const uint32_t*)&sAh[(r + 8) * GSTR + k0 + lc * 2];
                ah[mi][2] = *(const uint32_t*)&sAh[(r    ) * GSTR + k0 + lc * 2 + 8];
                ah[mi][3] = *(const uint32_t*)&sAh[(r + 8) * GSTR + k0 + lc * 2 + 8];
                al[mi][0] = *(const uint32_t*)&sAl[(r    ) * GSTR + k0 + lc * 2];
                al[mi][1] = *(const uint32_t*)&sAl[(r + 8) * GSTR + k0 + lc * 2];
                al[mi][2] = *(const uint32_t*)&sAl[(r    ) * GSTR + k0 + lc * 2 + 8];
                al[mi][3] = *(const uint32_t*)&sAl[(r + 8) * GSTR + k0 + lc * 2 + 8];
            }
#pragma unroll
            for (int ni = 0; ni < 4; ++ni) {
                const int n = wn + ni * 8 + lr;
                bh[ni][0] = *(const uint32_t*)&sBh[n * GSTR + k0 + lc * 2];
                bh[ni][1] = *(const uint32_t*)&sBh[n * GSTR + k0 + lc * 2 + 8];
                bl[ni][0] = *(const uint32_t*)&sBl[n * GSTR + k0 + lc * 2];
                bl[ni][1] = *(const uint32_t*)&sBl[n * GSTR + k0 + lc * 2 + 8];
            }
#pragma unroll
            for (int mi = 0; mi < 4; ++mi)
#pragma unroll
                for (int ni = 0; ni < 4; ++ni) {
                    mma16816(acc[mi][ni], ah[mi], bh[ni]);
                    mma16816(acc[mi][ni], ah[mi], bl[ni]);
                    mma16816(acc[mi][ni], al[mi], bh[ni]);
                }
        }
        __syncthreads();
    }

    // epilogue
#pragma unroll
    for (int mi = 0; mi < 4; ++mi) {
        const int row = bm + wm + mi * 16 + lr;
#pragma unroll
        for (int ni = 0; ni < 4; ++ni) {
            const int col = bn + wn + ni * 8 + lc * 2;
            *(float2*)&C[(size_t)row * N + col] =
                make_float2(acc[mi][ni][0], acc[mi][ni][1]);
            *(float2*)&C[(size_t)(row + 8) * N + col] =
                make_float2(acc[mi][ni][2], acc[mi][ni][3]);
        }
    }
}

// ---------------- RoPE scatter + V transpose --------------------------------
__global__ void rope_q_kernel(const float* __restrict__ fc)
{
    int gid = blockIdx.x * 256 + threadIdx.x;
    int p = gid & 31;
    int h = (gid >> 5) & 31;
    int s = (gid >> 10) & 2047;
    int b = gid >> 21;
    const float* src = g_qkv + (size_t)(b * SEQ + s) * QKV_N + h * HD + 2 * p;
    float x0 = src[0], x1 = src[1];
    float c  = fc[s * HD + 2 * p];
    float sn = fc[s * HD + 2 * p + 1];
    float* dst = g_q + (((size_t)(b * NH + h)) * SEQ + s) * HD + 2 * p;
    dst[0] = x0 * c - x1 * sn;
    dst[1] = x1 * c + x0 * sn;
}

__global__ void rope_k_kernel(const float* __restrict__ fc)
{
    int gid = blockIdx.x * 256 + threadIdx.x;
    int p  = gid & 31;
    int kv = (gid >> 5) & 7;
    int s  = (gid >> 8) & 2047;
    int b  = gid >> 19;
    const float* src = g_qkv + (size_t)(b * SEQ + s) * QKV_N + DIM + kv * HD + 2 * p;
    float x0 = src[0], x1 = src[1];
    float c  = fc[s * HD + 2 * p];
    float sn = fc[s * HD + 2 * p + 1];
    float* dst = g_k + (((size_t)(b * NKV + kv)) * SEQ + s) * HD + 2 * p;
    dst[0] = x0 * c - x1 * sn;
    dst[1] = x1 * c + x0 * sn;
}

__global__ void copy_v_kernel()
{
    int gid = blockIdx.x * 256 + threadIdx.x;
    int d4 = gid & 15;
    int kv = (gid >> 4) & 7;
    int s  = (gid >> 7) & 2047;
    int b  = gid >> 18;
    const float* src = g_qkv + (size_t)(b * SEQ + s) * QKV_N + DIM + NKV * HD + kv * HD + d4 * 4;
    float* dst = g_v + (((size_t)(b * NKV + kv)) * SEQ + s) * HD + d4 * 4;
    *(float4*)dst = *(const float4*)src;
}

// ---------------- flash attention (64x64 tiles, online softmax) -------------
__global__ __launch_bounds__(256)
void flash_kernel()
{
    __shared__ float sQ [64 * 64];
    __shared__ float sKP[64 * 64];
    __shared__ float sV [64 * 64];

    const int t  = threadIdx.x;
    const int qb = blockIdx.x;
    const int h  = blockIdx.y;
    const int b  = blockIdx.z;
    const int kvh = h >> 2;
    const int ty = t >> 4, tx = t & 15;

    {
        const int r  = t >> 2;
        const int f0 = t & 3;
        const float* qrow = g_q + (((size_t)(b * NH + h)) * SEQ + qb * 64 + r) * HD;
#pragma unroll
        for (int it = 0; it < 4; ++it) {
            int d = (f0 + it * 4) * 4;
            float4 v = *(const float4*)&qrow[d];
            sQ[(d + 0) * 64 + r] = v.x * 0.125f;
            sQ[(d + 1) * 64 + r] = v.y * 0.125f;
            sQ[(d + 2) * 64 + r] = v.z * 0.125f;
            sQ[(d + 3) * 64 + r] = v.w * 0.125f;
        }
    }

    float m[4], l[4], o[4][4];
#pragma unroll
    for (int i = 0; i < 4; ++i) {
        m[i] = -1e30f; l[i] = 0.f;
#pragma unroll
        for (int j = 0; j < 4; ++j) o[i][j] = 0.f;
    }

    const float* Kbase = g_k + ((size_t)(b * NKV + kvh)) * SEQ * HD;
    const float* Vbase = g_v + ((size_t)(b * NKV + kvh)) * SEQ * HD;

    for (int jb = 0; jb <= qb; ++jb) {
        __syncthreads();
        {
            const int r  = t >> 2;
            const int f0 = t & 3;
            const float* krow = Kbase + (size_t)(jb * 64 + r) * HD;
            const float* vrow = Vbase + (size_t)(jb * 64 + r) * HD;
#pragma unroll
            for (int it = 0; it < 4; ++it) {
                int d = (f0 + it * 4) * 4;
                float4 kvv = *(const float4*)&krow[d];
                sKP[(d + 0) * 64 + r] = kvv.x;
                sKP[(d + 1) * 64 + r] = kvv.y;
                sKP[(d + 2) * 64 + r] = kvv.z;
                sKP[(d + 3) * 64 + r] = kvv.w;
                *(float4*)&sV[r * 64 + d] = *(const float4*)&vrow[d];
            }
        }
        __syncthreads();

        float s[4][4];
#pragma unroll
        for (int i = 0; i < 4; ++i)
#pragma unroll
            for (int j = 0; j < 4; ++j) s[i][j] = 0.f;

#pragma unroll 16
        for (int d = 0; d < 64; ++d) {
            float a[4], bb[4];
            *(float4*)a  = *(const float4*)&sQ [d * 64 + ty * 4];
            *(float4*)bb = *(const float4*)&sKP[d * 64 + tx * 4];
#pragma unroll
            for (int i = 0; i < 4; ++i)
#pragma unroll
                for (int j = 0; j < 4; ++j)
                    s[i][j] = fmaf(a[i], bb[j], s[i][j]);
        }
        __syncthreads();

        if (jb == qb) {
#pragma unroll
            for (int i = 0; i < 4; ++i)
#pragma unroll
                for (int j = 0; j < 4; ++j)
                    if (tx * 4 + j > ty * 4 + i) s[i][j] = -1e30f;
        }

#pragma unroll
        for (int i = 0; i < 4; ++i) {
            float mt = fmaxf(fmaxf(s[i][0], s[i][1]), fmaxf(s[i][2], s[i][3]));
            mt = fmaxf(mt, __shfl_xor_sync(0xffffffffu, mt, 8, 16));
            mt = fmaxf(mt, __shfl_xor_sync(0xffffffffu, mt, 4, 16));
            mt = fmaxf(mt, __shfl_xor_sync(0xffffffffu, mt, 2, 16));
            mt = fmaxf(mt, __shfl_xor_sync(0xffffffffu, mt, 1, 16));
            float mn    = fmaxf(m[i], mt);
            float alpha = __expf(m[i] - mn);
            m[i] = mn;
            float rs = 0.f;
#pragma unroll
            for (int j = 0; j < 4; ++j) {
                float p = __expf(s[i][j] - mn);
                s[i][j] = p;
                rs += p;
            }
            l[i] = l[i] * alpha + rs;
#pragma unroll
            for (int j = 0; j < 4; ++j) o[i][j] *= alpha;
        }

#pragma unroll
        for (int i = 0; i < 4; ++i)
            *(float4*)&sKP[(ty * 4 + i) * 64 + tx * 4] =
                make_float4(s[i][0], s[i][1], s[i][2], s[i][3]);
        __syncthreads();

#pragma unroll 8
        for (int c = 0; c < 64; ++c) {
            float4 v = *(const float4*)&sV[c * 64 + tx * 4];
            float a0 = sKP[(ty * 4 + 0) * 64 + c];
            float a1 = sKP[(ty * 4 + 1) * 64 + c];
            float a2 = sKP[(ty * 4 + 2) * 64 + c];
            float a3 = sKP[(ty * 4 + 3) * 64 + c];
            o[0][0] = fmaf(a0, v.x, o[0][0]); o[0][1] = fmaf(a0, v.y, o[0][1]);
            o[0][2] = fmaf(a0, v.z, o[0][2]); o[0][3] = fmaf(a0, v.w, o[0][3]);
            o[1][0] = fmaf(a1, v.x, o[1][0]); o[1][1] = fmaf(a1, v.y, o[1][1]);
            o[1][2] = fmaf(a1, v.z, o[1][2]); o[1][3] = fmaf(a1, v.w, o[1][3]);
            o[2][0] = fmaf(a2, v.x, o[2][0]); o[2][1] = fmaf(a2, v.y, o[2][1]);
            o[2][2] = fmaf(a2, v.z, o[2][2]); o[2][3] = fmaf(a2, v.w, o[2][3]);
            o[3][0] = fmaf(a3, v.x, o[3][0]); o[3][1] = fmaf(a3, v.y, o[3][1]);
            o[3][2] = fmaf(a3, v.z, o[3][2]); o[3][3] = fmaf(a3, v.w, o[3][3]);
        }
    }

#pragma unroll
    for (int i = 0; i < 4; ++i) {
        float ls = l[i];
        ls += __shfl_xor_sync(0xffffffffu, ls, 8, 16);
        ls += __shfl_xor_sync(0xffffffffu, ls, 4, 16);
        ls += __shfl_xor_sync(0xffffffffu, ls, 2, 16);
        ls += __shfl_xor_sync(0xffffffffu, ls, 1, 16);
        float inv = 1.f / ls;
        int srow = qb * 64 + ty * 4 + i;
        float* dst = g_ao + ((size_t)(b * SEQ + srow)) * DIM + h * HD + tx * 4;
        *(float4*)dst = make_float4(o[i][0] * inv, o[i][1] * inv,
                                    o[i][2] * inv, o[i][3] * inv);
    }
}

// ---------------- launcher ---------------------------------------------------
extern "C" void kernel_launch(void* const* d_in, const int* in_sizes, int n_in,
                              void* d_out, int out_size)
{
    const float* x     = (const float*)d_in[0];   // [2,2048,2048]
    const float* fc    = (const float*)d_in[1];   // [2048,32,2]
    // d_in[2] = mask (causal, hardcoded)
    const float* wqkv  = (const float*)d_in[3];   // [3072,2048]
    const float* wo    = (const float*)d_in[4];   // [2048,2048]
    float* out = (float*)d_out;                   // [2,2048,2048]

    void *p_qkv, *p_ao;
    void *p_xh, *p_xl, *p_wqh, *p_wql, *p_aoh, *p_aol, *p_woh, *p_wol;
    cudaGetSymbolAddress(&p_qkv, g_qkv);
    cudaGetSymbolAddress(&p_ao,  g_ao);
    cudaGetSymbolAddress(&p_xh,  g_xh);  cudaGetSymbolAddress(&p_xl,  g_xl);
    cudaGetSymbolAddress(&p_wqh, g_wqh); cudaGetSymbolAddress(&p_wql, g_wql);
    cudaGetSymbolAddress(&p_aoh, g_aoh); cudaGetSymbolAddress(&p_aol, g_aol);
    cudaGetSymbolAddress(&p_woh, g_woh); cudaGetSymbolAddress(&p_wol, g_wol);

    cudaFuncSetAttribute(gemm_hmma_kernel,
                         cudaFuncAttributeMaxDynamicSharedMemorySize, GT_SMEM_BYTES);

    const int M = BSZ * SEQ;                      // 4096

    // split inputs to (hi,lo) bf16
    split4_kernel<<<(M * DIM / 4 + 255) / 256, 256>>>(x,
        (__nv_bfloat16*)p_xh, (__nv_bfloat16*)p_xl, M * DIM / 4);
    split4_kernel<<<(QKV_N * DIM / 4 + 255) / 256, 256>>>(wqkv,
        (__nv_bfloat16*)p_wqh, (__nv_bfloat16*)p_wql, QKV_N * DIM / 4);
    split4_kernel<<<(DIM * DIM / 4 + 255) / 256, 256>>>(wo,
        (__nv_bfloat16*)p_woh, (__nv_bfloat16*)p_wol, DIM * DIM / 4);

    // 1) QKV projection (HMMA): [4096,3072] = x @ wqkv^T
    gemm_hmma_kernel<<<dim3(QKV_N / 128, M / 128), 256, GT_SMEM_BYTES>>>(
        (const __nv_bfloat16*)p_xh, (const __nv_bfloat16*)p_xl,
        (const __nv_bfloat16*)p_wqh, (const __nv_bfloat16*)p_wql,
        (float*)p_qkv, M, QKV_N, DIM);

    // 2) RoPE + layout scatter
    rope_q_kernel<<<(BSZ * SEQ * NH  * 32) / 256, 256>>>(fc);
    rope_k_kernel<<<(BSZ * SEQ * NKV * 32) / 256, 256>>>(fc);
    copy_v_kernel<<<(BSZ * SEQ * NKV * 16) / 256, 256>>>();

    // 3) causal flash attention -> g_ao [b,s,h*d]
    flash_kernel<<<dim3(SEQ / 64, NH, BSZ), 256>>>();

    // 4) split attention output, then output projection (HMMA)
    split4_kernel<<<(M * DIM / 4 + 255) / 256, 256>>>((const float*)p_ao,
        (__nv_bfloat16*)p_aoh, (__nv_bfloat16*)p_aol, M * DIM / 4);
    gemm_hmma_kernel<<<dim3(DIM / 128, M / 128), 256, GT_SMEM_BYTES>>>(
        (const __nv_bfloat16*)p_aoh, (const __nv_bfloat16*)p_aol,
        (const __nv_bfloat16*)p_woh, (const __nv_bfloat16*)p_wol,
        out, M, DIM, DIM);
}

// round 5
// speedup vs baseline: 2.5533x; 1.6998x over previous
#include <cuda_runtime.h>
#include <cuda_bf16.h>
#include <cstdint>
#include <cstddef>

#define BSZ 2
#define SEQ 2048
#define DIM 2048
#define NH 32
#define NKV 8
#define HD 64
#define QKV_N ((NH + 2*NKV)*HD)   // 3072

// ---------------- scratch (static device globals; no allocation) -----------
__device__ float g_qkv[(size_t)BSZ*SEQ*QKV_N];     // [4096, 3072]
__device__ float g_ao [(size_t)BSZ*SEQ*DIM];       // [4096, 2048] = [b,s,h*d]

// bf16 split operands (projection GEMMs)
__device__ __nv_bfloat16 g_xh [(size_t)BSZ*SEQ*DIM];
__device__ __nv_bfloat16 g_xl [(size_t)BSZ*SEQ*DIM];
__device__ __nv_bfloat16 g_wqh[(size_t)QKV_N*DIM];
__device__ __nv_bfloat16 g_wql[(size_t)QKV_N*DIM];
__device__ __nv_bfloat16 g_aoh[(size_t)BSZ*SEQ*DIM];
__device__ __nv_bfloat16 g_aol[(size_t)BSZ*SEQ*DIM];
__device__ __nv_bfloat16 g_woh[(size_t)DIM*DIM];
__device__ __nv_bfloat16 g_wol[(size_t)DIM*DIM];

// bf16 split Q/K/V for flash
__device__ __nv_bfloat16 g_qh[(size_t)BSZ*NH *SEQ*HD];   // [b,h,s,d] (pre-scaled)
__device__ __nv_bfloat16 g_ql[(size_t)BSZ*NH *SEQ*HD];
__device__ __nv_bfloat16 g_kh[(size_t)BSZ*NKV*SEQ*HD];   // [b,kv,s,d]
__device__ __nv_bfloat16 g_kl[(size_t)BSZ*NKV*SEQ*HD];
__device__ __nv_bfloat16 g_vh[(size_t)BSZ*NKV*HD*SEQ];   // [b,kv,d,s] transposed
__device__ __nv_bfloat16 g_vl[(size_t)BSZ*NKV*HD*SEQ];

// ---------------- small PTX helpers (sm_80-baseline ISA only) ---------------
__device__ __forceinline__ uint32_t smem_to_u32(const void* p) {
    uint32_t a;
    asm("{ .reg .u64 t; cvta.to.shared.u64 t, %1; cvt.u32.u64 %0, t; }"
        : "=r"(a) : "l"(p));
    return a;
}
__device__ __forceinline__ void cp_async16(uint32_t dst, const void* src) {
    asm volatile("cp.async.cg.shared.global [%0], [%1], 16;"
                 :: "r"(dst), "l"(src) : "memory");
}
#define CP_COMMIT() asm volatile("cp.async.commit_group;" ::: "memory")
#define CP_WAIT1()  asm volatile("cp.async.wait_group 1;" ::: "memory")
#define CP_WAIT0()  asm volatile("cp.async.wait_group 0;" ::: "memory")

// D += A(16x16 bf16) * B(16x8 bf16), fp32 accum
__device__ __forceinline__ void mma16816(float* d, const uint32_t* a,
                                         const uint32_t* b) {
    asm volatile(
        "mma.sync.aligned.m16n8k16.row.col.f32.bf16.bf16.f32 "
        "{%0,%1,%2,%3}, {%4,%5,%6,%7}, {%8,%9}, {%0,%1,%2,%3};"
        : "+f"(d[0]), "+f"(d[1]), "+f"(d[2]), "+f"(d[3])
        : "r"(a[0]), "r"(a[1]), "r"(a[2]), "r"(a[3]), "r"(b[0]), "r"(b[1]));
}

// ---------------- float -> (hi,lo) bf16 split -------------------------------
__global__ void split4_kernel(const float* __restrict__ src,
                              __nv_bfloat16* __restrict__ hi,
                              __nv_bfloat16* __restrict__ lo, int n4)
{
    int i = blockIdx.x * 256 + threadIdx.x;
    if (i >= n4) return;
    float4 v = ((const float4*)src)[i];
    __nv_bfloat16 h0 = __float2bfloat16(v.x);
    __nv_bfloat16 h1 = __float2bfloat16(v.y);
    __nv_bfloat16 h2 = __float2bfloat16(v.z);
    __nv_bfloat16 h3 = __float2bfloat16(v.w);
    __nv_bfloat16 l0 = __float2bfloat16(v.x - __bfloat162float(h0));
    __nv_bfloat16 l1 = __float2bfloat16(v.y - __bfloat162float(h1));
    __nv_bfloat16 l2 = __float2bfloat16(v.z - __bfloat162float(h2));
    __nv_bfloat16 l3 = __float2bfloat16(v.w - __bfloat162float(h3));
    ((__nv_bfloat162*)hi)[2*i]   = __nv_bfloat162(h0, h1);
    ((__nv_bfloat162*)hi)[2*i+1] = __nv_bfloat162(h2, h3);
    ((__nv_bfloat162*)lo)[2*i]   = __nv_bfloat162(l0, l1);
    ((__nv_bfloat162*)lo)[2*i+1] = __nv_bfloat162(l2, l3);
}

// ---------------- HMMA GEMM: C[M,N] = A[M,K] * B[N,K]^T ---------------------
#define GSTR 40
#define TILE_ELEMS (128 * GSTR)
#define TILE_BYTES (TILE_ELEMS * 2)
#define GT_SMEM_BYTES (2 * 4 * TILE_BYTES)      // 81920

__global__ __launch_bounds__(256, 2)
void gemm_hmma_kernel(const __nv_bfloat16* __restrict__ Ah,
                      const __nv_bfloat16* __restrict__ Al,
                      const __nv_bfloat16* __restrict__ Bh,
                      const __nv_bfloat16* __restrict__ Bl,
                      float* __restrict__ C, int M, int N, int K)
{
    extern __shared__ __nv_bfloat16 sm[];
    const uint32_t sbase = smem_to_u32(sm);
    const int t    = threadIdx.x;
    const int wid  = t >> 5, lane = t & 31;
    const int bm   = blockIdx.y * 128, bn = blockIdx.x * 128;
    const int wm   = (wid & 1) * 64;
    const int wn   = (wid >> 1) * 32;
    const int lr   = lane >> 2;
    const int lc   = lane & 3;

    const int r0 = t >> 2,  c0 = t & 3;
    const int r1 = (t + 256) >> 2, c1 = t & 3;

    float acc[4][4][4];
#pragma unroll
    for (int mi = 0; mi < 4; ++mi)
#pragma unroll
        for (int ni = 0; ni < 4; ++ni)
#pragma unroll
            for (int q = 0; q < 4; ++q) acc[mi][ni][q] = 0.f;

    const int nch = K / 32;

    auto load_chunk = [&](int buf, int kc) {
        const __nv_bfloat16* g[4];
        g[0] = Ah + (size_t)bm * K + kc * 32;
        g[1] = Al + (size_t)bm * K + kc * 32;
        g[2] = Bh + (size_t)bn * K + kc * 32;
        g[3] = Bl + (size_t)bn * K + kc * 32;
#pragma unroll
        for (int tile = 0; tile < 4; ++tile) {
            uint32_t sd = sbase + (buf * 4 + tile) * TILE_BYTES;
            cp_async16(sd + r0 * (GSTR*2) + c0 * 16, g[tile] + (size_t)r0 * K + c0 * 8);
            cp_async16(sd + r1 * (GSTR*2) + c1 * 16, g[tile] + (size_t)r1 * K + c1 * 8);
        }
    };

    load_chunk(0, 0);
    CP_COMMIT();

    for (int c = 0; c < nch; ++c) {
        const int buf = c & 1;
        if (c + 1 < nch) { load_chunk(buf ^ 1, c + 1); CP_COMMIT(); CP_WAIT1(); }
        else             { CP_WAIT0(); }
        __syncthreads();

        const __nv_bfloat16* sAh = sm + (buf * 4 + 0) * TILE_ELEMS;
        const __nv_bfloat16* sAl = sm + (buf * 4 + 1) * TILE_ELEMS;
        const __nv_bfloat16* sBh = sm + (buf * 4 + 2) * TILE_ELEMS;
        const __nv_bfloat16* sBl = sm + (buf * 4 + 3) * TILE_ELEMS;

#pragma unroll
        for (int ks = 0; ks < 2; ++ks) {
            const int k0 = ks * 16;
            uint32_t ah[4][4], al[4][4], bh[4][2], bl[4][2];
#pragma unroll
            for (int mi = 0; mi < 4; ++mi) {
                const int r = wm + mi * 16 + lr;
                ah[mi][0] = *(const uint32_t*)&sAh[(r    ) * GSTR + k0 + lc * 2];
                ah[mi][1] = *(const uint32_t*)&sAh[(r + 8) * GSTR + k0 + lc * 2];
                ah[mi][2] = *(const uint32_t*)&sAh[(r    ) * GSTR + k0 + lc * 2 + 8];
                ah[mi][3] = *(const uint32_t*)&sAh[(r + 8) * GSTR + k0 + lc * 2 + 8];
                al[mi][0] = *(const uint32_t*)&sAl[(r    ) * GSTR + k0 + lc * 2];
                al[mi][1] = *(const uint32_t*)&sAl[(r + 8) * GSTR + k0 + lc * 2];
                al[mi][2] = *(const uint32_t*)&sAl[(r    ) * GSTR + k0 + lc * 2 + 8];
                al[mi][3] = *(const uint32_t*)&sAl[(r + 8) * GSTR + k0 + lc * 2 + 8];
            }
#pragma unroll
            for (int ni = 0; ni < 4; ++ni) {
                const int n = wn + ni * 8 + lr;
                bh[ni][0] = *(const uint32_t*)&sBh[n * GSTR + k0 + lc * 2];
                bh[ni][1] = *(const uint32_t*)&sBh[n * GSTR + k0 + lc * 2 + 8];
                bl[ni][0] = *(const uint32_t*)&sBl[n * GSTR + k0 + lc * 2];
                bl[ni][1] = *(const uint32_t*)&sBl[n * GSTR + k0 + lc * 2 + 8];
            }
#pragma unroll
            for (int mi = 0; mi < 4; ++mi)
#pragma unroll
                for (int ni = 0; ni < 4; ++ni) {
                    mma16816(acc[mi][ni], ah[mi], bh[ni]);
                    mma16816(acc[mi][ni], ah[mi], bl[ni]);
                    mma16816(acc[mi][ni], al[mi], bh[ni]);
                }
        }
        __syncthreads();
    }

#pragma unroll
    for (int mi = 0; mi < 4; ++mi) {
        const int row = bm + wm + mi * 16 + lr;
#pragma unroll
        for (int ni = 0; ni < 4; ++ni) {
            const int col = bn + wn + ni * 8 + lc * 2;
            *(float2*)&C[(size_t)row * N + col] =
                make_float2(acc[mi][ni][0], acc[mi][ni][1]);
            *(float2*)&C[(size_t)(row + 8) * N + col] =
                make_float2(acc[mi][ni][2], acc[mi][ni][3]);
        }
    }
}

// ---------------- RoPE -> bf16 hi/lo splits ---------------------------------
__device__ __forceinline__ void split_write(__nv_bfloat16* hi, __nv_bfloat16* lo,
                                            float v0, float v1)
{
    __nv_bfloat16 h0 = __float2bfloat16(v0);
    __nv_bfloat16 h1 = __float2bfloat16(v1);
    __nv_bfloat16 l0 = __float2bfloat16(v0 - __bfloat162float(h0));
    __nv_bfloat16 l1 = __float2bfloat16(v1 - __bfloat162float(h1));
    *(__nv_bfloat162*)hi = __nv_bfloat162(h0, h1);
    *(__nv_bfloat162*)lo = __nv_bfloat162(l0, l1);
}

__global__ void rope_q_kernel(const float* __restrict__ fc)
{
    int gid = blockIdx.x * 256 + threadIdx.x;
    int p = gid & 31;
    int h = (gid >> 5) & 31;
    int s = (gid >> 10) & 2047;
    int b = gid >> 21;
    const float* src = g_qkv + (size_t)(b * SEQ + s) * QKV_N + h * HD + 2 * p;
    float x0 = src[0], x1 = src[1];
    float c  = fc[s * HD + 2 * p];
    float sn = fc[s * HD + 2 * p + 1];
    size_t off = (((size_t)(b * NH + h)) * SEQ + s) * HD + 2 * p;
    split_write(g_qh + off, g_ql + off,
                (x0 * c - x1 * sn) * 0.125f, (x1 * c + x0 * sn) * 0.125f);
}

__global__ void rope_k_kernel(const float* __restrict__ fc)
{
    int gid = blockIdx.x * 256 + threadIdx.x;
    int p  = gid & 31;
    int kv = (gid >> 5) & 7;
    int s  = (gid >> 8) & 2047;
    int b  = gid >> 19;
    const float* src = g_qkv + (size_t)(b * SEQ + s) * QKV_N + DIM + kv * HD + 2 * p;
    float x0 = src[0], x1 = src[1];
    float c  = fc[s * HD + 2 * p];
    float sn = fc[s * HD + 2 * p + 1];
    size_t off = (((size_t)(b * NKV + kv)) * SEQ + s) * HD + 2 * p;
    split_write(g_kh + off, g_kl + off,
                x0 * c - x1 * sn, x1 * c + x0 * sn);
}

// V: split + transpose [s,d] -> [d,s] per (b,kv)
__global__ void split_v_kernel()
{
    __shared__ float tile[32][33];
    const int bk = blockIdx.z;                 // b*NKV + kv
    const int b  = bk >> 3, kv = bk & 7;
    const int s0 = blockIdx.x * 32;
    const int d0 = blockIdx.y * 32;
    const int tx = threadIdx.x & 31, ty = threadIdx.x >> 5;   // 32x8

    const float* src = g_qkv + (size_t)(b * SEQ + s0) * QKV_N
                       + DIM + NKV * HD + kv * HD + d0;
#pragma unroll
    for (int i = 0; i < 4; ++i)
        tile[ty + i * 8][tx] = src[(size_t)(ty + i * 8) * QKV_N + tx];
    __syncthreads();

    const size_t obase = ((size_t)bk * HD + d0) * SEQ + s0;
#pragma unroll
    for (int i = 0; i < 4; ++i) {
        int d = ty + i * 8;
        float v = tile[tx][d];
        __nv_bfloat16 h = __float2bfloat16(v);
        g_vh[obase + (size_t)d * SEQ + tx] = h;
        g_vl[obase + (size_t)d * SEQ + tx] = __float2bfloat16(v - __bfloat162float(h));
    }
}

// ---------------- flash attention on HMMA ------------------------------------
// Block: 128 q rows (8 warps x 16), KV tile 64. Split-bf16 both MMAs.
#define FSTR 72

__global__ __launch_bounds__(256)
void flash_hmma_kernel()
{
    __shared__ __nv_bfloat16 sKh[64 * FSTR];
    __shared__ __nv_bfloat16 sKl[64 * FSTR];
    __shared__ __nv_bfloat16 sVh[64 * FSTR];   // [d][key]
    __shared__ __nv_bfloat16 sVl[64 * FSTR];

    const int t = threadIdx.x;
    const int w = t >> 5, lane = t & 31;
    const int g = lane >> 2, tg = lane & 3;
    const int qb = blockIdx.x, h = blockIdx.y, b = blockIdx.z;
    const int kvh = h >> 2;
    const int qrow0 = qb * 128 + w * 16;

    // Q fragments (hi/lo), 4 k-chunks of 16 over d=64
    uint32_t qfh[4][4], qfl[4][4];
    {
        const __nv_bfloat16* gq = g_qh + (((size_t)(b*NH+h))*SEQ + qrow0)*HD;
        const __nv_bfloat16* gl = g_ql + (((size_t)(b*NH+h))*SEQ + qrow0)*HD;
#pragma unroll
        for (int kk = 0; kk < 4; ++kk) {
            int d0 = kk * 16 + tg * 2;
            qfh[kk][0] = *(const uint32_t*)&gq[(size_t)(g    ) * HD + d0];
            qfh[kk][1] = *(const uint32_t*)&gq[(size_t)(g + 8) * HD + d0];
            qfh[kk][2] = *(const uint32_t*)&gq[(size_t)(g    ) * HD + d0 + 8];
            qfh[kk][3] = *(const uint32_t*)&gq[(size_t)(g + 8) * HD + d0 + 8];
            qfl[kk][0] = *(const uint32_t*)&gl[(size_t)(g    ) * HD + d0];
            qfl[kk][1] = *(const uint32_t*)&gl[(size_t)(g + 8) * HD + d0];
            qfl[kk][2] = *(const uint32_t*)&gl[(size_t)(g    ) * HD + d0 + 8];
            qfl[kk][3] = *(const uint32_t*)&gl[(size_t)(g + 8) * HD + d0 + 8];
        }
    }

    float m0 = -1e30f, m1 = -1e30f, l0 = 0.f, l1 = 0.f;
    float o[8][4];
#pragma unroll
    for (int ni = 0; ni < 8; ++ni)
#pragma unroll
        for (int q = 0; q < 4; ++q) o[ni][q] = 0.f;

    const __nv_bfloat16* gkh = g_kh + ((size_t)(b * NKV + kvh)) * SEQ * HD;
    const __nv_bfloat16* gkl = g_kl + ((size_t)(b * NKV + kvh)) * SEQ * HD;
    const __nv_bfloat16* gvh = g_vh + ((size_t)(b * NKV + kvh)) * HD * SEQ;
    const __nv_bfloat16* gvl = g_vl + ((size_t)(b * NKV + kvh)) * HD * SEQ;

    const int ntile = 2 * qb + 2;
    for (int jb = 0; jb < ntile; ++jb) {
        __syncthreads();
        {
            // 512 uint4 chunks per array; thread does 2
#pragma unroll
            for (int cc = 0; cc < 2; ++cc) {
                int c   = t + cc * 256;
                int row = c >> 3, col = (c & 7) * 8;
                *(uint4*)&sKh[row * FSTR + col] =
                    *(const uint4*)&gkh[(size_t)(jb * 64 + row) * HD + col];
                *(uint4*)&sKl[row * FSTR + col] =
                    *(const uint4*)&gkl[(size_t)(jb * 64 + row) * HD + col];
                *(uint4*)&sVh[row * FSTR + col] =
                    *(const uint4*)&gvh[(size_t)row * SEQ + jb * 64 + col];
                *(uint4*)&sVl[row * FSTR + col] =
                    *(const uint4*)&gvl[(size_t)row * SEQ + jb * 64 + col];
            }
        }
        __syncthreads();

        if (jb * 64 > qrow0 + 15) continue;   // fully masked for this warp

        // S = Q K^T
        float s[8][4];
#pragma unroll
        for (int ni = 0; ni < 8; ++ni) {
            s[ni][0] = s[ni][1] = s[ni][2] = s[ni][3] = 0.f;
            const int key = ni * 8 + g;
#pragma unroll
            for (int kk = 0; kk < 4; ++kk) {
                uint32_t bh[2], bl[2];
                bh[0] = *(const uint32_t*)&sKh[key * FSTR + kk * 16 + tg * 2];
                bh[1] = *(const uint32_t*)&sKh[key * FSTR + kk * 16 + tg * 2 + 8];
                bl[0] = *(const uint32_t*)&sKl[key * FSTR + kk * 16 + tg * 2];
                bl[1] = *(const uint32_t*)&sKl[key * FSTR + kk * 16 + tg * 2 + 8];
                mma16816(s[ni], qfh[kk], bh);
                mma16816(s[ni], qfh[kk], bl);
                mma16816(s[ni], qfl[kk], bh);
            }
        }

        // causal mask (diagonal tiles only)
        if (jb * 64 + 63 > qrow0) {
            const int cb = jb * 64 + tg * 2;
            const int r0 = qrow0 + g, r1 = r0 + 8;
#pragma unroll
            for (int ni = 0; ni < 8; ++ni) {
                int c0 = cb + ni * 8, c1 = c0 + 1;
                if (c0 > r0) s[ni][0] = -1e30f;
                if (c1 > r0) s[ni][1] = -1e30f;
                if (c0 > r1) s[ni][2] = -1e30f;
                if (c1 > r1) s[ni][3] = -1e30f;
            }
        }

        // online softmax
        float mt0 = -1e30f, mt1 = -1e30f;
#pragma unroll
        for (int ni = 0; ni < 8; ++ni) {
            mt0 = fmaxf(mt0, fmaxf(s[ni][0], s[ni][1]));
            mt1 = fmaxf(mt1, fmaxf(s[ni][2], s[ni][3]));
        }
        mt0 = fmaxf(mt0, __shfl_xor_sync(0xffffffffu, mt0, 1));
        mt0 = fmaxf(mt0, __shfl_xor_sync(0xffffffffu, mt0, 2));
        mt1 = fmaxf(mt1, __shfl_xor_sync(0xffffffffu, mt1, 1));
        mt1 = fmaxf(mt1, __shfl_xor_sync(0xffffffffu, mt1, 2));
        float mn0 = fmaxf(m0, mt0), mn1 = fmaxf(m1, mt1);
        float a0 = __expf(m0 - mn0), a1 = __expf(m1 - mn1);
        m0 = mn0; m1 = mn1;
        float rs0 = 0.f, rs1 = 0.f;
#pragma unroll
        for (int ni = 0; ni < 8; ++ni) {
            s[ni][0] = __expf(s[ni][0] - mn0);
            s[ni][1] = __expf(s[ni][1] - mn0);
            s[ni][2] = __expf(s[ni][2] - mn1);
            s[ni][3] = __expf(s[ni][3] - mn1);
            rs0 += s[ni][0] + s[ni][1];
            rs1 += s[ni][2] + s[ni][3];
        }
        l0 = l0 * a0 + rs0;
        l1 = l1 * a1 + rs1;
#pragma unroll
        for (int ni = 0; ni < 8; ++ni) {
            o[ni][0] *= a0; o[ni][1] *= a0;
            o[ni][2] *= a1; o[ni][3] *= a1;
        }

        // O += P V. P A-fragments from S C-fragments:
        // a0=(row g, k-low)  <- tile 2kk   (c0,c1)
        // a1=(row g+8,k-low) <- tile 2kk   (c2,c3)
        // a2=(row g, k-high) <- tile 2kk+1 (c0,c1)
        // a3=(row g+8,k-high)<- tile 2kk+1 (c2,c3)
#pragma unroll
        for (int kk = 0; kk < 4; ++kk) {
            uint32_t ph[4], pl[4];
#pragma unroll
            for (int half = 0; half < 2; ++half) {
                const int ni = 2 * kk + half;
                __nv_bfloat162 h0 = __floats2bfloat162_rn(s[ni][0], s[ni][1]);
                __nv_bfloat162 l0v = __floats2bfloat162_rn(
                    s[ni][0] - __bfloat162float(h0.x),
                    s[ni][1] - __bfloat162float(h0.y));
                __nv_bfloat162 h1 = __floats2bfloat162_rn(s[ni][2], s[ni][3]);
                __nv_bfloat162 l1v = __floats2bfloat162_rn(
                    s[ni][2] - __bfloat162float(h1.x),
                    s[ni][3] - __bfloat162float(h1.y));
                ph[half * 2 + 0] = *(uint32_t*)&h0;
                ph[half * 2 + 1] = *(uint32_t*)&h1;
                pl[half * 2 + 0] = *(uint32_t*)&l0v;
                pl[half * 2 + 1] = *(uint32_t*)&l1v;
            }
#pragma unroll
            for (int ni = 0; ni < 8; ++ni) {
                const int d = ni * 8 + g;
                uint32_t vh[2], vl[2];
                vh[0] = *(const uint32_t*)&sVh[d * FSTR + kk * 16 + tg * 2];
                vh[1] = *(const uint32_t*)&sVh[d * FSTR + kk * 16 + tg * 2 + 8];
                vl[0] = *(const uint32_t*)&sVl[d * FSTR + kk * 16 + tg * 2];
                vl[1] = *(const uint32_t*)&sVl[d * FSTR + kk * 16 + tg * 2 + 8];
                mma16816(o[ni], ph, vh);
                mma16816(o[ni], ph, vl);
                mma16816(o[ni], pl, vh);
            }
        }
    }

    // finalize
    l0 += __shfl_xor_sync(0xffffffffu, l0, 1);
    l0 += __shfl_xor_sync(0xffffffffu, l0, 2);
    l1 += __shfl_xor_sync(0xffffffffu, l1, 1);
    l1 += __shfl_xor_sync(0xffffffffu, l1, 2);
    const float inv0 = 1.f / l0, inv1 = 1.f / l1;

    const int r0 = qrow0 + g, r1 = r0 + 8;
#pragma unroll
    for (int ni = 0; ni < 8; ++ni) {
        const int col = h * HD + ni * 8 + tg * 2;
        *(float2*)&g_ao[(size_t)(b * SEQ + r0) * DIM + col] =
            make_float2(o[ni][0] * inv0, o[ni][1] * inv0);
        *(float2*)&g_ao[(size_t)(b * SEQ + r1) * DIM + col] =
            make_float2(o[ni][2] * inv1, o[ni][3] * inv1);
    }
}

// ---------------- launcher ---------------------------------------------------
extern "C" void kernel_launch(void* const* d_in, const int* in_sizes, int n_in,
                              void* d_out, int out_size)
{
    const float* x     = (const float*)d_in[0];   // [2,2048,2048]
    const float* fc    = (const float*)d_in[1];   // [2048,32,2]
    // d_in[2] = mask (causal, hardcoded)
    const float* wqkv  = (const float*)d_in[3];   // [3072,2048]
    const float* wo    = (const float*)d_in[4];   // [2048,2048]
    float* out = (float*)d_out;                   // [2,2048,2048]

    void *p_qkv, *p_ao;
    void *p_xh, *p_xl, *p_wqh, *p_wql, *p_aoh, *p_aol, *p_woh, *p_wol;
    cudaGetSymbolAddress(&p_qkv, g_qkv);
    cudaGetSymbolAddress(&p_ao,  g_ao);
    cudaGetSymbolAddress(&p_xh,  g_xh);  cudaGetSymbolAddress(&p_xl,  g_xl);
    cudaGetSymbolAddress(&p_wqh, g_wqh); cudaGetSymbolAddress(&p_wql, g_wql);
    cudaGetSymbolAddress(&p_aoh, g_aoh); cudaGetSymbolAddress(&p_aol, g_aol);
    cudaGetSymbolAddress(&p_woh, g_woh); cudaGetSymbolAddress(&p_wol, g_wol);

    cudaFuncSetAttribute(gemm_hmma_kernel,
                         cudaFuncAttributeMaxDynamicSharedMemorySize, GT_SMEM_BYTES);

    const int M = BSZ * SEQ;                      // 4096

    split4_kernel<<<(M * DIM / 4 + 255) / 256, 256>>>(x,
        (__nv_bfloat16*)p_xh, (__nv_bfloat16*)p_xl, M * DIM / 4);
    split4_kernel<<<(QKV_N * DIM / 4 + 255) / 256, 256>>>(wqkv,
        (__nv_bfloat16*)p_wqh, (__nv_bfloat16*)p_wql, QKV_N * DIM / 4);
    split4_kernel<<<(DIM * DIM / 4 + 255) / 256, 256>>>(wo,
        (__nv_bfloat16*)p_woh, (__nv_bfloat16*)p_wol, DIM * DIM / 4);

    // 1) QKV projection
    gemm_hmma_kernel<<<dim3(QKV_N / 128, M / 128), 256, GT_SMEM_BYTES>>>(
        (const __nv_bfloat16*)p_xh, (const __nv_bfloat16*)p_xl,
        (const __nv_bfloat16*)p_wqh, (const __nv_bfloat16*)p_wql,
        (float*)p_qkv, M, QKV_N, DIM);

    // 2) RoPE + V split/transpose (all emit bf16 hi/lo)
    rope_q_kernel<<<(BSZ * SEQ * NH  * 32) / 256, 256>>>(fc);
    rope_k_kernel<<<(BSZ * SEQ * NKV * 32) / 256, 256>>>(fc);
    split_v_kernel<<<dim3(SEQ / 32, HD / 32, BSZ * NKV), 256>>>();

    // 3) causal flash attention on tensor cores -> g_ao [b,s,h*d]
    flash_hmma_kernel<<<dim3(SEQ / 128, NH, BSZ), 256>>>();

    // 4) output projection
    split4_kernel<<<(M * DIM / 4 + 255) / 256, 256>>>((const float*)p_ao,
        (__nv_bfloat16*)p_aoh, (__nv_bfloat16*)p_aol, M * DIM / 4);
    gemm_hmma_kernel<<<dim3(DIM / 128, M / 128), 256, GT_SMEM_BYTES>>>(
        (const __nv_bfloat16*)p_aoh, (const __nv_bfloat16*)p_aol,
        (const __nv_bfloat16*)p_woh, (const __nv_bfloat16*)p_wol,
        out, M, DIM, DIM);
}

// round 6
// speedup vs baseline: 2.6422x; 1.0348x over previous
#include <cuda_runtime.h>
#include <cuda_bf16.h>
#include <cstdint>
#include <cstddef>

#define BSZ 2
#define SEQ 2048
#define DIM 2048
#define NH 32
#define NKV 8
#define HD 64
#define QKV_N ((NH + 2*NKV)*HD)   // 3072

// ---------------- scratch (static device globals; no allocation) -----------
__device__ float g_qkv[(size_t)BSZ*SEQ*QKV_N];     // [4096, 3072]

// bf16 split operands (projection GEMMs)
__device__ __nv_bfloat16 g_xh [(size_t)BSZ*SEQ*DIM];
__device__ __nv_bfloat16 g_xl [(size_t)BSZ*SEQ*DIM];
__device__ __nv_bfloat16 g_wqh[(size_t)QKV_N*DIM];
__device__ __nv_bfloat16 g_wql[(size_t)QKV_N*DIM];
__device__ __nv_bfloat16 g_aoh[(size_t)BSZ*SEQ*DIM];
__device__ __nv_bfloat16 g_aol[(size_t)BSZ*SEQ*DIM];
__device__ __nv_bfloat16 g_woh[(size_t)DIM*DIM];
__device__ __nv_bfloat16 g_wol[(size_t)DIM*DIM];

// bf16 split Q/K/V for flash
__device__ __nv_bfloat16 g_qh[(size_t)BSZ*NH *SEQ*HD];   // [b,h,s,d] (pre-scaled)
__device__ __nv_bfloat16 g_ql[(size_t)BSZ*NH *SEQ*HD];
__device__ __nv_bfloat16 g_kh[(size_t)BSZ*NKV*SEQ*HD];   // [b,kv,s,d]
__device__ __nv_bfloat16 g_kl[(size_t)BSZ*NKV*SEQ*HD];
__device__ __nv_bfloat16 g_vh[(size_t)BSZ*NKV*HD*SEQ];   // [b,kv,d,s] transposed
__device__ __nv_bfloat16 g_vl[(size_t)BSZ*NKV*HD*SEQ];

// ---------------- small PTX helpers (sm_80-baseline ISA only) ---------------
__device__ __forceinline__ uint32_t smem_to_u32(const void* p) {
    uint32_t a;
    asm("{ .reg .u64 t; cvta.to.shared.u64 t, %1; cvt.u32.u64 %0, t; }"
        : "=r"(a) : "l"(p));
    return a;
}
__device__ __forceinline__ void cp_async16(uint32_t dst, const void* src) {
    asm volatile("cp.async.cg.shared.global [%0], [%1], 16;"
                 :: "r"(dst), "l"(src) : "memory");
}
#define CP_COMMIT() asm volatile("cp.async.commit_group;" ::: "memory")
#define CP_WAIT1()  asm volatile("cp.async.wait_group 1;" ::: "memory")
#define CP_WAIT0()  asm volatile("cp.async.wait_group 0;" ::: "memory")

__device__ __forceinline__ void ldsm4(uint32_t* r, uint32_t addr) {
    asm volatile("ldmatrix.sync.aligned.m8n8.x4.shared.b16 {%0,%1,%2,%3}, [%4];"
        : "=r"(r[0]), "=r"(r[1]), "=r"(r[2]), "=r"(r[3]) : "r"(addr));
}

// D += A(16x16 bf16) * B(16x8 bf16), fp32 accum
__device__ __forceinline__ void mma16816(float* d, const uint32_t* a,
                                         const uint32_t* b) {
    asm volatile(
        "mma.sync.aligned.m16n8k16.row.col.f32.bf16.bf16.f32 "
        "{%0,%1,%2,%3}, {%4,%5,%6,%7}, {%8,%9}, {%0,%1,%2,%3};"
        : "+f"(d[0]), "+f"(d[1]), "+f"(d[2]), "+f"(d[3])
        : "r"(a[0]), "r"(a[1]), "r"(a[2]), "r"(a[3]), "r"(b[0]), "r"(b[1]));
}

// ---------------- float -> (hi,lo) bf16 split -------------------------------
__global__ void split4_kernel(const float* __restrict__ src,
                              __nv_bfloat16* __restrict__ hi,
                              __nv_bfloat16* __restrict__ lo, int n4)
{
    int i = blockIdx.x * 256 + threadIdx.x;
    if (i >= n4) return;
    float4 v = ((const float4*)src)[i];
    __nv_bfloat16 h0 = __float2bfloat16(v.x);
    __nv_bfloat16 h1 = __float2bfloat16(v.y);
    __nv_bfloat16 h2 = __float2bfloat16(v.z);
    __nv_bfloat16 h3 = __float2bfloat16(v.w);
    __nv_bfloat16 l0 = __float2bfloat16(v.x - __bfloat162float(h0));
    __nv_bfloat16 l1 = __float2bfloat16(v.y - __bfloat162float(h1));
    __nv_bfloat16 l2 = __float2bfloat16(v.z - __bfloat162float(h2));
    __nv_bfloat16 l3 = __float2bfloat16(v.w - __bfloat162float(h3));
    ((__nv_bfloat162*)hi)[2*i]   = __nv_bfloat162(h0, h1);
    ((__nv_bfloat162*)hi)[2*i+1] = __nv_bfloat162(h2, h3);
    ((__nv_bfloat162*)lo)[2*i]   = __nv_bfloat162(l0, l1);
    ((__nv_bfloat162*)lo)[2*i+1] = __nv_bfloat162(l2, l3);
}

// ---------------- HMMA GEMM: C[M,N] = A[M,K] * B[N,K]^T ---------------------
#define GSTR 40
#define TILE_ELEMS (128 * GSTR)
#define TILE_BYTES (TILE_ELEMS * 2)
#define GT_SMEM_BYTES (2 * 4 * TILE_BYTES)      // 81920

__global__ __launch_bounds__(256, 2)
void gemm_hmma_kernel(const __nv_bfloat16* __restrict__ Ah,
                      const __nv_bfloat16* __restrict__ Al,
                      const __nv_bfloat16* __restrict__ Bh,
                      const __nv_bfloat16* __restrict__ Bl,
                      float* __restrict__ C, int M, int N, int K)
{
    extern __shared__ __nv_bfloat16 sm[];
    const uint32_t sbase = smem_to_u32(sm);
    const int t    = threadIdx.x;
    const int wid  = t >> 5, lane = t & 31;
    const int bm   = blockIdx.y * 128, bn = blockIdx.x * 128;
    const int wm   = (wid & 1) * 64;
    const int wn   = (wid >> 1) * 32;
    const int lr   = lane >> 2;
    const int lc   = lane & 3;

    // ldmatrix lane offsets
    const int arow = (lane & 7) + ((lane >> 3) & 1) * 8;
    const int acol = (lane >> 4) * 8;
    const uint32_t aoff = (uint32_t)(arow * GSTR + acol) * 2;
    const int brow = (lane & 7) + ((lane >> 4) & 1) * 8;
    const int bcol = ((lane >> 3) & 1) * 8;
    const uint32_t boff = (uint32_t)(brow * GSTR + bcol) * 2;

    const int r0 = t >> 2,  c0 = t & 3;
    const int r1 = (t + 256) >> 2, c1 = t & 3;

    float acc[4][4][4];
#pragma unroll
    for (int mi = 0; mi < 4; ++mi)
#pragma unroll
        for (int ni = 0; ni < 4; ++ni)
#pragma unroll
            for (int q = 0; q < 4; ++q) acc[mi][ni][q] = 0.f;

    const int nch = K / 32;

    auto load_chunk = [&](int buf, int kc) {
        const __nv_bfloat16* g[4];
        g[0] = Ah + (size_t)bm * K + kc * 32;
        g[1] = Al + (size_t)bm * K + kc * 32;
        g[2] = Bh + (size_t)bn * K + kc * 32;
        g[3] = Bl + (size_t)bn * K + kc * 32;
#pragma unroll
        for (int tile = 0; tile < 4; ++tile) {
            uint32_t sd = sbase + (buf * 4 + tile) * TILE_BYTES;
            cp_async16(sd + r0 * (GSTR*2) + c0 * 16, g[tile] + (size_t)r0 * K + c0 * 8);
            cp_async16(sd + r1 * (GSTR*2) + c1 * 16, g[tile] + (size_t)r1 * K + c1 * 8);
        }
    };

    load_chunk(0, 0);
    CP_COMMIT();

    for (int c = 0; c < nch; ++c) {
        const int buf = c & 1;
        if (c + 1 < nch) { load_chunk(buf ^ 1, c + 1); CP_COMMIT(); CP_WAIT1(); }
        else             { CP_WAIT0(); }
        __syncthreads();

        const uint32_t uAh = sbase + (buf * 4 + 0) * TILE_BYTES;
        const uint32_t uAl = sbase + (buf * 4 + 1) * TILE_BYTES;
        const uint32_t uBh = sbase + (buf * 4 + 2) * TILE_BYTES;
        const uint32_t uBl = sbase + (buf * 4 + 3) * TILE_BYTES;

#pragma unroll
        for (int ks = 0; ks < 2; ++ks) {
            uint32_t ah[4][4], al[4][4], bh4[2][4], bl4[2][4];
#pragma unroll
            for (int mi = 0; mi < 4; ++mi) {
                const uint32_t ra = (uint32_t)((wm + mi * 16) * GSTR) * 2 + ks * 32;
                ldsm4(ah[mi], uAh + ra + aoff);
                ldsm4(al[mi], uAl + ra + aoff);
            }
#pragma unroll
            for (int p = 0; p < 2; ++p) {
                const uint32_t rb = (uint32_t)((wn + p * 16) * GSTR) * 2 + ks * 32;
                ldsm4(bh4[p], uBh + rb + boff);
                ldsm4(bl4[p], uBl + rb + boff);
            }
#pragma unroll
            for (int mi = 0; mi < 4; ++mi)
#pragma unroll
                for (int ni = 0; ni < 4; ++ni) {
                    const uint32_t* bh = &bh4[ni >> 1][(ni & 1) * 2];
                    const uint32_t* bl = &bl4[ni >> 1][(ni & 1) * 2];
                    mma16816(acc[mi][ni], ah[mi], bh);
                    mma16816(acc[mi][ni], ah[mi], bl);
                    mma16816(acc[mi][ni], al[mi], bh);
                }
        }
        __syncthreads();
    }

#pragma unroll
    for (int mi = 0; mi < 4; ++mi) {
        const int row = bm + wm + mi * 16 + lr;
#pragma unroll
        for (int ni = 0; ni < 4; ++ni) {
            const int col = bn + wn + ni * 8 + lc * 2;
            *(float2*)&C[(size_t)row * N + col] =
                make_float2(acc[mi][ni][0], acc[mi][ni][1]);
            *(float2*)&C[(size_t)(row + 8) * N + col] =
                make_float2(acc[mi][ni][2], acc[mi][ni][3]);
        }
    }
}

// ---------------- RoPE -> bf16 hi/lo splits ---------------------------------
__device__ __forceinline__ void split_write(__nv_bfloat16* hi, __nv_bfloat16* lo,
                                            float v0, float v1)
{
    __nv_bfloat16 h0 = __float2bfloat16(v0);
    __nv_bfloat16 h1 = __float2bfloat16(v1);
    __nv_bfloat16 l0 = __float2bfloat16(v0 - __bfloat162float(h0));
    __nv_bfloat16 l1 = __float2bfloat16(v1 - __bfloat162float(h1));
    *(__nv_bfloat162*)hi = __nv_bfloat162(h0, h1);
    *(__nv_bfloat162*)lo = __nv_bfloat162(l0, l1);
}

__global__ void rope_q_kernel(const float* __restrict__ fc)
{
    int gid = blockIdx.x * 256 + threadIdx.x;
    int p = gid & 31;
    int h = (gid >> 5) & 31;
    int s = (gid >> 10) & 2047;
    int b = gid >> 21;
    const float* src = g_qkv + (size_t)(b * SEQ + s) * QKV_N + h * HD + 2 * p;
    float x0 = src[0], x1 = src[1];
    float c  = fc[s * HD + 2 * p];
    float sn = fc[s * HD + 2 * p + 1];
    size_t off = (((size_t)(b * NH + h)) * SEQ + s) * HD + 2 * p;
    split_write(g_qh + off, g_ql + off,
                (x0 * c - x1 * sn) * 0.125f, (x1 * c + x0 * sn) * 0.125f);
}

__global__ void rope_k_kernel(const float* __restrict__ fc)
{
    int gid = blockIdx.x * 256 + threadIdx.x;
    int p  = gid & 31;
    int kv = (gid >> 5) & 7;
    int s  = (gid >> 8) & 2047;
    int b  = gid >> 19;
    const float* src = g_qkv + (size_t)(b * SEQ + s) * QKV_N + DIM + kv * HD + 2 * p;
    float x0 = src[0], x1 = src[1];
    float c  = fc[s * HD + 2 * p];
    float sn = fc[s * HD + 2 * p + 1];
    size_t off = (((size_t)(b * NKV + kv)) * SEQ + s) * HD + 2 * p;
    split_write(g_kh + off, g_kl + off,
                x0 * c - x1 * sn, x1 * c + x0 * sn);
}

// V: split + transpose [s,d] -> [d,s] per (b,kv)
__global__ void split_v_kernel()
{
    __shared__ float tile[32][33];
    const int bk = blockIdx.z;                 // b*NKV + kv
    const int b  = bk >> 3, kv = bk & 7;
    const int s0 = blockIdx.x * 32;
    const int d0 = blockIdx.y * 32;
    const int tx = threadIdx.x & 31, ty = threadIdx.x >> 5;   // 32x8

    const float* src = g_qkv + (size_t)(b * SEQ + s0) * QKV_N
                       + DIM + NKV * HD + kv * HD + d0;
#pragma unroll
    for (int i = 0; i < 4; ++i)
        tile[ty + i * 8][tx] = src[(size_t)(ty + i * 8) * QKV_N + tx];
    __syncthreads();

    const size_t obase = ((size_t)bk * HD + d0) * SEQ + s0;
#pragma unroll
    for (int i = 0; i < 4; ++i) {
        int d = ty + i * 8;
        float v = tile[tx][d];
        __nv_bfloat16 h = __float2bfloat16(v);
        g_vh[obase + (size_t)d * SEQ + tx] = h;
        g_vl[obase + (size_t)d * SEQ + tx] = __float2bfloat16(v - __bfloat162float(h));
    }
}

// ---------------- flash attention on HMMA ------------------------------------
// Block: 128 q rows (8 warps x 16), KV tile 64. Split-bf16 both MMAs.
#define FSTR 72

__global__ __launch_bounds__(256)
void flash_hmma_kernel()
{
    __shared__ __nv_bfloat16 sKh[64 * FSTR];
    __shared__ __nv_bfloat16 sKl[64 * FSTR];
    __shared__ __nv_bfloat16 sVh[64 * FSTR];   // [d][key]
    __shared__ __nv_bfloat16 sVl[64 * FSTR];

    const int t = threadIdx.x;
    const int w = t >> 5, lane = t & 31;
    const int g = lane >> 2, tg = lane & 3;
    const int qb = blockIdx.x, h = blockIdx.y, b = blockIdx.z;
    const int kvh = h >> 2;
    const int qrow0 = qb * 128 + w * 16;

    const uint32_t uKh = smem_to_u32(sKh);
    const uint32_t uKl = smem_to_u32(sKl);
    const uint32_t uVh = smem_to_u32(sVh);
    const uint32_t uVl = smem_to_u32(sVl);

    // ldmatrix B-operand lane offset (rows 0..15, col halves)
    const int brow = (lane & 7) + ((lane >> 4) & 1) * 8;
    const int bcol = ((lane >> 3) & 1) * 8;
    const uint32_t boff = (uint32_t)(brow * FSTR + bcol) * 2;

    // Q fragments (hi/lo), 4 k-chunks of 16 over d=64
    uint32_t qfh[4][4], qfl[4][4];
    {
        const __nv_bfloat16* gq = g_qh + (((size_t)(b*NH+h))*SEQ + qrow0)*HD;
        const __nv_bfloat16* gl = g_ql + (((size_t)(b*NH+h))*SEQ + qrow0)*HD;
#pragma unroll
        for (int kk = 0; kk < 4; ++kk) {
            int d0 = kk * 16 + tg * 2;
            qfh[kk][0] = *(const uint32_t*)&gq[(size_t)(g    ) * HD + d0];
            qfh[kk][1] = *(const uint32_t*)&gq[(size_t)(g + 8) * HD + d0];
            qfh[kk][2] = *(const uint32_t*)&gq[(size_t)(g    ) * HD + d0 + 8];
            qfh[kk][3] = *(const uint32_t*)&gq[(size_t)(g + 8) * HD + d0 + 8];
            qfl[kk][0] = *(const uint32_t*)&gl[(size_t)(g    ) * HD + d0];
            qfl[kk][1] = *(const uint32_t*)&gl[(size_t)(g + 8) * HD + d0];
            qfl[kk][2] = *(const uint32_t*)&gl[(size_t)(g    ) * HD + d0 + 8];
            qfl[kk][3] = *(const uint32_t*)&gl[(size_t)(g + 8) * HD + d0 + 8];
        }
    }

    float m0 = -1e30f, m1 = -1e30f, l0 = 0.f, l1 = 0.f;
    float o[8][4];
#pragma unroll
    for (int ni = 0; ni < 8; ++ni)
#pragma unroll
        for (int q = 0; q < 4; ++q) o[ni][q] = 0.f;

    const __nv_bfloat16* gkh = g_kh + ((size_t)(b * NKV + kvh)) * SEQ * HD;
    const __nv_bfloat16* gkl = g_kl + ((size_t)(b * NKV + kvh)) * SEQ * HD;
    const __nv_bfloat16* gvh = g_vh + ((size_t)(b * NKV + kvh)) * HD * SEQ;
    const __nv_bfloat16* gvl = g_vl + ((size_t)(b * NKV + kvh)) * HD * SEQ;

    const int ntile = 2 * qb + 2;
    for (int jb = 0; jb < ntile; ++jb) {
        __syncthreads();
        {
#pragma unroll
            for (int cc = 0; cc < 2; ++cc) {
                int c   = t + cc * 256;
                int row = c >> 3, col = (c & 7) * 8;
                *(uint4*)&sKh[row * FSTR + col] =
                    *(const uint4*)&gkh[(size_t)(jb * 64 + row) * HD + col];
                *(uint4*)&sKl[row * FSTR + col] =
                    *(const uint4*)&gkl[(size_t)(jb * 64 + row) * HD + col];
                *(uint4*)&sVh[row * FSTR + col] =
                    *(const uint4*)&gvh[(size_t)row * SEQ + jb * 64 + col];
                *(uint4*)&sVl[row * FSTR + col] =
                    *(const uint4*)&gvl[(size_t)row * SEQ + jb * 64 + col];
            }
        }
        __syncthreads();

        if (jb * 64 > qrow0 + 15) continue;   // fully masked for this warp

        // S = Q K^T
        float s[8][4];
#pragma unroll
        for (int ni = 0; ni < 8; ++ni)
            s[ni][0] = s[ni][1] = s[ni][2] = s[ni][3] = 0.f;

#pragma unroll
        for (int kk = 0; kk < 4; ++kk)
#pragma unroll
            for (int p = 0; p < 4; ++p) {
                const uint32_t rb = (uint32_t)(p * 16 * FSTR) * 2 + kk * 32;
                uint32_t kh4[4], kl4[4];
                ldsm4(kh4, uKh + rb + boff);
                ldsm4(kl4, uKl + rb + boff);
                mma16816(s[2*p],   qfh[kk], kh4 + 0);
                mma16816(s[2*p],   qfh[kk], kl4 + 0);
                mma16816(s[2*p],   qfl[kk], kh4 + 0);
                mma16816(s[2*p+1], qfh[kk], kh4 + 2);
                mma16816(s[2*p+1], qfh[kk], kl4 + 2);
                mma16816(s[2*p+1], qfl[kk], kh4 + 2);
            }

        // causal mask (diagonal tiles only)
        if (jb * 64 + 63 > qrow0) {
            const int cb = jb * 64 + tg * 2;
            const int r0 = qrow0 + g, r1 = r0 + 8;
#pragma unroll
            for (int ni = 0; ni < 8; ++ni) {
                int c0 = cb + ni * 8, c1 = c0 + 1;
                if (c0 > r0) s[ni][0] = -1e30f;
                if (c1 > r0) s[ni][1] = -1e30f;
                if (c0 > r1) s[ni][2] = -1e30f;
                if (c1 > r1) s[ni][3] = -1e30f;
            }
        }

        // online softmax
        float mt0 = -1e30f, mt1 = -1e30f;
#pragma unroll
        for (int ni = 0; ni < 8; ++ni) {
            mt0 = fmaxf(mt0, fmaxf(s[ni][0], s[ni][1]));
            mt1 = fmaxf(mt1, fmaxf(s[ni][2], s[ni][3]));
        }
        mt0 = fmaxf(mt0, __shfl_xor_sync(0xffffffffu, mt0, 1));
        mt0 = fmaxf(mt0, __shfl_xor_sync(0xffffffffu, mt0, 2));
        mt1 = fmaxf(mt1, __shfl_xor_sync(0xffffffffu, mt1, 1));
        mt1 = fmaxf(mt1, __shfl_xor_sync(0xffffffffu, mt1, 2));
        float mn0 = fmaxf(m0, mt0), mn1 = fmaxf(m1, mt1);
        float a0 = __expf(m0 - mn0), a1 = __expf(m1 - mn1);
        m0 = mn0; m1 = mn1;
        float rs0 = 0.f, rs1 = 0.f;
#pragma unroll
        for (int ni = 0; ni < 8; ++ni) {
            s[ni][0] = __expf(s[ni][0] - mn0);
            s[ni][1] = __expf(s[ni][1] - mn0);
            s[ni][2] = __expf(s[ni][2] - mn1);
            s[ni][3] = __expf(s[ni][3] - mn1);
            rs0 += s[ni][0] + s[ni][1];
            rs1 += s[ni][2] + s[ni][3];
        }
        l0 = l0 * a0 + rs0;
        l1 = l1 * a1 + rs1;
#pragma unroll
        for (int ni = 0; ni < 8; ++ni) {
            o[ni][0] *= a0; o[ni][1] *= a0;
            o[ni][2] *= a1; o[ni][3] *= a1;
        }

        // O += P V. P A-fragments from S C-fragments.
#pragma unroll
        for (int kk = 0; kk < 4; ++kk) {
            uint32_t ph[4], pl[4];
#pragma unroll
            for (int half = 0; half < 2; ++half) {
                const int ni = 2 * kk + half;
                __nv_bfloat162 h0 = __floats2bfloat162_rn(s[ni][0], s[ni][1]);
                __nv_bfloat162 l0v = __floats2bfloat162_rn(
                    s[ni][0] - __bfloat162float(h0.x),
                    s[ni][1] - __bfloat162float(h0.y));
                __nv_bfloat162 h1 = __floats2bfloat162_rn(s[ni][2], s[ni][3]);
                __nv_bfloat162 l1v = __floats2bfloat162_rn(
                    s[ni][2] - __bfloat162float(h1.x),
                    s[ni][3] - __bfloat162float(h1.y));
                ph[half * 2 + 0] = *(uint32_t*)&h0;
                ph[half * 2 + 1] = *(uint32_t*)&h1;
                pl[half * 2 + 0] = *(uint32_t*)&l0v;
                pl[half * 2 + 1] = *(uint32_t*)&l1v;
            }
#pragma unroll
            for (int p = 0; p < 4; ++p) {
                const uint32_t rb = (uint32_t)(p * 16 * FSTR) * 2 + kk * 32;
                uint32_t vh4[4], vl4[4];
                ldsm4(vh4, uVh + rb + boff);
                ldsm4(vl4, uVl + rb + boff);
                mma16816(o[2*p],   ph, vh4 + 0);
                mma16816(o[2*p],   ph, vl4 + 0);
                mma16816(o[2*p],   pl, vh4 + 0);
                mma16816(o[2*p+1], ph, vh4 + 2);
                mma16816(o[2*p+1], ph, vl4 + 2);
                mma16816(o[2*p+1], pl, vh4 + 2);
            }
        }
    }

    // finalize: write bf16 hi/lo splits directly (feeds out-projection)
    l0 += __shfl_xor_sync(0xffffffffu, l0, 1);
    l0 += __shfl_xor_sync(0xffffffffu, l0, 2);
    l1 += __shfl_xor_sync(0xffffffffu, l1, 1);
    l1 += __shfl_xor_sync(0xffffffffu, l1, 2);
    const float inv0 = 1.f / l0, inv1 = 1.f / l1;

    const int r0 = qrow0 + g, r1 = r0 + 8;
#pragma unroll
    for (int ni = 0; ni < 8; ++ni) {
        const int col = h * HD + ni * 8 + tg * 2;
        {
            float v0 = o[ni][0] * inv0, v1 = o[ni][1] * inv0;
            __nv_bfloat162 hv = __floats2bfloat162_rn(v0, v1);
            __nv_bfloat162 lv = __floats2bfloat162_rn(
                v0 - __bfloat162float(hv.x), v1 - __bfloat162float(hv.y));
            size_t i0 = (size_t)(b * SEQ + r0) * DIM + col;
            *(__nv_bfloat162*)&g_aoh[i0] = hv;
            *(__nv_bfloat162*)&g_aol[i0] = lv;
        }
        {
            float v0 = o[ni][2] * inv1, v1 = o[ni][3] * inv1;
            __nv_bfloat162 hv = __floats2bfloat162_rn(v0, v1);
            __nv_bfloat162 lv = __floats2bfloat162_rn(
                v0 - __bfloat162float(hv.x), v1 - __bfloat162float(hv.y));
            size_t i1 = (size_t)(b * SEQ + r1) * DIM + col;
            *(__nv_bfloat162*)&g_aoh[i1] = hv;
            *(__nv_bfloat162*)&g_aol[i1] = lv;
        }
    }
}

// ---------------- launcher ---------------------------------------------------
extern "C" void kernel_launch(void* const* d_in, const int* in_sizes, int n_in,
                              void* d_out, int out_size)
{
    const float* x     = (const float*)d_in[0];   // [2,2048,2048]
    const float* fc    = (const float*)d_in[1];   // [2048,32,2]
    // d_in[2] = mask (causal, hardcoded)
    const float* wqkv  = (const float*)d_in[3];   // [3072,2048]
    const float* wo    = (const float*)d_in[4];   // [2048,2048]
    float* out = (float*)d_out;                   // [2,2048,2048]

    void *p_qkv;
    void *p_xh, *p_xl, *p_wqh, *p_wql, *p_aoh, *p_aol, *p_woh, *p_wol;
    cudaGetSymbolAddress(&p_qkv, g_qkv);
    cudaGetSymbolAddress(&p_xh,  g_xh);  cudaGetSymbolAddress(&p_xl,  g_xl);
    cudaGetSymbolAddress(&p_wqh, g_wqh); cudaGetSymbolAddress(&p_wql, g_wql);
    cudaGetSymbolAddress(&p_aoh, g_aoh); cudaGetSymbolAddress(&p_aol, g_aol);
    cudaGetSymbolAddress(&p_woh, g_woh); cudaGetSymbolAddress(&p_wol, g_wol);

    cudaFuncSetAttribute(gemm_hmma_kernel,
                         cudaFuncAttributeMaxDynamicSharedMemorySize, GT_SMEM_BYTES);

    const int M = BSZ * SEQ;                      // 4096

    split4_kernel<<<(M * DIM / 4 + 255) / 256, 256>>>(x,
        (__nv_bfloat16*)p_xh, (__nv_bfloat16*)p_xl, M * DIM / 4);
    split4_kernel<<<(QKV_N * DIM / 4 + 255) / 256, 256>>>(wqkv,
        (__nv_bfloat16*)p_wqh, (__nv_bfloat16*)p_wql, QKV_N * DIM / 4);
    split4_kernel<<<(DIM * DIM / 4 + 255) / 256, 256>>>(wo,
        (__nv_bfloat16*)p_woh, (__nv_bfloat16*)p_wol, DIM * DIM / 4);

    // 1) QKV projection
    gemm_hmma_kernel<<<dim3(QKV_N / 128, M / 128), 256, GT_SMEM_BYTES>>>(
        (const __nv_bfloat16*)p_xh, (const __nv_bfloat16*)p_xl,
        (const __nv_bfloat16*)p_wqh, (const __nv_bfloat16*)p_wql,
        (float*)p_qkv, M, QKV_N, DIM);

    // 2) RoPE + V split/transpose (all emit bf16 hi/lo)
    rope_q_kernel<<<(BSZ * SEQ * NH  * 32) / 256, 256>>>(fc);
    rope_k_kernel<<<(BSZ * SEQ * NKV * 32) / 256, 256>>>(fc);
    split_v_kernel<<<dim3(SEQ / 32, HD / 32, BSZ * NKV), 256>>>();

    // 3) causal flash attention -> g_aoh/g_aol [b,s,h*d] (bf16 hi/lo)
    flash_hmma_kernel<<<dim3(SEQ / 128, NH, BSZ), 256>>>();

    // 4) output projection
    gemm_hmma_kernel<<<dim3(DIM / 128, M / 128), 256, GT_SMEM_BYTES>>>(
        (const __nv_bfloat16*)p_aoh, (const __nv_bfloat16*)p_aol,
        (const __nv_bfloat16*)p_woh, (const __nv_bfloat16*)p_wol,
        out, M, DIM, DIM);
}

// round 7
// speedup vs baseline: 3.5681x; 1.3504x over previous
#include <cuda_runtime.h>
#include <cuda_fp16.h>
#include <cstdint>
#include <cstddef>

#define BSZ 2
#define SEQ 2048
#define DIM 2048
#define NH 32
#define NKV 8
#define HD 64
#define QKV_N ((NH + 2*NKV)*HD)   // 3072

// ---------------- scratch (static device globals; no allocation) -----------
__device__ float g_qkv[(size_t)BSZ*SEQ*QKV_N];     // [4096, 3072]

// fp16 operands: activations split hi/lo, weights single
__device__ __half g_xh [(size_t)BSZ*SEQ*DIM];
__device__ __half g_xl [(size_t)BSZ*SEQ*DIM];
__device__ __half g_wq [(size_t)QKV_N*DIM];
__device__ __half g_aoh[(size_t)BSZ*SEQ*DIM];
__device__ __half g_aol[(size_t)BSZ*SEQ*DIM];
__device__ __half g_wo [(size_t)DIM*DIM];

// fp16 Q (split, pre-scaled), K/V single
__device__ __half g_qh[(size_t)BSZ*NH *SEQ*HD];    // [b,h,s,d]
__device__ __half g_ql[(size_t)BSZ*NH *SEQ*HD];
__device__ __half g_k [(size_t)BSZ*NKV*SEQ*HD];    // [b,kv,s,d]
__device__ __half g_v [(size_t)BSZ*NKV*HD*SEQ];    // [b,kv,d,s] transposed

// ---------------- small PTX helpers (sm_80-baseline ISA only) ---------------
__device__ __forceinline__ uint32_t smem_to_u32(const void* p) {
    uint32_t a;
    asm("{ .reg .u64 t; cvta.to.shared.u64 t, %1; cvt.u32.u64 %0, t; }"
        : "=r"(a) : "l"(p));
    return a;
}
__device__ __forceinline__ void cp_async16(uint32_t dst, const void* src) {
    asm volatile("cp.async.cg.shared.global [%0], [%1], 16;"
                 :: "r"(dst), "l"(src) : "memory");
}
#define CP_COMMIT() asm volatile("cp.async.commit_group;" ::: "memory")
#define CP_WAIT1()  asm volatile("cp.async.wait_group 1;" ::: "memory")
#define CP_WAIT0()  asm volatile("cp.async.wait_group 0;" ::: "memory")

__device__ __forceinline__ void ldsm4(uint32_t* r, uint32_t addr) {
    asm volatile("ldmatrix.sync.aligned.m8n8.x4.shared.b16 {%0,%1,%2,%3}, [%4];"
        : "=r"(r[0]), "=r"(r[1]), "=r"(r[2]), "=r"(r[3]) : "r"(addr));
}

// D += A(16x16 fp16) * B(16x8 fp16), fp32 accum
__device__ __forceinline__ void mma16816(float* d, const uint32_t* a,
                                         const uint32_t* b) {
    asm volatile(
        "mma.sync.aligned.m16n8k16.row.col.f32.f16.f16.f32 "
        "{%0,%1,%2,%3}, {%4,%5,%6,%7}, {%8,%9}, {%0,%1,%2,%3};"
        : "+f"(d[0]), "+f"(d[1]), "+f"(d[2]), "+f"(d[3])
        : "r"(a[0]), "r"(a[1]), "r"(a[2]), "r"(a[3]), "r"(b[0]), "r"(b[1]));
}

// ---------------- conversion kernels ----------------------------------------
__global__ void split4h_kernel(const float* __restrict__ src,
                               __half* __restrict__ hi,
                               __half* __restrict__ lo, int n4)
{
    int i = blockIdx.x * 256 + threadIdx.x;
    if (i >= n4) return;
    float4 v = ((const float4*)src)[i];
    __half h0 = __float2half_rn(v.x), h1 = __float2half_rn(v.y);
    __half h2 = __float2half_rn(v.z), h3 = __float2half_rn(v.w);
    __half l0 = __float2half_rn(v.x - __half2float(h0));
    __half l1 = __float2half_rn(v.y - __half2float(h1));
    __half l2 = __float2half_rn(v.z - __half2float(h2));
    __half l3 = __float2half_rn(v.w - __half2float(h3));
    ((__half2*)hi)[2*i]   = __half2(h0, h1);
    ((__half2*)hi)[2*i+1] = __half2(h2, h3);
    ((__half2*)lo)[2*i]   = __half2(l0, l1);
    ((__half2*)lo)[2*i+1] = __half2(l2, l3);
}

__global__ void conv4h_kernel(const float* __restrict__ src,
                              __half* __restrict__ dst, int n4)
{
    int i = blockIdx.x * 256 + threadIdx.x;
    if (i >= n4) return;
    float4 v = ((const float4*)src)[i];
    ((__half2*)dst)[2*i]   = __floats2half2_rn(v.x, v.y);
    ((__half2*)dst)[2*i+1] = __floats2half2_rn(v.z, v.w);
}

// ---------------- HMMA GEMM: C[M,N] = (Ah+Al)[M,K] * B[N,K]^T ---------------
#define GSTR 40
#define TILE_ELEMS (128 * GSTR)
#define TILE_BYTES (TILE_ELEMS * 2)
#define GT_SMEM_BYTES (2 * 3 * TILE_BYTES)      // 61440

__global__ __launch_bounds__(256, 2)
void gemm_hmma_kernel(const __half* __restrict__ Ah,
                      const __half* __restrict__ Al,
                      const __half* __restrict__ B,
                      float* __restrict__ C, int M, int N, int K)
{
    extern __shared__ __half sm[];
    const uint32_t sbase = smem_to_u32(sm);
    const int t    = threadIdx.x;
    const int wid  = t >> 5, lane = t & 31;
    const int bm   = blockIdx.y * 128, bn = blockIdx.x * 128;
    const int wm   = (wid & 1) * 64;
    const int wn   = (wid >> 1) * 32;
    const int lr   = lane >> 2;
    const int lc   = lane & 3;

    // ldmatrix lane offsets
    const int arow = (lane & 7) + ((lane >> 3) & 1) * 8;
    const int acol = (lane >> 4) * 8;
    const uint32_t aoff = (uint32_t)(arow * GSTR + acol) * 2;
    const int brow = (lane & 7) + ((lane >> 4) & 1) * 8;
    const int bcol = ((lane >> 3) & 1) * 8;
    const uint32_t boff = (uint32_t)(brow * GSTR + bcol) * 2;

    const int r0 = t >> 2,  c0 = t & 3;
    const int r1 = (t + 256) >> 2, c1 = t & 3;

    float acc[4][4][4];
#pragma unroll
    for (int mi = 0; mi < 4; ++mi)
#pragma unroll
        for (int ni = 0; ni < 4; ++ni)
#pragma unroll
            for (int q = 0; q < 4; ++q) acc[mi][ni][q] = 0.f;

    const int nch = K / 32;

    auto load_chunk = [&](int buf, int kc) {
        const __half* g[3];
        g[0] = Ah + (size_t)bm * K + kc * 32;
        g[1] = Al + (size_t)bm * K + kc * 32;
        g[2] = B  + (size_t)bn * K + kc * 32;
#pragma unroll
        for (int tile = 0; tile < 3; ++tile) {
            uint32_t sd = sbase + (buf * 3 + tile) * TILE_BYTES;
            cp_async16(sd + r0 * (GSTR*2) + c0 * 16, g[tile] + (size_t)r0 * K + c0 * 8);
            cp_async16(sd + r1 * (GSTR*2) + c1 * 16, g[tile] + (size_t)r1 * K + c1 * 8);
        }
    };

    load_chunk(0, 0);
    CP_COMMIT();

    for (int c = 0; c < nch; ++c) {
        const int buf = c & 1;
        if (c + 1 < nch) { load_chunk(buf ^ 1, c + 1); CP_COMMIT(); CP_WAIT1(); }
        else             { CP_WAIT0(); }
        __syncthreads();

        const uint32_t uAh = sbase + (buf * 3 + 0) * TILE_BYTES;
        const uint32_t uAl = sbase + (buf * 3 + 1) * TILE_BYTES;
        const uint32_t uB  = sbase + (buf * 3 + 2) * TILE_BYTES;

#pragma unroll
        for (int ks = 0; ks < 2; ++ks) {
            uint32_t ah[4][4], al[4][4], b4[2][4];
#pragma unroll
            for (int mi = 0; mi < 4; ++mi) {
                const uint32_t ra = (uint32_t)((wm + mi * 16) * GSTR) * 2 + ks * 32;
                ldsm4(ah[mi], uAh + ra + aoff);
                ldsm4(al[mi], uAl + ra + aoff);
            }
#pragma unroll
            for (int p = 0; p < 2; ++p) {
                const uint32_t rb = (uint32_t)((wn + p * 16) * GSTR) * 2 + ks * 32;
                ldsm4(b4[p], uB + rb + boff);
            }
            // pass-outer ordering: consecutive MMAs hit different accumulators
#pragma unroll
            for (int mi = 0; mi < 4; ++mi)
#pragma unroll
                for (int ni = 0; ni < 4; ++ni)
                    mma16816(acc[mi][ni], ah[mi], &b4[ni >> 1][(ni & 1) * 2]);
#pragma unroll
            for (int mi = 0; mi < 4; ++mi)
#pragma unroll
                for (int ni = 0; ni < 4; ++ni)
                    mma16816(acc[mi][ni], al[mi], &b4[ni >> 1][(ni & 1) * 2]);
        }
        __syncthreads();
    }

#pragma unroll
    for (int mi = 0; mi < 4; ++mi) {
        const int row = bm + wm + mi * 16 + lr;
#pragma unroll
        for (int ni = 0; ni < 4; ++ni) {
            const int col = bn + wn + ni * 8 + lc * 2;
            *(float2*)&C[(size_t)row * N + col] =
                make_float2(acc[mi][ni][0], acc[mi][ni][1]);
            *(float2*)&C[(size_t)(row + 8) * N + col] =
                make_float2(acc[mi][ni][2], acc[mi][ni][3]);
        }
    }
}

// ---------------- RoPE -> fp16 -----------------------------------------------
__global__ void rope_q_kernel(const float* __restrict__ fc)
{
    int gid = blockIdx.x * 256 + threadIdx.x;
    int p = gid & 31;
    int h = (gid >> 5) & 31;
    int s = (gid >> 10) & 2047;
    int b = gid >> 21;
    const float* src = g_qkv + (size_t)(b * SEQ + s) * QKV_N + h * HD + 2 * p;
    float x0 = src[0], x1 = src[1];
    float c  = fc[s * HD + 2 * p];
    float sn = fc[s * HD + 2 * p + 1];
    float v0 = (x0 * c - x1 * sn) * 0.125f;
    float v1 = (x1 * c + x0 * sn) * 0.125f;
    size_t off = (((size_t)(b * NH + h)) * SEQ + s) * HD + 2 * p;
    __half h0 = __float2half_rn(v0), h1 = __float2half_rn(v1);
    *(__half2*)(g_qh + off) = __half2(h0, h1);
    *(__half2*)(g_ql + off) = __half2(
        __float2half_rn(v0 - __half2float(h0)),
        __float2half_rn(v1 - __half2float(h1)));
}

__global__ void rope_k_kernel(const float* __restrict__ fc)
{
    int gid = blockIdx.x * 256 + threadIdx.x;
    int p  = gid & 31;
    int kv = (gid >> 5) & 7;
    int s  = (gid >> 8) & 2047;
    int b  = gid >> 19;
    const float* src = g_qkv + (size_t)(b * SEQ + s) * QKV_N + DIM + kv * HD + 2 * p;
    float x0 = src[0], x1 = src[1];
    float c  = fc[s * HD + 2 * p];
    float sn = fc[s * HD + 2 * p + 1];
    size_t off = (((size_t)(b * NKV + kv)) * SEQ + s) * HD + 2 * p;
    *(__half2*)(g_k + off) =
        __floats2half2_rn(x0 * c - x1 * sn, x1 * c + x0 * sn);
}

// V: convert + transpose [s,d] -> [d,s] per (b,kv)
__global__ void split_v_kernel()
{
    __shared__ float tile[32][33];
    const int bk = blockIdx.z;                 // b*NKV + kv
    const int b  = bk >> 3, kv = bk & 7;
    const int s0 = blockIdx.x * 32;
    const int d0 = blockIdx.y * 32;
    const int tx = threadIdx.x & 31, ty = threadIdx.x >> 5;   // 32x8

    const float* src = g_qkv + (size_t)(b * SEQ + s0) * QKV_N
                       + DIM + NKV * HD + kv * HD + d0;
#pragma unroll
    for (int i = 0; i < 4; ++i)
        tile[ty + i * 8][tx] = src[(size_t)(ty + i * 8) * QKV_N + tx];
    __syncthreads();

    const size_t obase = ((size_t)bk * HD + d0) * SEQ + s0;
#pragma unroll
    for (int i = 0; i < 4; ++i) {
        int d = ty + i * 8;
        g_v[obase + (size_t)d * SEQ + tx] = __float2half_rn(tile[tx][d]);
    }
}

// ---------------- flash attention on HMMA ------------------------------------
// Block: 128 q rows (8 warps x 16), KV tile 64. Q/P split fp16, K/V single.
#define FSTR 72

__global__ __launch_bounds__(256)
void flash_hmma_kernel()
{
    __shared__ __half sK[64 * FSTR];
    __shared__ __half sV[64 * FSTR];   // [d][key]

    const int t = threadIdx.x;
    const int w = t >> 5, lane = t & 31;
    const int g = lane >> 2, tg = lane & 3;
    const int qb = blockIdx.x, h = blockIdx.y, b = blockIdx.z;
    const int kvh = h >> 2;
    const int qrow0 = qb * 128 + w * 16;

    const uint32_t uK = smem_to_u32(sK);
    const uint32_t uV = smem_to_u32(sV);

    const int brow = (lane & 7) + ((lane >> 4) & 1) * 8;
    const int bcol = ((lane >> 3) & 1) * 8;
    const uint32_t boff = (uint32_t)(brow * FSTR + bcol) * 2;

    // Q fragments (hi/lo), 4 k-chunks of 16 over d=64
    uint32_t qfh[4][4], qfl[4][4];
    {
        const __half* gq = g_qh + (((size_t)(b*NH+h))*SEQ + qrow0)*HD;
        const __half* gl = g_ql + (((size_t)(b*NH+h))*SEQ + qrow0)*HD;
#pragma unroll
        for (int kk = 0; kk < 4; ++kk) {
            int d0 = kk * 16 + tg * 2;
            qfh[kk][0] = *(const uint32_t*)&gq[(size_t)(g    ) * HD + d0];
            qfh[kk][1] = *(const uint32_t*)&gq[(size_t)(g + 8) * HD + d0];
            qfh[kk][2] = *(const uint32_t*)&gq[(size_t)(g    ) * HD + d0 + 8];
            qfh[kk][3] = *(const uint32_t*)&gq[(size_t)(g + 8) * HD + d0 + 8];
            qfl[kk][0] = *(const uint32_t*)&gl[(size_t)(g    ) * HD + d0];
            qfl[kk][1] = *(const uint32_t*)&gl[(size_t)(g + 8) * HD + d0];
            qfl[kk][2] = *(const uint32_t*)&gl[(size_t)(g    ) * HD + d0 + 8];
            qfl[kk][3] = *(const uint32_t*)&gl[(size_t)(g + 8) * HD + d0 + 8];
        }
    }

    float m0 = -1e30f, m1 = -1e30f, l0 = 0.f, l1 = 0.f;
    float o[8][4];
#pragma unroll
    for (int ni = 0; ni < 8; ++ni)
#pragma unroll
        for (int q = 0; q < 4; ++q) o[ni][q] = 0.f;

    const __half* gk = g_k + ((size_t)(b * NKV + kvh)) * SEQ * HD;
    const __half* gv = g_v + ((size_t)(b * NKV + kvh)) * HD * SEQ;

    const int ntile = 2 * qb + 2;
    for (int jb = 0; jb < ntile; ++jb) {
        __syncthreads();
        {
#pragma unroll
            for (int cc = 0; cc < 2; ++cc) {
                int c   = t + cc * 256;
                int row = c >> 3, col = (c & 7) * 8;
                *(uint4*)&sK[row * FSTR + col] =
                    *(const uint4*)&gk[(size_t)(jb * 64 + row) * HD + col];
                *(uint4*)&sV[row * FSTR + col] =
                    *(const uint4*)&gv[(size_t)row * SEQ + jb * 64 + col];
            }
        }
        __syncthreads();

        if (jb * 64 > qrow0 + 15) continue;   // fully masked for this warp

        // S = Q K^T
        float s[8][4];
#pragma unroll
        for (int ni = 0; ni < 8; ++ni)
            s[ni][0] = s[ni][1] = s[ni][2] = s[ni][3] = 0.f;

#pragma unroll
        for (int kk = 0; kk < 4; ++kk)
#pragma unroll
            for (int p = 0; p < 4; ++p) {
                const uint32_t rb = (uint32_t)(p * 16 * FSTR) * 2 + kk * 32;
                uint32_t k4[4];
                ldsm4(k4, uK + rb + boff);
                mma16816(s[2*p],   qfh[kk], k4 + 0);
                mma16816(s[2*p+1], qfh[kk], k4 + 2);
                mma16816(s[2*p],   qfl[kk], k4 + 0);
                mma16816(s[2*p+1], qfl[kk], k4 + 2);
            }

        // causal mask (diagonal tiles only)
        if (jb * 64 + 63 > qrow0) {
            const int cb = jb * 64 + tg * 2;
            const int r0 = qrow0 + g, r1 = r0 + 8;
#pragma unroll
            for (int ni = 0; ni < 8; ++ni) {
                int c0 = cb + ni * 8, c1 = c0 + 1;
                if (c0 > r0) s[ni][0] = -1e30f;
                if (c1 > r0) s[ni][1] = -1e30f;
                if (c0 > r1) s[ni][2] = -1e30f;
                if (c1 > r1) s[ni][3] = -1e30f;
            }
        }

        // online softmax
        float mt0 = -1e30f, mt1 = -1e30f;
#pragma unroll
        for (int ni = 0; ni < 8; ++ni) {
            mt0 = fmaxf(mt0, fmaxf(s[ni][0], s[ni][1]));
            mt1 = fmaxf(mt1, fmaxf(s[ni][2], s[ni][3]));
        }
        mt0 = fmaxf(mt0, __shfl_xor_sync(0xffffffffu, mt0, 1));
        mt0 = fmaxf(mt0, __shfl_xor_sync(0xffffffffu, mt0, 2));
        mt1 = fmaxf(mt1, __shfl_xor_sync(0xffffffffu, mt1, 1));
        mt1 = fmaxf(mt1, __shfl_xor_sync(0xffffffffu, mt1, 2));
        float mn0 = fmaxf(m0, mt0), mn1 = fmaxf(m1, mt1);
        float a0 = __expf(m0 - mn0), a1 = __expf(m1 - mn1);
        m0 = mn0; m1 = mn1;
        float rs0 = 0.f, rs1 = 0.f;
#pragma unroll
        for (int ni = 0; ni < 8; ++ni) {
            s[ni][0] = __expf(s[ni][0] - mn0);
            s[ni][1] = __expf(s[ni][1] - mn0);
            s[ni][2] = __expf(s[ni][2] - mn1);
            s[ni][3] = __expf(s[ni][3] - mn1);
            rs0 += s[ni][0] + s[ni][1];
            rs1 += s[ni][2] + s[ni][3];
        }
        l0 = l0 * a0 + rs0;
        l1 = l1 * a1 + rs1;
#pragma unroll
        for (int ni = 0; ni < 8; ++ni) {
            o[ni][0] *= a0; o[ni][1] *= a0;
            o[ni][2] *= a1; o[ni][3] *= a1;
        }

        // O += P V. P split hi/lo fp16, V single.
#pragma unroll
        for (int kk = 0; kk < 4; ++kk) {
            uint32_t ph[4], pl[4];
#pragma unroll
            for (int half = 0; half < 2; ++half) {
                const int ni = 2 * kk + half;
                __half2 h0 = __floats2half2_rn(s[ni][0], s[ni][1]);
                __half2 l0v = __floats2half2_rn(
                    s[ni][0] - __half2float(h0.x),
                    s[ni][1] - __half2float(h0.y));
                __half2 h1 = __floats2half2_rn(s[ni][2], s[ni][3]);
                __half2 l1v = __floats2half2_rn(
                    s[ni][2] - __half2float(h1.x),
                    s[ni][3] - __half2float(h1.y));
                ph[half * 2 + 0] = *(uint32_t*)&h0;
                ph[half * 2 + 1] = *(uint32_t*)&h1;
                pl[half * 2 + 0] = *(uint32_t*)&l0v;
                pl[half * 2 + 1] = *(uint32_t*)&l1v;
            }
#pragma unroll
            for (int p = 0; p < 4; ++p) {
                const uint32_t rb = (uint32_t)(p * 16 * FSTR) * 2 + kk * 32;
                uint32_t v4[4];
                ldsm4(v4, uV + rb + boff);
                mma16816(o[2*p],   ph, v4 + 0);
                mma16816(o[2*p+1], ph, v4 + 2);
                mma16816(o[2*p],   pl, v4 + 0);
                mma16816(o[2*p+1], pl, v4 + 2);
            }
        }
    }

    // finalize: write fp16 hi/lo splits directly (feeds out-projection)
    l0 += __shfl_xor_sync(0xffffffffu, l0, 1);
    l0 += __shfl_xor_sync(0xffffffffu, l0, 2);
    l1 += __shfl_xor_sync(0xffffffffu, l1, 1);
    l1 += __shfl_xor_sync(0xffffffffu, l1, 2);
    const float inv0 = 1.f / l0, inv1 = 1.f / l1;

    const int r0 = qrow0 + g, r1 = r0 + 8;
#pragma unroll
    for (int ni = 0; ni < 8; ++ni) {
        const int col = h * HD + ni * 8 + tg * 2;
        {
            float v0 = o[ni][0] * inv0, v1 = o[ni][1] * inv0;
            __half2 hv = __floats2half2_rn(v0, v1);
            __half2 lv = __floats2half2_rn(
                v0 - __half2float(hv.x), v1 - __half2float(hv.y));
            size_t i0 = (size_t)(b * SEQ + r0) * DIM + col;
            *(__half2*)&g_aoh[i0] = hv;
            *(__half2*)&g_aol[i0] = lv;
        }
        {
            float v0 = o[ni][2] * inv1, v1 = o[ni][3] * inv1;
            __half2 hv = __floats2half2_rn(v0, v1);
            __half2 lv = __floats2half2_rn(
                v0 - __half2float(hv.x), v1 - __half2float(hv.y));
            size_t i1 = (size_t)(b * SEQ + r1) * DIM + col;
            *(__half2*)&g_aoh[i1] = hv;
            *(__half2*)&g_aol[i1] = lv;
        }
    }
}

// ---------------- launcher ---------------------------------------------------
extern "C" void kernel_launch(void* const* d_in, const int* in_sizes, int n_in,
                              void* d_out, int out_size)
{
    const float* x     = (const float*)d_in[0];   // [2,2048,2048]
    const float* fc    = (const float*)d_in[1];   // [2048,32,2]
    // d_in[2] = mask (causal, hardcoded)
    const float* wqkv  = (const float*)d_in[3];   // [3072,2048]
    const float* wo    = (const float*)d_in[4];   // [2048,2048]
    float* out = (float*)d_out;                   // [2,2048,2048]

    void *p_qkv;
    void *p_xh, *p_xl, *p_wq, *p_aoh, *p_aol, *p_wo;
    cudaGetSymbolAddress(&p_qkv, g_qkv);
    cudaGetSymbolAddress(&p_xh,  g_xh);  cudaGetSymbolAddress(&p_xl,  g_xl);
    cudaGetSymbolAddress(&p_wq,  g_wq);
    cudaGetSymbolAddress(&p_aoh, g_aoh); cudaGetSymbolAddress(&p_aol, g_aol);
    cudaGetSymbolAddress(&p_wo,  g_wo);

    cudaFuncSetAttribute(gemm_hmma_kernel,
                         cudaFuncAttributeMaxDynamicSharedMemorySize, GT_SMEM_BYTES);

    const int M = BSZ * SEQ;                      // 4096

    split4h_kernel<<<(M * DIM / 4 + 255) / 256, 256>>>(x,
        (__half*)p_xh, (__half*)p_xl, M * DIM / 4);
    conv4h_kernel<<<(QKV_N * DIM / 4 + 255) / 256, 256>>>(wqkv,
        (__half*)p_wq, QKV_N * DIM / 4);
    conv4h_kernel<<<(DIM * DIM / 4 + 255) / 256, 256>>>(wo,
        (__half*)p_wo, DIM * DIM / 4);

    // 1) QKV projection
    gemm_hmma_kernel<<<dim3(QKV_N / 128, M / 128), 256, GT_SMEM_BYTES>>>(
        (const __half*)p_xh, (const __half*)p_xl, (const __half*)p_wq,
        (float*)p_qkv, M, QKV_N, DIM);

    // 2) RoPE + V convert/transpose
    rope_q_kernel<<<(BSZ * SEQ * NH  * 32) / 256, 256>>>(fc);
    rope_k_kernel<<<(BSZ * SEQ * NKV * 32) / 256, 256>>>(fc);
    split_v_kernel<<<dim3(SEQ / 32, HD / 32, BSZ * NKV), 256>>>();

    // 3) causal flash attention -> g_aoh/g_aol [b,s,h*d] (fp16 hi/lo)
    flash_hmma_kernel<<<dim3(SEQ / 128, NH, BSZ), 256>>>();

    // 4) output projection
    gemm_hmma_kernel<<<dim3(DIM / 128, M / 128), 256, GT_SMEM_BYTES>>>(
        (const __half*)p_aoh, (const __half*)p_aol, (const __half*)p_wo,
        out, M, DIM, DIM);
}

// round 8
// speedup vs baseline: 3.7022x; 1.0376x over previous
#include <cuda_runtime.h>
#include <cuda_fp16.h>
#include <cstdint>
#include <cstddef>

#define BSZ 2
#define SEQ 2048
#define DIM 2048
#define NH 32
#define NKV 8
#define HD 64
#define QKV_N ((NH + 2*NKV)*HD)   // 3072

// ---------------- scratch (static device globals; no allocation) -----------
__device__ float g_qkv[(size_t)BSZ*SEQ*QKV_N];     // [4096, 3072]

// fp16 operands: activations split hi/lo, weights single
__device__ __half g_xh [(size_t)BSZ*SEQ*DIM];
__device__ __half g_xl [(size_t)BSZ*SEQ*DIM];
__device__ __half g_wq [(size_t)QKV_N*DIM];
__device__ __half g_aoh[(size_t)BSZ*SEQ*DIM];
__device__ __half g_aol[(size_t)BSZ*SEQ*DIM];
__device__ __half g_wo [(size_t)DIM*DIM];

// fp16 Q (split, pre-scaled), K/V single
__device__ __half g_qh[(size_t)BSZ*NH *SEQ*HD];    // [b,h,s,d]
__device__ __half g_ql[(size_t)BSZ*NH *SEQ*HD];
__device__ __half g_k [(size_t)BSZ*NKV*SEQ*HD];    // [b,kv,s,d]
__device__ __half g_v [(size_t)BSZ*NKV*HD*SEQ];    // [b,kv,d,s] transposed

// ---------------- small PTX helpers (sm_80-baseline ISA only) ---------------
__device__ __forceinline__ uint32_t smem_to_u32(const void* p) {
    uint32_t a;
    asm("{ .reg .u64 t; cvta.to.shared.u64 t, %1; cvt.u32.u64 %0, t; }"
        : "=r"(a) : "l"(p));
    return a;
}
__device__ __forceinline__ void cp_async16(uint32_t dst, const void* src) {
    asm volatile("cp.async.cg.shared.global [%0], [%1], 16;"
                 :: "r"(dst), "l"(src) : "memory");
}
#define CP_COMMIT() asm volatile("cp.async.commit_group;" ::: "memory")
#define CP_WAIT2()  asm volatile("cp.async.wait_group 2;" ::: "memory")
#define CP_WAIT1()  asm volatile("cp.async.wait_group 1;" ::: "memory")
#define CP_WAIT0()  asm volatile("cp.async.wait_group 0;" ::: "memory")

__device__ __forceinline__ void ldsm4(uint32_t* r, uint32_t addr) {
    asm volatile("ldmatrix.sync.aligned.m8n8.x4.shared.b16 {%0,%1,%2,%3}, [%4];"
        : "=r"(r[0]), "=r"(r[1]), "=r"(r[2]), "=r"(r[3]) : "r"(addr));
}

// D += A(16x16 fp16) * B(16x8 fp16), fp32 accum
__device__ __forceinline__ void mma16816(float* d, const uint32_t* a,
                                         const uint32_t* b) {
    asm volatile(
        "mma.sync.aligned.m16n8k16.row.col.f32.f16.f16.f32 "
        "{%0,%1,%2,%3}, {%4,%5,%6,%7}, {%8,%9}, {%0,%1,%2,%3};"
        : "+f"(d[0]), "+f"(d[1]), "+f"(d[2]), "+f"(d[3])
        : "r"(a[0]), "r"(a[1]), "r"(a[2]), "r"(a[3]), "r"(b[0]), "r"(b[1]));
}

// ---------------- conversion kernels ----------------------------------------
__global__ void split4h_kernel(const float* __restrict__ src,
                               __half* __restrict__ hi,
                               __half* __restrict__ lo, int n4)
{
    int i = blockIdx.x * 256 + threadIdx.x;
    if (i >= n4) return;
    float4 v = ((const float4*)src)[i];
    __half h0 = __float2half_rn(v.x), h1 = __float2half_rn(v.y);
    __half h2 = __float2half_rn(v.z), h3 = __float2half_rn(v.w);
    __half l0 = __float2half_rn(v.x - __half2float(h0));
    __half l1 = __float2half_rn(v.y - __half2float(h1));
    __half l2 = __float2half_rn(v.z - __half2float(h2));
    __half l3 = __float2half_rn(v.w - __half2float(h3));
    ((__half2*)hi)[2*i]   = __half2(h0, h1);
    ((__half2*)hi)[2*i+1] = __half2(h2, h3);
    ((__half2*)lo)[2*i]   = __half2(l0, l1);
    ((__half2*)lo)[2*i+1] = __half2(l2, l3);
}

__global__ void conv4h_kernel(const float* __restrict__ src,
                              __half* __restrict__ dst, int n4)
{
    int i = blockIdx.x * 256 + threadIdx.x;
    if (i >= n4) return;
    float4 v = ((const float4*)src)[i];
    ((__half2*)dst)[2*i]   = __floats2half2_rn(v.x, v.y);
    ((__half2*)dst)[2*i+1] = __floats2half2_rn(v.z, v.w);
}

// ---------------- HMMA GEMM: C[M,N] = (Ah+Al)[M,K] * B[N,K]^T ---------------
// 3-stage cp.async pipeline, 128x128x32 tiles, 8 warps.
#define GSTR 40
#define TILE_ELEMS (128 * GSTR)
#define TILE_BYTES (TILE_ELEMS * 2)
#define GT_SMEM_BYTES (3 * 3 * TILE_BYTES)      // 92160

__global__ __launch_bounds__(256, 2)
void gemm_hmma_kernel(const __half* __restrict__ Ah,
                      const __half* __restrict__ Al,
                      const __half* __restrict__ B,
                      float* __restrict__ C, int M, int N, int K)
{
    extern __shared__ __half sm[];
    const uint32_t sbase = smem_to_u32(sm);
    const int t    = threadIdx.x;
    const int wid  = t >> 5, lane = t & 31;
    const int bm   = blockIdx.y * 128, bn = blockIdx.x * 128;
    const int wm   = (wid & 1) * 64;
    const int wn   = (wid >> 1) * 32;
    const int lr   = lane >> 2;
    const int lc   = lane & 3;

    // ldmatrix lane offsets
    const int arow = (lane & 7) + ((lane >> 3) & 1) * 8;
    const int acol = (lane >> 4) * 8;
    const uint32_t aoff = (uint32_t)(arow * GSTR + acol) * 2;
    const int brow = (lane & 7) + ((lane >> 4) & 1) * 8;
    const int bcol = ((lane >> 3) & 1) * 8;
    const uint32_t boff = (uint32_t)(brow * GSTR + bcol) * 2;

    const int r0 = t >> 2,  c0 = t & 3;
    const int r1 = (t + 256) >> 2, c1 = t & 3;

    float acc[4][4][4];
#pragma unroll
    for (int mi = 0; mi < 4; ++mi)
#pragma unroll
        for (int ni = 0; ni < 4; ++ni)
#pragma unroll
            for (int q = 0; q < 4; ++q) acc[mi][ni][q] = 0.f;

    const int nch = K / 32;

    auto load_chunk = [&](int buf, int kc) {
        const __half* g[3];
        g[0] = Ah + (size_t)bm * K + kc * 32;
        g[1] = Al + (size_t)bm * K + kc * 32;
        g[2] = B  + (size_t)bn * K + kc * 32;
#pragma unroll
        for (int tile = 0; tile < 3; ++tile) {
            uint32_t sd = sbase + (buf * 3 + tile) * TILE_BYTES;
            cp_async16(sd + r0 * (GSTR*2) + c0 * 16, g[tile] + (size_t)r0 * K + c0 * 8);
            cp_async16(sd + r1 * (GSTR*2) + c1 * 16, g[tile] + (size_t)r1 * K + c1 * 8);
        }
    };

    load_chunk(0, 0); CP_COMMIT();
    load_chunk(1, 1); CP_COMMIT();

    int buf = 0;
    for (int c = 0; c < nch; ++c) {
        if (c + 2 < nch) { load_chunk((c + 2) % 3, c + 2); CP_COMMIT(); }
        if (c + 2 < nch)      CP_WAIT2();
        else if (c + 1 < nch) CP_WAIT1();
        else                  CP_WAIT0();
        __syncthreads();

        const uint32_t uAh = sbase + (buf * 3 + 0) * TILE_BYTES;
        const uint32_t uAl = sbase + (buf * 3 + 1) * TILE_BYTES;
        const uint32_t uB  = sbase + (buf * 3 + 2) * TILE_BYTES;

#pragma unroll
        for (int ks = 0; ks < 2; ++ks) {
            uint32_t ah[4][4], al[4][4], b4[2][4];
#pragma unroll
            for (int mi = 0; mi < 4; ++mi) {
                const uint32_t ra = (uint32_t)((wm + mi * 16) * GSTR) * 2 + ks * 32;
                ldsm4(ah[mi], uAh + ra + aoff);
                ldsm4(al[mi], uAl + ra + aoff);
            }
#pragma unroll
            for (int p = 0; p < 2; ++p) {
                const uint32_t rb = (uint32_t)((wn + p * 16) * GSTR) * 2 + ks * 32;
                ldsm4(b4[p], uB + rb + boff);
            }
#pragma unroll
            for (int mi = 0; mi < 4; ++mi)
#pragma unroll
                for (int ni = 0; ni < 4; ++ni)
                    mma16816(acc[mi][ni], ah[mi], &b4[ni >> 1][(ni & 1) * 2]);
#pragma unroll
            for (int mi = 0; mi < 4; ++mi)
#pragma unroll
                for (int ni = 0; ni < 4; ++ni)
                    mma16816(acc[mi][ni], al[mi], &b4[ni >> 1][(ni & 1) * 2]);
        }
        __syncthreads();
        buf = (buf == 2) ? 0 : buf + 1;
    }

#pragma unroll
    for (int mi = 0; mi < 4; ++mi) {
        const int row = bm + wm + mi * 16 + lr;
#pragma unroll
        for (int ni = 0; ni < 4; ++ni) {
            const int col = bn + wn + ni * 8 + lc * 2;
            *(float2*)&C[(size_t)row * N + col] =
                make_float2(acc[mi][ni][0], acc[mi][ni][1]);
            *(float2*)&C[(size_t)(row + 8) * N + col] =
                make_float2(acc[mi][ni][2], acc[mi][ni][3]);
        }
    }
}

// ---------------- RoPE -> fp16 -----------------------------------------------
__global__ void rope_q_kernel(const float* __restrict__ fc)
{
    int gid = blockIdx.x * 256 + threadIdx.x;
    int p = gid & 31;
    int h = (gid >> 5) & 31;
    int s = (gid >> 10) & 2047;
    int b = gid >> 21;
    const float* src = g_qkv + (size_t)(b * SEQ + s) * QKV_N + h * HD + 2 * p;
    float x0 = src[0], x1 = src[1];
    float c  = fc[s * HD + 2 * p];
    float sn = fc[s * HD + 2 * p + 1];
    float v0 = (x0 * c - x1 * sn) * 0.125f;
    float v1 = (x1 * c + x0 * sn) * 0.125f;
    size_t off = (((size_t)(b * NH + h)) * SEQ + s) * HD + 2 * p;
    __half h0 = __float2half_rn(v0), h1 = __float2half_rn(v1);
    *(__half2*)(g_qh + off) = __half2(h0, h1);
    *(__half2*)(g_ql + off) = __half2(
        __float2half_rn(v0 - __half2float(h0)),
        __float2half_rn(v1 - __half2float(h1)));
}

__global__ void rope_k_kernel(const float* __restrict__ fc)
{
    int gid = blockIdx.x * 256 + threadIdx.x;
    int p  = gid & 31;
    int kv = (gid >> 5) & 7;
    int s  = (gid >> 8) & 2047;
    int b  = gid >> 19;
    const float* src = g_qkv + (size_t)(b * SEQ + s) * QKV_N + DIM + kv * HD + 2 * p;
    float x0 = src[0], x1 = src[1];
    float c  = fc[s * HD + 2 * p];
    float sn = fc[s * HD + 2 * p + 1];
    size_t off = (((size_t)(b * NKV + kv)) * SEQ + s) * HD + 2 * p;
    *(__half2*)(g_k + off) =
        __floats2half2_rn(x0 * c - x1 * sn, x1 * c + x0 * sn);
}

// V: convert + transpose [s,d] -> [d,s] per (b,kv)
__global__ void split_v_kernel()
{
    __shared__ float tile[32][33];
    const int bk = blockIdx.z;                 // b*NKV + kv
    const int b  = bk >> 3, kv = bk & 7;
    const int s0 = blockIdx.x * 32;
    const int d0 = blockIdx.y * 32;
    const int tx = threadIdx.x & 31, ty = threadIdx.x >> 5;   // 32x8

    const float* src = g_qkv + (size_t)(b * SEQ + s0) * QKV_N
                       + DIM + NKV * HD + kv * HD + d0;
#pragma unroll
    for (int i = 0; i < 4; ++i)
        tile[ty + i * 8][tx] = src[(size_t)(ty + i * 8) * QKV_N + tx];
    __syncthreads();

    const size_t obase = ((size_t)bk * HD + d0) * SEQ + s0;
#pragma unroll
    for (int i = 0; i < 4; ++i) {
        int d = ty + i * 8;
        g_v[obase + (size_t)d * SEQ + tx] = __float2half_rn(tile[tx][d]);
    }
}

// ---------------- flash attention on HMMA ------------------------------------
// Block: 128 q rows (8 warps x 16), KV tile 64. Q/P split fp16, K/V single.
// Double-buffered K/V tiles via cp.async (1-tile lookahead).
#define FSTR 72
#define FTILE_BYTES (64 * FSTR * 2)   // 9216

__global__ __launch_bounds__(256)
void flash_hmma_kernel()
{
    __shared__ __half sK[2][64 * FSTR];
    __shared__ __half sV[2][64 * FSTR];   // [d][key]

    const int t = threadIdx.x;
    const int w = t >> 5, lane = t & 31;
    const int g = lane >> 2, tg = lane & 3;
    const int qb = blockIdx.x, h = blockIdx.y, b = blockIdx.z;
    const int kvh = h >> 2;
    const int qrow0 = qb * 128 + w * 16;

    const uint32_t uK0 = smem_to_u32(sK);
    const uint32_t uV0 = smem_to_u32(sV);

    const int brow = (lane & 7) + ((lane >> 4) & 1) * 8;
    const int bcol = ((lane >> 3) & 1) * 8;
    const uint32_t boff = (uint32_t)(brow * FSTR + bcol) * 2;

    // Q fragments (hi/lo), 4 k-chunks of 16 over d=64
    uint32_t qfh[4][4], qfl[4][4];
    {
        const __half* gq = g_qh + (((size_t)(b*NH+h))*SEQ + qrow0)*HD;
        const __half* gl = g_ql + (((size_t)(b*NH+h))*SEQ + qrow0)*HD;
#pragma unroll
        for (int kk = 0; kk < 4; ++kk) {
            int d0 = kk * 16 + tg * 2;
            qfh[kk][0] = *(const uint32_t*)&gq[(size_t)(g    ) * HD + d0];
            qfh[kk][1] = *(const uint32_t*)&gq[(size_t)(g + 8) * HD + d0];
            qfh[kk][2] = *(const uint32_t*)&gq[(size_t)(g    ) * HD + d0 + 8];
            qfh[kk][3] = *(const uint32_t*)&gq[(size_t)(g + 8) * HD + d0 + 8];
            qfl[kk][0] = *(const uint32_t*)&gl[(size_t)(g    ) * HD + d0];
            qfl[kk][1] = *(const uint32_t*)&gl[(size_t)(g + 8) * HD + d0];
            qfl[kk][2] = *(const uint32_t*)&gl[(size_t)(g    ) * HD + d0 + 8];
            qfl[kk][3] = *(const uint32_t*)&gl[(size_t)(g + 8) * HD + d0 + 8];
        }
    }

    float m0 = -1e30f, m1 = -1e30f, l0 = 0.f, l1 = 0.f;
    float o[8][4];
#pragma unroll
    for (int ni = 0; ni < 8; ++ni)
#pragma unroll
        for (int q = 0; q < 4; ++q) o[ni][q] = 0.f;

    const __half* gk = g_k + ((size_t)(b * NKV + kvh)) * SEQ * HD;
    const __half* gv = g_v + ((size_t)(b * NKV + kvh)) * HD * SEQ;

    auto load_tile = [&](int buf, int jb) {
#pragma unroll
        for (int cc = 0; cc < 2; ++cc) {
            int c   = t + cc * 256;
            int row = c >> 3, col = (c & 7) * 8;
            uint32_t so = (uint32_t)buf * FTILE_BYTES + (uint32_t)(row * FSTR + col) * 2;
            cp_async16(uK0 + so, &gk[(size_t)(jb * 64 + row) * HD + col]);
            cp_async16(uV0 + so, &gv[(size_t)row * SEQ + jb * 64 + col]);
        }
    };

    const int ntile = 2 * qb + 2;
    load_tile(0, 0); CP_COMMIT();

    for (int jb = 0; jb < ntile; ++jb) {
        const int buf = jb & 1;
        if (jb + 1 < ntile) { load_tile(buf ^ 1, jb + 1); CP_COMMIT(); CP_WAIT1(); }
        else                 CP_WAIT0();
        __syncthreads();

        if (jb * 64 <= qrow0 + 15) {
            const uint32_t uK = uK0 + buf * FTILE_BYTES;
            const uint32_t uV = uV0 + buf * FTILE_BYTES;

            // S = Q K^T
            float s[8][4];
#pragma unroll
            for (int ni = 0; ni < 8; ++ni)
                s[ni][0] = s[ni][1] = s[ni][2] = s[ni][3] = 0.f;

#pragma unroll
            for (int kk = 0; kk < 4; ++kk)
#pragma unroll
                for (int p = 0; p < 4; ++p) {
                    const uint32_t rb = (uint32_t)(p * 16 * FSTR) * 2 + kk * 32;
                    uint32_t k4[4];
                    ldsm4(k4, uK + rb + boff);
                    mma16816(s[2*p],   qfh[kk], k4 + 0);
                    mma16816(s[2*p+1], qfh[kk], k4 + 2);
                    mma16816(s[2*p],   qfl[kk], k4 + 0);
                    mma16816(s[2*p+1], qfl[kk], k4 + 2);
                }

            // causal mask (diagonal tiles only)
            if (jb * 64 + 63 > qrow0) {
                const int cb = jb * 64 + tg * 2;
                const int r0 = qrow0 + g, r1 = r0 + 8;
#pragma unroll
                for (int ni = 0; ni < 8; ++ni) {
                    int c0 = cb + ni * 8, c1 = c0 + 1;
                    if (c0 > r0) s[ni][0] = -1e30f;
                    if (c1 > r0) s[ni][1] = -1e30f;
                    if (c0 > r1) s[ni][2] = -1e30f;
                    if (c1 > r1) s[ni][3] = -1e30f;
                }
            }

            // online softmax
            float mt0 = -1e30f, mt1 = -1e30f;
#pragma unroll
            for (int ni = 0; ni < 8; ++ni) {
                mt0 = fmaxf(mt0, fmaxf(s[ni][0], s[ni][1]));
                mt1 = fmaxf(mt1, fmaxf(s[ni][2], s[ni][3]));
            }
            mt0 = fmaxf(mt0, __shfl_xor_sync(0xffffffffu, mt0, 1));
            mt0 = fmaxf(mt0, __shfl_xor_sync(0xffffffffu, mt0, 2));
            mt1 = fmaxf(mt1, __shfl_xor_sync(0xffffffffu, mt1, 1));
            mt1 = fmaxf(mt1, __shfl_xor_sync(0xffffffffu, mt1, 2));
            float mn0 = fmaxf(m0, mt0), mn1 = fmaxf(m1, mt1);
            float a0 = __expf(m0 - mn0), a1 = __expf(m1 - mn1);
            m0 = mn0; m1 = mn1;
            float rs0 = 0.f, rs1 = 0.f;
#pragma unroll
            for (int ni = 0; ni < 8; ++ni) {
                s[ni][0] = __expf(s[ni][0] - mn0);
                s[ni][1] = __expf(s[ni][1] - mn0);
                s[ni][2] = __expf(s[ni][2] - mn1);
                s[ni][3] = __expf(s[ni][3] - mn1);
                rs0 += s[ni][0] + s[ni][1];
                rs1 += s[ni][2] + s[ni][3];
            }
            l0 = l0 * a0 + rs0;
            l1 = l1 * a1 + rs1;
#pragma unroll
            for (int ni = 0; ni < 8; ++ni) {
                o[ni][0] *= a0; o[ni][1] *= a0;
                o[ni][2] *= a1; o[ni][3] *= a1;
            }

            // O += P V. P split hi/lo fp16, V single.
#pragma unroll
            for (int kk = 0; kk < 4; ++kk) {
                uint32_t ph[4], pl[4];
#pragma unroll
                for (int half = 0; half < 2; ++half) {
                    const int ni = 2 * kk + half;
                    __half2 h0 = __floats2half2_rn(s[ni][0], s[ni][1]);
                    __half2 l0v = __floats2half2_rn(
                        s[ni][0] - __half2float(h0.x),
                        s[ni][1] - __half2float(h0.y));
                    __half2 h1 = __floats2half2_rn(s[ni][2], s[ni][3]);
                    __half2 l1v = __floats2half2_rn(
                        s[ni][2] - __half2float(h1.x),
                        s[ni][3] - __half2float(h1.y));
                    ph[half * 2 + 0] = *(uint32_t*)&h0;
                    ph[half * 2 + 1] = *(uint32_t*)&h1;
                    pl[half * 2 + 0] = *(uint32_t*)&l0v;
                    pl[half * 2 + 1] = *(uint32_t*)&l1v;
                }
#pragma unroll
                for (int p = 0; p < 4; ++p) {
                    const uint32_t rb = (uint32_t)(p * 16 * FSTR) * 2 + kk * 32;
                    uint32_t v4[4];
                    ldsm4(v4, uV + rb + boff);
                    mma16816(o[2*p],   ph, v4 + 0);
                    mma16816(o[2*p+1], ph, v4 + 2);
                    mma16816(o[2*p],   pl, v4 + 0);
                    mma16816(o[2*p+1], pl, v4 + 2);
                }
            }
        }
        __syncthreads();
    }

    // finalize: write fp16 hi/lo splits directly (feeds out-projection)
    l0 += __shfl_xor_sync(0xffffffffu, l0, 1);
    l0 += __shfl_xor_sync(0xffffffffu, l0, 2);
    l1 += __shfl_xor_sync(0xffffffffu, l1, 1);
    l1 += __shfl_xor_sync(0xffffffffu, l1, 2);
    const float inv0 = 1.f / l0, inv1 = 1.f / l1;

    const int r0 = qrow0 + g, r1 = r0 + 8;
#pragma unroll
    for (int ni = 0; ni < 8; ++ni) {
        const int col = h * HD + ni * 8 + tg * 2;
        {
            float v0 = o[ni][0] * inv0, v1 = o[ni][1] * inv0;
            __half2 hv = __floats2half2_rn(v0, v1);
            __half2 lv = __floats2half2_rn(
                v0 - __half2float(hv.x), v1 - __half2float(hv.y));
            size_t i0 = (size_t)(b * SEQ + r0) * DIM + col;
            *(__half2*)&g_aoh[i0] = hv;
            *(__half2*)&g_aol[i0] = lv;
        }
        {
            float v0 = o[ni][2] * inv1, v1 = o[ni][3] * inv1;
            __half2 hv = __floats2half2_rn(v0, v1);
            __half2 lv = __floats2half2_rn(
                v0 - __half2float(hv.x), v1 - __half2float(hv.y));
            size_t i1 = (size_t)(b * SEQ + r1) * DIM + col;
            *(__half2*)&g_aoh[i1] = hv;
            *(__half2*)&g_aol[i1] = lv;
        }
    }
}

// ---------------- launcher ---------------------------------------------------
extern "C" void kernel_launch(void* const* d_in, const int* in_sizes, int n_in,
                              void* d_out, int out_size)
{
    const float* x     = (const float*)d_in[0];   // [2,2048,2048]
    const float* fc    = (const float*)d_in[1];   // [2048,32,2]
    // d_in[2] = mask (causal, hardcoded)
    const float* wqkv  = (const float*)d_in[3];   // [3072,2048]
    const float* wo    = (const float*)d_in[4];   // [2048,2048]
    float* out = (float*)d_out;                   // [2,2048,2048]

    void *p_qkv;
    void *p_xh, *p_xl, *p_wq, *p_aoh, *p_aol, *p_wo;
    cudaGetSymbolAddress(&p_qkv, g_qkv);
    cudaGetSymbolAddress(&p_xh,  g_xh);  cudaGetSymbolAddress(&p_xl,  g_xl);
    cudaGetSymbolAddress(&p_wq,  g_wq);
    cudaGetSymbolAddress(&p_aoh, g_aoh); cudaGetSymbolAddress(&p_aol, g_aol);
    cudaGetSymbolAddress(&p_wo,  g_wo);

    cudaFuncSetAttribute(gemm_hmma_kernel,
                         cudaFuncAttributeMaxDynamicSharedMemorySize, GT_SMEM_BYTES);

    const int M = BSZ * SEQ;                      // 4096

    split4h_kernel<<<(M * DIM / 4 + 255) / 256, 256>>>(x,
        (__half*)p_xh, (__half*)p_xl, M * DIM / 4);
    conv4h_kernel<<<(QKV_N * DIM / 4 + 255) / 256, 256>>>(wqkv,
        (__half*)p_wq, QKV_N * DIM / 4);
    conv4h_kernel<<<(DIM * DIM / 4 + 255) / 256, 256>>>(wo,
        (__half*)p_wo, DIM * DIM / 4);

    // 1) QKV projection
    gemm_hmma_kernel<<<dim3(QKV_N / 128, M / 128), 256, GT_SMEM_BYTES>>>(
        (const __half*)p_xh, (const __half*)p_xl, (const __half*)p_wq,
        (float*)p_qkv, M, QKV_N, DIM);

    // 2) RoPE + V convert/transpose
    rope_q_kernel<<<(BSZ * SEQ * NH  * 32) / 256, 256>>>(fc);
    rope_k_kernel<<<(BSZ * SEQ * NKV * 32) / 256, 256>>>(fc);
    split_v_kernel<<<dim3(SEQ / 32, HD / 32, BSZ * NKV), 256>>>();

    // 3) causal flash attention -> g_aoh/g_aol [b,s,h*d] (fp16 hi/lo)
    flash_hmma_kernel<<<dim3(SEQ / 128, NH, BSZ), 256>>>();

    // 4) output projection
    gemm_hmma_kernel<<<dim3(DIM / 128, M / 128), 256, GT_SMEM_BYTES>>>(
        (const __half*)p_aoh, (const __half*)p_aol, (const __half*)p_wo,
        out, M, DIM, DIM);
}

// round 9
// speedup vs baseline: 3.8300x; 1.0345x over previous
#include <cuda_runtime.h>
#include <cuda_fp16.h>
#include <cstdint>
#include <cstddef>

#define BSZ 2
#define SEQ 2048
#define DIM 2048
#define NH 32
#define NKV 8
#define HD 64
#define QKV_N ((NH + 2*NKV)*HD)   // 3072

// ---------------- scratch (static device globals; no allocation) -----------
__device__ float g_qkv[(size_t)BSZ*SEQ*QKV_N];     // [4096, 3072]

// fp16 operands: activations split hi/lo, weights single
__device__ __half g_xh [(size_t)BSZ*SEQ*DIM];
__device__ __half g_xl [(size_t)BSZ*SEQ*DIM];
__device__ __half g_wq [(size_t)QKV_N*DIM];
__device__ __half g_aoh[(size_t)BSZ*SEQ*DIM];
__device__ __half g_aol[(size_t)BSZ*SEQ*DIM];
__device__ __half g_wo [(size_t)DIM*DIM];

// fp16 Q (split, pre-scaled), K/V single
__device__ __half g_qh[(size_t)BSZ*NH *SEQ*HD];    // [b,h,s,d]
__device__ __half g_ql[(size_t)BSZ*NH *SEQ*HD];
__device__ __half g_k [(size_t)BSZ*NKV*SEQ*HD];    // [b,kv,s,d]
__device__ __half g_v [(size_t)BSZ*NKV*HD*SEQ];    // [b,kv,d,s] transposed

// ---------------- small PTX helpers (sm_80-baseline ISA only) ---------------
__device__ __forceinline__ uint32_t smem_to_u32(const void* p) {
    uint32_t a;
    asm("{ .reg .u64 t; cvta.to.shared.u64 t, %1; cvt.u32.u64 %0, t; }"
        : "=r"(a) : "l"(p));
    return a;
}
__device__ __forceinline__ void cp_async16(uint32_t dst, const void* src) {
    asm volatile("cp.async.cg.shared.global [%0], [%1], 16;"
                 :: "r"(dst), "l"(src) : "memory");
}
#define CP_COMMIT() asm volatile("cp.async.commit_group;" ::: "memory")
#define CP_WAIT1()  asm volatile("cp.async.wait_group 1;" ::: "memory")
#define CP_WAIT0()  asm volatile("cp.async.wait_group 0;" ::: "memory")

__device__ __forceinline__ void ldsm4(uint32_t* r, uint32_t addr) {
    asm volatile("ldmatrix.sync.aligned.m8n8.x4.shared.b16 {%0,%1,%2,%3}, [%4];"
        : "=r"(r[0]), "=r"(r[1]), "=r"(r[2]), "=r"(r[3]) : "r"(addr));
}

// D += A(16x16 fp16) * B(16x8 fp16), fp32 accum
__device__ __forceinline__ void mma16816(float* d, const uint32_t* a,
                                         const uint32_t* b) {
    asm volatile(
        "mma.sync.aligned.m16n8k16.row.col.f32.f16.f16.f32 "
        "{%0,%1,%2,%3}, {%4,%5,%6,%7}, {%8,%9}, {%0,%1,%2,%3};"
        : "+f"(d[0]), "+f"(d[1]), "+f"(d[2]), "+f"(d[3])
        : "r"(a[0]), "r"(a[1]), "r"(a[2]), "r"(a[3]), "r"(b[0]), "r"(b[1]));
}

// ---------------- conversion kernels ----------------------------------------
__global__ void split4h_kernel(const float* __restrict__ src,
                               __half* __restrict__ hi,
                               __half* __restrict__ lo, int n4)
{
    int i = blockIdx.x * 256 + threadIdx.x;
    if (i >= n4) return;
    float4 v = ((const float4*)src)[i];
    __half h0 = __float2half_rn(v.x), h1 = __float2half_rn(v.y);
    __half h2 = __float2half_rn(v.z), h3 = __float2half_rn(v.w);
    __half l0 = __float2half_rn(v.x - __half2float(h0));
    __half l1 = __float2half_rn(v.y - __half2float(h1));
    __half l2 = __float2half_rn(v.z - __half2float(h2));
    __half l3 = __float2half_rn(v.w - __half2float(h3));
    ((__half2*)hi)[2*i]   = __half2(h0, h1);
    ((__half2*)hi)[2*i+1] = __half2(h2, h3);
    ((__half2*)lo)[2*i]   = __half2(l0, l1);
    ((__half2*)lo)[2*i+1] = __half2(l2, l3);
}

__global__ void conv4h_kernel(const float* __restrict__ src,
                              __half* __restrict__ dst, int n4)
{
    int i = blockIdx.x * 256 + threadIdx.x;
    if (i >= n4) return;
    float4 v = ((const float4*)src)[i];
    ((__half2*)dst)[2*i]   = __floats2half2_rn(v.x, v.y);
    ((__half2*)dst)[2*i+1] = __floats2half2_rn(v.z, v.w);
}

// ---------------- HMMA GEMM: C[M,N] = (Ah+Al)[M,K] * B[N,K]^T ---------------
// 3-stage cp.async pipeline, 128x128x32 tiles, 8 warps, ONE barrier per chunk.
#define GSTR 40
#define TILE_ELEMS (128 * GSTR)
#define TILE_BYTES (TILE_ELEMS * 2)
#define GT_SMEM_BYTES (3 * 3 * TILE_BYTES)      // 92160

__global__ __launch_bounds__(256, 2)
void gemm_hmma_kernel(const __half* __restrict__ Ah,
                      const __half* __restrict__ Al,
                      const __half* __restrict__ B,
                      float* __restrict__ C, int M, int N, int K)
{
    extern __shared__ __half sm[];
    const uint32_t sbase = smem_to_u32(sm);
    const int t    = threadIdx.x;
    const int wid  = t >> 5, lane = t & 31;
    const int bm   = blockIdx.y * 128, bn = blockIdx.x * 128;
    const int wm   = (wid & 1) * 64;
    const int wn   = (wid >> 1) * 32;
    const int lr   = lane >> 2;
    const int lc   = lane & 3;

    // ldmatrix lane offsets
    const int arow = (lane & 7) + ((lane >> 3) & 1) * 8;
    const int acol = (lane >> 4) * 8;
    const uint32_t aoff = (uint32_t)(arow * GSTR + acol) * 2;
    const int brow = (lane & 7) + ((lane >> 4) & 1) * 8;
    const int bcol = ((lane >> 3) & 1) * 8;
    const uint32_t boff = (uint32_t)(brow * GSTR + bcol) * 2;

    const int r0 = t >> 2,  c0 = t & 3;
    const int r1 = (t + 256) >> 2, c1 = t & 3;

    float acc[4][4][4];
#pragma unroll
    for (int mi = 0; mi < 4; ++mi)
#pragma unroll
        for (int ni = 0; ni < 4; ++ni)
#pragma unroll
            for (int q = 0; q < 4; ++q) acc[mi][ni][q] = 0.f;

    const int nch = K / 32;

    auto load_chunk = [&](int buf, int kc) {
        const __half* g[3];
        g[0] = Ah + (size_t)bm * K + kc * 32;
        g[1] = Al + (size_t)bm * K + kc * 32;
        g[2] = B  + (size_t)bn * K + kc * 32;
#pragma unroll
        for (int tile = 0; tile < 3; ++tile) {
            uint32_t sd = sbase + (buf * 3 + tile) * TILE_BYTES;
            cp_async16(sd + r0 * (GSTR*2) + c0 * 16, g[tile] + (size_t)r0 * K + c0 * 8);
            cp_async16(sd + r1 * (GSTR*2) + c1 * 16, g[tile] + (size_t)r1 * K + c1 * 8);
        }
    };

    load_chunk(0, 0); CP_COMMIT();
    load_chunk(1, 1); CP_COMMIT();

    int buf = 0;
    for (int c = 0; c < nch; ++c) {
        if (c + 1 < nch) CP_WAIT1();
        else             CP_WAIT0();
        __syncthreads();
        // Safe to overwrite buffer (c+2)%3 == (c-1)%3 now: its readers
        // (compute of chunk c-1) finished before this barrier in program order.
        if (c + 2 < nch) { load_chunk((c + 2) % 3, c + 2); CP_COMMIT(); }

        const uint32_t uAh = sbase + (buf * 3 + 0) * TILE_BYTES;
        const uint32_t uAl = sbase + (buf * 3 + 1) * TILE_BYTES;
        const uint32_t uB  = sbase + (buf * 3 + 2) * TILE_BYTES;

#pragma unroll
        for (int ks = 0; ks < 2; ++ks) {
            uint32_t ah[4][4], al[4][4], b4[2][4];
#pragma unroll
            for (int mi = 0; mi < 4; ++mi) {
                const uint32_t ra = (uint32_t)((wm + mi * 16) * GSTR) * 2 + ks * 32;
                ldsm4(ah[mi], uAh + ra + aoff);
                ldsm4(al[mi], uAl + ra + aoff);
            }
#pragma unroll
            for (int p = 0; p < 2; ++p) {
                const uint32_t rb = (uint32_t)((wn + p * 16) * GSTR) * 2 + ks * 32;
                ldsm4(b4[p], uB + rb + boff);
            }
#pragma unroll
            for (int mi = 0; mi < 4; ++mi)
#pragma unroll
                for (int ni = 0; ni < 4; ++ni)
                    mma16816(acc[mi][ni], ah[mi], &b4[ni >> 1][(ni & 1) * 2]);
#pragma unroll
            for (int mi = 0; mi < 4; ++mi)
#pragma unroll
                for (int ni = 0; ni < 4; ++ni)
                    mma16816(acc[mi][ni], al[mi], &b4[ni >> 1][(ni & 1) * 2]);
        }
        buf = (buf == 2) ? 0 : buf + 1;
    }

#pragma unroll
    for (int mi = 0; mi < 4; ++mi) {
        const int row = bm + wm + mi * 16 + lr;
#pragma unroll
        for (int ni = 0; ni < 4; ++ni) {
            const int col = bn + wn + ni * 8 + lc * 2;
            *(float2*)&C[(size_t)row * N + col] =
                make_float2(acc[mi][ni][0], acc[mi][ni][1]);
            *(float2*)&C[(size_t)(row + 8) * N + col] =
                make_float2(acc[mi][ni][2], acc[mi][ni][3]);
        }
    }
}

// ---------------- RoPE -> fp16 -----------------------------------------------
__global__ void rope_q_kernel(const float* __restrict__ fc)
{
    int gid = blockIdx.x * 256 + threadIdx.x;
    int p = gid & 31;
    int h = (gid >> 5) & 31;
    int s = (gid >> 10) & 2047;
    int b = gid >> 21;
    const float* src = g_qkv + (size_t)(b * SEQ + s) * QKV_N + h * HD + 2 * p;
    float x0 = src[0], x1 = src[1];
    float c  = fc[s * HD + 2 * p];
    float sn = fc[s * HD + 2 * p + 1];
    float v0 = (x0 * c - x1 * sn) * 0.125f;
    float v1 = (x1 * c + x0 * sn) * 0.125f;
    size_t off = (((size_t)(b * NH + h)) * SEQ + s) * HD + 2 * p;
    __half h0 = __float2half_rn(v0), h1 = __float2half_rn(v1);
    *(__half2*)(g_qh + off) = __half2(h0, h1);
    *(__half2*)(g_ql + off) = __half2(
        __float2half_rn(v0 - __half2float(h0)),
        __float2half_rn(v1 - __half2float(h1)));
}

__global__ void rope_k_kernel(const float* __restrict__ fc)
{
    int gid = blockIdx.x * 256 + threadIdx.x;
    int p  = gid & 31;
    int kv = (gid >> 5) & 7;
    int s  = (gid >> 8) & 2047;
    int b  = gid >> 19;
    const float* src = g_qkv + (size_t)(b * SEQ + s) * QKV_N + DIM + kv * HD + 2 * p;
    float x0 = src[0], x1 = src[1];
    float c  = fc[s * HD + 2 * p];
    float sn = fc[s * HD + 2 * p + 1];
    size_t off = (((size_t)(b * NKV + kv)) * SEQ + s) * HD + 2 * p;
    *(__half2*)(g_k + off) =
        __floats2half2_rn(x0 * c - x1 * sn, x1 * c + x0 * sn);
}

// V: convert + transpose [s,d] -> [d,s] per (b,kv)
__global__ void split_v_kernel()
{
    __shared__ float tile[32][33];
    const int bk = blockIdx.z;                 // b*NKV + kv
    const int b  = bk >> 3, kv = bk & 7;
    const int s0 = blockIdx.x * 32;
    const int d0 = blockIdx.y * 32;
    const int tx = threadIdx.x & 31, ty = threadIdx.x >> 5;   // 32x8

    const float* src = g_qkv + (size_t)(b * SEQ + s0) * QKV_N
                       + DIM + NKV * HD + kv * HD + d0;
#pragma unroll
    for (int i = 0; i < 4; ++i)
        tile[ty + i * 8][tx] = src[(size_t)(ty + i * 8) * QKV_N + tx];
    __syncthreads();

    const size_t obase = ((size_t)bk * HD + d0) * SEQ + s0;
#pragma unroll
    for (int i = 0; i < 4; ++i) {
        int d = ty + i * 8;
        g_v[obase + (size_t)d * SEQ + tx] = __float2half_rn(tile[tx][d]);
    }
}

// ---------------- flash attention on HMMA ------------------------------------
// Block: 128 q rows (8 warps x 16), KV tile 64. Q/P split fp16, K/V single.
// Double-buffered K/V via cp.async, one barrier per tile, 2 CTAs/SM.
#define FSTR 72
#define FTILE_BYTES (64 * FSTR * 2)   // 9216

__global__ __launch_bounds__(256, 2)
void flash_hmma_kernel()
{
    __shared__ __half sK[2][64 * FSTR];
    __shared__ __half sV[2][64 * FSTR];   // [d][key]

    const int t = threadIdx.x;
    const int w = t >> 5, lane = t & 31;
    const int g = lane >> 2, tg = lane & 3;
    const int qb = blockIdx.x, h = blockIdx.y, b = blockIdx.z;
    const int kvh = h >> 2;
    const int qrow0 = qb * 128 + w * 16;

    const uint32_t uK0 = smem_to_u32(sK);
    const uint32_t uV0 = smem_to_u32(sV);

    const int brow = (lane & 7) + ((lane >> 4) & 1) * 8;
    const int bcol = ((lane >> 3) & 1) * 8;
    const uint32_t boff = (uint32_t)(brow * FSTR + bcol) * 2;

    // Q fragments (hi/lo), 4 k-chunks of 16 over d=64
    uint32_t qfh[4][4], qfl[4][4];
    {
        const __half* gq = g_qh + (((size_t)(b*NH+h))*SEQ + qrow0)*HD;
        const __half* gl = g_ql + (((size_t)(b*NH+h))*SEQ + qrow0)*HD;
#pragma unroll
        for (int kk = 0; kk < 4; ++kk) {
            int d0 = kk * 16 + tg * 2;
            qfh[kk][0] = *(const uint32_t*)&gq[(size_t)(g    ) * HD + d0];
            qfh[kk][1] = *(const uint32_t*)&gq[(size_t)(g + 8) * HD + d0];
            qfh[kk][2] = *(const uint32_t*)&gq[(size_t)(g    ) * HD + d0 + 8];
            qfh[kk][3] = *(const uint32_t*)&gq[(size_t)(g + 8) * HD + d0 + 8];
            qfl[kk][0] = *(const uint32_t*)&gl[(size_t)(g    ) * HD + d0];
            qfl[kk][1] = *(const uint32_t*)&gl[(size_t)(g + 8) * HD + d0];
            qfl[kk][2] = *(const uint32_t*)&gl[(size_t)(g    ) * HD + d0 + 8];
            qfl[kk][3] = *(const uint32_t*)&gl[(size_t)(g + 8) * HD + d0 + 8];
        }
    }

    float m0 = -1e30f, m1 = -1e30f, l0 = 0.f, l1 = 0.f;
    float o[8][4];
#pragma unroll
    for (int ni = 0; ni < 8; ++ni)
#pragma unroll
        for (int q = 0; q < 4; ++q) o[ni][q] = 0.f;

    const __half* gk = g_k + ((size_t)(b * NKV + kvh)) * SEQ * HD;
    const __half* gv = g_v + ((size_t)(b * NKV + kvh)) * HD * SEQ;

    auto load_tile = [&](int buf, int jb) {
#pragma unroll
        for (int cc = 0; cc < 2; ++cc) {
            int c   = t + cc * 256;
            int row = c >> 3, col = (c & 7) * 8;
            uint32_t so = (uint32_t)buf * FTILE_BYTES + (uint32_t)(row * FSTR + col) * 2;
            cp_async16(uK0 + so, &gk[(size_t)(jb * 64 + row) * HD + col]);
            cp_async16(uV0 + so, &gv[(size_t)row * SEQ + jb * 64 + col]);
        }
    };

    const int ntile = 2 * qb + 2;
    load_tile(0, 0); CP_COMMIT();

    for (int jb = 0; jb < ntile; ++jb) {
        const int buf = jb & 1;
        CP_WAIT0();
        __syncthreads();
        // Buffer buf^1's readers (compute of jb-1) finished before this barrier.
        if (jb + 1 < ntile) { load_tile(buf ^ 1, jb + 1); CP_COMMIT(); }

        if (jb * 64 <= qrow0 + 15) {
            const uint32_t uK = uK0 + buf * FTILE_BYTES;
            const uint32_t uV = uV0 + buf * FTILE_BYTES;

            // S = Q K^T
            float s[8][4];
#pragma unroll
            for (int ni = 0; ni < 8; ++ni)
                s[ni][0] = s[ni][1] = s[ni][2] = s[ni][3] = 0.f;

#pragma unroll
            for (int kk = 0; kk < 4; ++kk)
#pragma unroll
                for (int p = 0; p < 4; ++p) {
                    const uint32_t rb = (uint32_t)(p * 16 * FSTR) * 2 + kk * 32;
                    uint32_t k4[4];
                    ldsm4(k4, uK + rb + boff);
                    mma16816(s[2*p],   qfh[kk], k4 + 0);
                    mma16816(s[2*p+1], qfh[kk], k4 + 2);
                    mma16816(s[2*p],   qfl[kk], k4 + 0);
                    mma16816(s[2*p+1], qfl[kk], k4 + 2);
                }

            // causal mask (diagonal tiles only)
            if (jb * 64 + 63 > qrow0) {
                const int cb = jb * 64 + tg * 2;
                const int r0 = qrow0 + g, r1 = r0 + 8;
#pragma unroll
                for (int ni = 0; ni < 8; ++ni) {
                    int c0 = cb + ni * 8, c1 = c0 + 1;
                    if (c0 > r0) s[ni][0] = -1e30f;
                    if (c1 > r0) s[ni][1] = -1e30f;
                    if (c0 > r1) s[ni][2] = -1e30f;
                    if (c1 > r1) s[ni][3] = -1e30f;
                }
            }

            // online softmax
            float mt0 = -1e30f, mt1 = -1e30f;
#pragma unroll
            for (int ni = 0; ni < 8; ++ni) {
                mt0 = fmaxf(mt0, fmaxf(s[ni][0], s[ni][1]));
                mt1 = fmaxf(mt1, fmaxf(s[ni][2], s[ni][3]));
            }
            mt0 = fmaxf(mt0, __shfl_xor_sync(0xffffffffu, mt0, 1));
            mt0 = fmaxf(mt0, __shfl_xor_sync(0xffffffffu, mt0, 2));
            mt1 = fmaxf(mt1, __shfl_xor_sync(0xffffffffu, mt1, 1));
            mt1 = fmaxf(mt1, __shfl_xor_sync(0xffffffffu, mt1, 2));
            float mn0 = fmaxf(m0, mt0), mn1 = fmaxf(m1, mt1);
            float a0 = __expf(m0 - mn0), a1 = __expf(m1 - mn1);
            m0 = mn0; m1 = mn1;
            float rs0 = 0.f, rs1 = 0.f;
#pragma unroll
            for (int ni = 0; ni < 8; ++ni) {
                s[ni][0] = __expf(s[ni][0] - mn0);
                s[ni][1] = __expf(s[ni][1] - mn0);
                s[ni][2] = __expf(s[ni][2] - mn1);
                s[ni][3] = __expf(s[ni][3] - mn1);
                rs0 += s[ni][0] + s[ni][1];
                rs1 += s[ni][2] + s[ni][3];
            }
            l0 = l0 * a0 + rs0;
            l1 = l1 * a1 + rs1;
#pragma unroll
            for (int ni = 0; ni < 8; ++ni) {
                o[ni][0] *= a0; o[ni][1] *= a0;
                o[ni][2] *= a1; o[ni][3] *= a1;
            }

            // O += P V. P split hi/lo fp16, V single.
#pragma unroll
            for (int kk = 0; kk < 4; ++kk) {
                uint32_t ph[4], pl[4];
#pragma unroll
                for (int half = 0; half < 2; ++half) {
                    const int ni = 2 * kk + half;
                    __half2 h0 = __floats2half2_rn(s[ni][0], s[ni][1]);
                    __half2 l0v = __floats2half2_rn(
                        s[ni][0] - __half2float(h0.x),
                        s[ni][1] - __half2float(h0.y));
                    __half2 h1 = __floats2half2_rn(s[ni][2], s[ni][3]);
                    __half2 l1v = __floats2half2_rn(
                        s[ni][2] - __half2float(h1.x),
                        s[ni][3] - __half2float(h1.y));
                    ph[half * 2 + 0] = *(uint32_t*)&h0;
                    ph[half * 2 + 1] = *(uint32_t*)&h1;
                    pl[half * 2 + 0] = *(uint32_t*)&l0v;
                    pl[half * 2 + 1] = *(uint32_t*)&l1v;
                }
#pragma unroll
                for (int p = 0; p < 4; ++p) {
                    const uint32_t rb = (uint32_t)(p * 16 * FSTR) * 2 + kk * 32;
                    uint32_t v4[4];
                    ldsm4(v4, uV + rb + boff);
                    mma16816(o[2*p],   ph, v4 + 0);
                    mma16816(o[2*p+1], ph, v4 + 2);
                    mma16816(o[2*p],   pl, v4 + 0);
                    mma16816(o[2*p+1], pl, v4 + 2);
                }
            }
        }
    }

    // finalize: write fp16 hi/lo splits directly (feeds out-projection)
    l0 += __shfl_xor_sync(0xffffffffu, l0, 1);
    l0 += __shfl_xor_sync(0xffffffffu, l0, 2);
    l1 += __shfl_xor_sync(0xffffffffu, l1, 1);
    l1 += __shfl_xor_sync(0xffffffffu, l1, 2);
    const float inv0 = 1.f / l0, inv1 = 1.f / l1;

    const int r0 = qrow0 + g, r1 = r0 + 8;
#pragma unroll
    for (int ni = 0; ni < 8; ++ni) {
        const int col = h * HD + ni * 8 + tg * 2;
        {
            float v0 = o[ni][0] * inv0, v1 = o[ni][1] * inv0;
            __half2 hv = __floats2half2_rn(v0, v1);
            __half2 lv = __floats2half2_rn(
                v0 - __half2float(hv.x), v1 - __half2float(hv.y));
            size_t i0 = (size_t)(b * SEQ + r0) * DIM + col;
            *(__half2*)&g_aoh[i0] = hv;
            *(__half2*)&g_aol[i0] = lv;
        }
        {
            float v0 = o[ni][2] * inv1, v1 = o[ni][3] * inv1;
            __half2 hv = __floats2half2_rn(v0, v1);
            __half2 lv = __floats2half2_rn(
                v0 - __half2float(hv.x), v1 - __half2float(hv.y));
            size_t i1 = (size_t)(b * SEQ + r1) * DIM + col;
            *(__half2*)&g_aoh[i1] = hv;
            *(__half2*)&g_aol[i1] = lv;
        }
    }
}

// ---------------- launcher ---------------------------------------------------
extern "C" void kernel_launch(void* const* d_in, const int* in_sizes, int n_in,
                              void* d_out, int out_size)
{
    const float* x     = (const float*)d_in[0];   // [2,2048,2048]
    const float* fc    = (const float*)d_in[1];   // [2048,32,2]
    // d_in[2] = mask (causal, hardcoded)
    const float* wqkv  = (const float*)d_in[3];   // [3072,2048]
    const float* wo    = (const float*)d_in[4];   // [2048,2048]
    float* out = (float*)d_out;                   // [2,2048,2048]

    void *p_qkv;
    void *p_xh, *p_xl, *p_wq, *p_aoh, *p_aol, *p_wo;
    cudaGetSymbolAddress(&p_qkv, g_qkv);
    cudaGetSymbolAddress(&p_xh,  g_xh);  cudaGetSymbolAddress(&p_xl,  g_xl);
    cudaGetSymbolAddress(&p_wq,  g_wq);
    cudaGetSymbolAddress(&p_aoh, g_aoh); cudaGetSymbolAddress(&p_aol, g_aol);
    cudaGetSymbolAddress(&p_wo,  g_wo);

    cudaFuncSetAttribute(gemm_hmma_kernel,
                         cudaFuncAttributeMaxDynamicSharedMemorySize, GT_SMEM_BYTES);

    const int M = BSZ * SEQ;                      // 4096

    split4h_kernel<<<(M * DIM / 4 + 255) / 256, 256>>>(x,
        (__half*)p_xh, (__half*)p_xl, M * DIM / 4);
    conv4h_kernel<<<(QKV_N * DIM / 4 + 255) / 256, 256>>>(wqkv,
        (__half*)p_wq, QKV_N * DIM / 4);
    conv4h_kernel<<<(DIM * DIM / 4 + 255) / 256, 256>>>(wo,
        (__half*)p_wo, DIM * DIM / 4);

    // 1) QKV projection
    gemm_hmma_kernel<<<dim3(QKV_N / 128, M / 128), 256, GT_SMEM_BYTES>>>(
        (const __half*)p_xh, (const __half*)p_xl, (const __half*)p_wq,
        (float*)p_qkv, M, QKV_N, DIM);

    // 2) RoPE + V convert/transpose
    rope_q_kernel<<<(BSZ * SEQ * NH  * 32) / 256, 256>>>(fc);
    rope_k_kernel<<<(BSZ * SEQ * NKV * 32) / 256, 256>>>(fc);
    split_v_kernel<<<dim3(SEQ / 32, HD / 32, BSZ * NKV), 256>>>();

    // 3) causal flash attention -> g_aoh/g_aol [b,s,h*d] (fp16 hi/lo)
    flash_hmma_kernel<<<dim3(SEQ / 128, NH, BSZ), 256>>>();

    // 4) output projection
    gemm_hmma_kernel<<<dim3(DIM / 128, M / 128), 256, GT_SMEM_BYTES>>>(
        (const __half*)p_aoh, (const __half*)p_aol, (const __half*)p_wo,
        out, M, DIM, DIM);
}

// round 10
// speedup vs baseline: 6.1479x; 1.6052x over previous
#include <cuda_runtime.h>
#include <cuda_fp16.h>
#include <cstdint>
#include <cstddef>

#define BSZ 2
#define SEQ 2048
#define DIM 2048
#define NH 32
#define NKV 8
#define HD 64
#define QKV_N ((NH + 2*NKV)*HD)   // 3072

// ---------------- scratch (static device globals; no allocation) -----------
__device__ float g_qkv[(size_t)BSZ*SEQ*QKV_N];     // [4096, 3072]

// fp16 operands (single precision-pass)
__device__ __half g_x  [(size_t)BSZ*SEQ*DIM];
__device__ __half g_wq [(size_t)QKV_N*DIM];
__device__ __half g_ao [(size_t)BSZ*SEQ*DIM];
__device__ __half g_wo [(size_t)DIM*DIM];

__device__ __half g_q  [(size_t)BSZ*NH *SEQ*HD];   // [b,h,s,d] (pre-scaled 1/8)
__device__ __half g_k  [(size_t)BSZ*NKV*SEQ*HD];   // [b,kv,s,d]
__device__ __half g_v  [(size_t)BSZ*NKV*HD*SEQ];   // [b,kv,d,s] transposed

// ---------------- small PTX helpers (sm_80-baseline ISA only) ---------------
__device__ __forceinline__ uint32_t smem_to_u32(const void* p) {
    uint32_t a;
    asm("{ .reg .u64 t; cvta.to.shared.u64 t, %1; cvt.u32.u64 %0, t; }"
        : "=r"(a) : "l"(p));
    return a;
}
__device__ __forceinline__ void cp_async16(uint32_t dst, const void* src) {
    asm volatile("cp.async.cg.shared.global [%0], [%1], 16;"
                 :: "r"(dst), "l"(src) : "memory");
}
#define CP_COMMIT() asm volatile("cp.async.commit_group;" ::: "memory")
#define CP_WAIT1()  asm volatile("cp.async.wait_group 1;" ::: "memory")
#define CP_WAIT0()  asm volatile("cp.async.wait_group 0;" ::: "memory")

__device__ __forceinline__ void ldsm4(uint32_t* r, uint32_t addr) {
    asm volatile("ldmatrix.sync.aligned.m8n8.x4.shared.b16 {%0,%1,%2,%3}, [%4];"
        : "=r"(r[0]), "=r"(r[1]), "=r"(r[2]), "=r"(r[3]) : "r"(addr));
}

// D += A(16x16 fp16) * B(16x8 fp16), fp32 accum
__device__ __forceinline__ void mma16816(float* d, const uint32_t* a,
                                         const uint32_t* b) {
    asm volatile(
        "mma.sync.aligned.m16n8k16.row.col.f32.f16.f16.f32 "
        "{%0,%1,%2,%3}, {%4,%5,%6,%7}, {%8,%9}, {%0,%1,%2,%3};"
        : "+f"(d[0]), "+f"(d[1]), "+f"(d[2]), "+f"(d[3])
        : "r"(a[0]), "r"(a[1]), "r"(a[2]), "r"(a[3]), "r"(b[0]), "r"(b[1]));
}

// ---------------- conversion kernel ------------------------------------------
__global__ void conv4h_kernel(const float* __restrict__ src,
                              __half* __restrict__ dst, int n4)
{
    int i = blockIdx.x * 256 + threadIdx.x;
    if (i >= n4) return;
    float4 v = ((const float4*)src)[i];
    ((__half2*)dst)[2*i]   = __floats2half2_rn(v.x, v.y);
    ((__half2*)dst)[2*i+1] = __floats2half2_rn(v.z, v.w);
}

// ---------------- HMMA GEMM: C[M,N] = A[M,K] * B[N,K]^T ---------------------
// Single fp16 pass. 3-stage cp.async pipeline, 128x128x32 tiles, 8 warps,
// one barrier per chunk.
#define GSTR 40
#define TILE_ELEMS (128 * GSTR)
#define TILE_BYTES (TILE_ELEMS * 2)
#define GT_SMEM_BYTES (3 * 2 * TILE_BYTES)      // 61440

__global__ __launch_bounds__(256, 2)
void gemm_hmma_kernel(const __half* __restrict__ A,
                      const __half* __restrict__ B,
                      float* __restrict__ C, int M, int N, int K)
{
    extern __shared__ __half sm[];
    const uint32_t sbase = smem_to_u32(sm);
    const int t    = threadIdx.x;
    const int wid  = t >> 5, lane = t & 31;
    const int bm   = blockIdx.y * 128, bn = blockIdx.x * 128;
    const int wm   = (wid & 1) * 64;
    const int wn   = (wid >> 1) * 32;
    const int lr   = lane >> 2;
    const int lc   = lane & 3;

    // ldmatrix lane offsets
    const int arow = (lane & 7) + ((lane >> 3) & 1) * 8;
    const int acol = (lane >> 4) * 8;
    const uint32_t aoff = (uint32_t)(arow * GSTR + acol) * 2;
    const int brow = (lane & 7) + ((lane >> 4) & 1) * 8;
    const int bcol = ((lane >> 3) & 1) * 8;
    const uint32_t boff = (uint32_t)(brow * GSTR + bcol) * 2;

    const int r0 = t >> 2,  c0 = t & 3;
    const int r1 = (t + 256) >> 2, c1 = t & 3;

    float acc[4][4][4];
#pragma unroll
    for (int mi = 0; mi < 4; ++mi)
#pragma unroll
        for (int ni = 0; ni < 4; ++ni)
#pragma unroll
            for (int q = 0; q < 4; ++q) acc[mi][ni][q] = 0.f;

    const int nch = K / 32;

    auto load_chunk = [&](int buf, int kc) {
        const __half* gA = A + (size_t)bm * K + kc * 32;
        const __half* gB = B + (size_t)bn * K + kc * 32;
        uint32_t sdA = sbase + (buf * 2 + 0) * TILE_BYTES;
        uint32_t sdB = sbase + (buf * 2 + 1) * TILE_BYTES;
        cp_async16(sdA + r0 * (GSTR*2) + c0 * 16, gA + (size_t)r0 * K + c0 * 8);
        cp_async16(sdA + r1 * (GSTR*2) + c1 * 16, gA + (size_t)r1 * K + c1 * 8);
        cp_async16(sdB + r0 * (GSTR*2) + c0 * 16, gB + (size_t)r0 * K + c0 * 8);
        cp_async16(sdB + r1 * (GSTR*2) + c1 * 16, gB + (size_t)r1 * K + c1 * 8);
    };

    load_chunk(0, 0); CP_COMMIT();
    load_chunk(1, 1); CP_COMMIT();

    int buf = 0;
    for (int c = 0; c < nch; ++c) {
        if (c + 1 < nch) CP_WAIT1();
        else             CP_WAIT0();
        __syncthreads();
        // Buffer (c+2)%3's readers (compute of chunk c-1) finished before
        // this barrier in program order.
        if (c + 2 < nch) { load_chunk((c + 2) % 3, c + 2); CP_COMMIT(); }

        const uint32_t uA = sbase + (buf * 2 + 0) * TILE_BYTES;
        const uint32_t uB = sbase + (buf * 2 + 1) * TILE_BYTES;

#pragma unroll
        for (int ks = 0; ks < 2; ++ks) {
            uint32_t a4[4][4], b4[2][4];
#pragma unroll
            for (int mi = 0; mi < 4; ++mi) {
                const uint32_t ra = (uint32_t)((wm + mi * 16) * GSTR) * 2 + ks * 32;
                ldsm4(a4[mi], uA + ra + aoff);
            }
#pragma unroll
            for (int p = 0; p < 2; ++p) {
                const uint32_t rb = (uint32_t)((wn + p * 16) * GSTR) * 2 + ks * 32;
                ldsm4(b4[p], uB + rb + boff);
            }
#pragma unroll
            for (int mi = 0; mi < 4; ++mi)
#pragma unroll
                for (int ni = 0; ni < 4; ++ni)
                    mma16816(acc[mi][ni], a4[mi], &b4[ni >> 1][(ni & 1) * 2]);
        }
        buf = (buf == 2) ? 0 : buf + 1;
    }

#pragma unroll
    for (int mi = 0; mi < 4; ++mi) {
        const int row = bm + wm + mi * 16 + lr;
#pragma unroll
        for (int ni = 0; ni < 4; ++ni) {
            const int col = bn + wn + ni * 8 + lc * 2;
            *(float2*)&C[(size_t)row * N + col] =
                make_float2(acc[mi][ni][0], acc[mi][ni][1]);
            *(float2*)&C[(size_t)(row + 8) * N + col] =
                make_float2(acc[mi][ni][2], acc[mi][ni][3]);
        }
    }
}

// ---------------- RoPE -> fp16 -----------------------------------------------
__global__ void rope_q_kernel(const float* __restrict__ fc)
{
    int gid = blockIdx.x * 256 + threadIdx.x;
    int p = gid & 31;
    int h = (gid >> 5) & 31;
    int s = (gid >> 10) & 2047;
    int b = gid >> 21;
    const float* src = g_qkv + (size_t)(b * SEQ + s) * QKV_N + h * HD + 2 * p;
    float x0 = src[0], x1 = src[1];
    float c  = fc[s * HD + 2 * p];
    float sn = fc[s * HD + 2 * p + 1];
    size_t off = (((size_t)(b * NH + h)) * SEQ + s) * HD + 2 * p;
    *(__half2*)(g_q + off) = __floats2half2_rn(
        (x0 * c - x1 * sn) * 0.125f, (x1 * c + x0 * sn) * 0.125f);
}

__global__ void rope_k_kernel(const float* __restrict__ fc)
{
    int gid = blockIdx.x * 256 + threadIdx.x;
    int p  = gid & 31;
    int kv = (gid >> 5) & 7;
    int s  = (gid >> 8) & 2047;
    int b  = gid >> 19;
    const float* src = g_qkv + (size_t)(b * SEQ + s) * QKV_N + DIM + kv * HD + 2 * p;
    float x0 = src[0], x1 = src[1];
    float c  = fc[s * HD + 2 * p];
    float sn = fc[s * HD + 2 * p + 1];
    size_t off = (((size_t)(b * NKV + kv)) * SEQ + s) * HD + 2 * p;
    *(__half2*)(g_k + off) =
        __floats2half2_rn(x0 * c - x1 * sn, x1 * c + x0 * sn);
}

// V: convert + transpose [s,d] -> [d,s] per (b,kv)
__global__ void split_v_kernel()
{
    __shared__ float tile[32][33];
    const int bk = blockIdx.z;                 // b*NKV + kv
    const int b  = bk >> 3, kv = bk & 7;
    const int s0 = blockIdx.x * 32;
    const int d0 = blockIdx.y * 32;
    const int tx = threadIdx.x & 31, ty = threadIdx.x >> 5;   // 32x8

    const float* src = g_qkv + (size_t)(b * SEQ + s0) * QKV_N
                       + DIM + NKV * HD + kv * HD + d0;
#pragma unroll
    for (int i = 0; i < 4; ++i)
        tile[ty + i * 8][tx] = src[(size_t)(ty + i * 8) * QKV_N + tx];
    __syncthreads();

    const size_t obase = ((size_t)bk * HD + d0) * SEQ + s0;
#pragma unroll
    for (int i = 0; i < 4; ++i) {
        int d = ty + i * 8;
        g_v[obase + (size_t)d * SEQ + tx] = __float2half_rn(tile[tx][d]);
    }
}

// ---------------- flash attention on HMMA ------------------------------------
// Block: 128 q rows (8 warps x 16), KV tile 64. Single fp16 pass everywhere.
// Double-buffered K/V via cp.async, one barrier per tile, 2 CTAs/SM.
#define FSTR 72
#define FTILE_BYTES (64 * FSTR * 2)   // 9216

__global__ __launch_bounds__(256, 2)
void flash_hmma_kernel()
{
    __shared__ __half sK[2][64 * FSTR];
    __shared__ __half sV[2][64 * FSTR];   // [d][key]

    const int t = threadIdx.x;
    const int w = t >> 5, lane = t & 31;
    const int g = lane >> 2, tg = lane & 3;
    const int qb = blockIdx.x, h = blockIdx.y, b = blockIdx.z;
    const int kvh = h >> 2;
    const int qrow0 = qb * 128 + w * 16;

    const uint32_t uK0 = smem_to_u32(sK);
    const uint32_t uV0 = smem_to_u32(sV);

    const int brow = (lane & 7) + ((lane >> 4) & 1) * 8;
    const int bcol = ((lane >> 3) & 1) * 8;
    const uint32_t boff = (uint32_t)(brow * FSTR + bcol) * 2;

    // Q fragments, 4 k-chunks of 16 over d=64
    uint32_t qf[4][4];
    {
        const __half* gq = g_q + (((size_t)(b*NH+h))*SEQ + qrow0)*HD;
#pragma unroll
        for (int kk = 0; kk < 4; ++kk) {
            int d0 = kk * 16 + tg * 2;
            qf[kk][0] = *(const uint32_t*)&gq[(size_t)(g    ) * HD + d0];
            qf[kk][1] = *(const uint32_t*)&gq[(size_t)(g + 8) * HD + d0];
            qf[kk][2] = *(const uint32_t*)&gq[(size_t)(g    ) * HD + d0 + 8];
            qf[kk][3] = *(const uint32_t*)&gq[(size_t)(g + 8) * HD + d0 + 8];
        }
    }

    float m0 = -1e30f, m1 = -1e30f, l0 = 0.f, l1 = 0.f;
    float o[8][4];
#pragma unroll
    for (int ni = 0; ni < 8; ++ni)
#pragma unroll
        for (int q = 0; q < 4; ++q) o[ni][q] = 0.f;

    const __half* gk = g_k + ((size_t)(b * NKV + kvh)) * SEQ * HD;
    const __half* gv = g_v + ((size_t)(b * NKV + kvh)) * HD * SEQ;

    auto load_tile = [&](int buf, int jb) {
#pragma unroll
        for (int cc = 0; cc < 2; ++cc) {
            int c   = t + cc * 256;
            int row = c >> 3, col = (c & 7) * 8;
            uint32_t so = (uint32_t)buf * FTILE_BYTES + (uint32_t)(row * FSTR + col) * 2;
            cp_async16(uK0 + so, &gk[(size_t)(jb * 64 + row) * HD + col]);
            cp_async16(uV0 + so, &gv[(size_t)row * SEQ + jb * 64 + col]);
        }
    };

    const int ntile = 2 * qb + 2;
    load_tile(0, 0); CP_COMMIT();

    for (int jb = 0; jb < ntile; ++jb) {
        const int buf = jb & 1;
        CP_WAIT0();
        __syncthreads();
        if (jb + 1 < ntile) { load_tile(buf ^ 1, jb + 1); CP_COMMIT(); }

        if (jb * 64 <= qrow0 + 15) {
            const uint32_t uK = uK0 + buf * FTILE_BYTES;
            const uint32_t uV = uV0 + buf * FTILE_BYTES;

            // S = Q K^T
            float s[8][4];
#pragma unroll
            for (int ni = 0; ni < 8; ++ni)
                s[ni][0] = s[ni][1] = s[ni][2] = s[ni][3] = 0.f;

#pragma unroll
            for (int kk = 0; kk < 4; ++kk)
#pragma unroll
                for (int p = 0; p < 4; ++p) {
                    const uint32_t rb = (uint32_t)(p * 16 * FSTR) * 2 + kk * 32;
                    uint32_t k4[4];
                    ldsm4(k4, uK + rb + boff);
                    mma16816(s[2*p],   qf[kk], k4 + 0);
                    mma16816(s[2*p+1], qf[kk], k4 + 2);
                }

            // causal mask (diagonal tiles only)
            if (jb * 64 + 63 > qrow0) {
                const int cb = jb * 64 + tg * 2;
                const int r0 = qrow0 + g, r1 = r0 + 8;
#pragma unroll
                for (int ni = 0; ni < 8; ++ni) {
                    int c0 = cb + ni * 8, c1 = c0 + 1;
                    if (c0 > r0) s[ni][0] = -1e30f;
                    if (c1 > r0) s[ni][1] = -1e30f;
                    if (c0 > r1) s[ni][2] = -1e30f;
                    if (c1 > r1) s[ni][3] = -1e30f;
                }
            }

            // online softmax
            float mt0 = -1e30f, mt1 = -1e30f;
#pragma unroll
            for (int ni = 0; ni < 8; ++ni) {
                mt0 = fmaxf(mt0, fmaxf(s[ni][0], s[ni][1]));
                mt1 = fmaxf(mt1, fmaxf(s[ni][2], s[ni][3]));
            }
            mt0 = fmaxf(mt0, __shfl_xor_sync(0xffffffffu, mt0, 1));
            mt0 = fmaxf(mt0, __shfl_xor_sync(0xffffffffu, mt0, 2));
            mt1 = fmaxf(mt1, __shfl_xor_sync(0xffffffffu, mt1, 1));
            mt1 = fmaxf(mt1, __shfl_xor_sync(0xffffffffu, mt1, 2));
            float mn0 = fmaxf(m0, mt0), mn1 = fmaxf(m1, mt1);
            float a0 = __expf(m0 - mn0), a1 = __expf(m1 - mn1);
            m0 = mn0; m1 = mn1;
            float rs0 = 0.f, rs1 = 0.f;
#pragma unroll
            for (int ni = 0; ni < 8; ++ni) {
                s[ni][0] = __expf(s[ni][0] - mn0);
                s[ni][1] = __expf(s[ni][1] - mn0);
                s[ni][2] = __expf(s[ni][2] - mn1);
                s[ni][3] = __expf(s[ni][3] - mn1);
                rs0 += s[ni][0] + s[ni][1];
                rs1 += s[ni][2] + s[ni][3];
            }
            l0 = l0 * a0 + rs0;
            l1 = l1 * a1 + rs1;
#pragma unroll
            for (int ni = 0; ni < 8; ++ni) {
                o[ni][0] *= a0; o[ni][1] *= a0;
                o[ni][2] *= a1; o[ni][3] *= a1;
            }

            // O += P V (single fp16 P)
#pragma unroll
            for (int kk = 0; kk < 4; ++kk) {
                uint32_t ph[4];
#pragma unroll
                for (int half = 0; half < 2; ++half) {
                    const int ni = 2 * kk + half;
                    __half2 h0 = __floats2half2_rn(s[ni][0], s[ni][1]);
                    __half2 h1 = __floats2half2_rn(s[ni][2], s[ni][3]);
                    ph[half * 2 + 0] = *(uint32_t*)&h0;
                    ph[half * 2 + 1] = *(uint32_t*)&h1;
                }
#pragma unroll
                for (int p = 0; p < 4; ++p) {
                    const uint32_t rb = (uint32_t)(p * 16 * FSTR) * 2 + kk * 32;
                    uint32_t v4[4];
                    ldsm4(v4, uV + rb + boff);
                    mma16816(o[2*p],   ph, v4 + 0);
                    mma16816(o[2*p+1], ph, v4 + 2);
                }
            }
        }
    }

    // finalize: write fp16 directly (feeds out-projection)
    l0 += __shfl_xor_sync(0xffffffffu, l0, 1);
    l0 += __shfl_xor_sync(0xffffffffu, l0, 2);
    l1 += __shfl_xor_sync(0xffffffffu, l1, 1);
    l1 += __shfl_xor_sync(0xffffffffu, l1, 2);
    const float inv0 = 1.f / l0, inv1 = 1.f / l1;

    const int r0 = qrow0 + g, r1 = r0 + 8;
#pragma unroll
    for (int ni = 0; ni < 8; ++ni) {
        const int col = h * HD + ni * 8 + tg * 2;
        *(__half2*)&g_ao[(size_t)(b * SEQ + r0) * DIM + col] =
            __floats2half2_rn(o[ni][0] * inv0, o[ni][1] * inv0);
        *(__half2*)&g_ao[(size_t)(b * SEQ + r1) * DIM + col] =
            __floats2half2_rn(o[ni][2] * inv1, o[ni][3] * inv1);
    }
}

// ---------------- launcher ---------------------------------------------------
extern "C" void kernel_launch(void* const* d_in, const int* in_sizes, int n_in,
                              void* d_out, int out_size)
{
    const float* x     = (const float*)d_in[0];   // [2,2048,2048]
    const float* fc    = (const float*)d_in[1];   // [2048,32,2]
    // d_in[2] = mask (causal, hardcoded)
    const float* wqkv  = (const float*)d_in[3];   // [3072,2048]
    const float* wo    = (const float*)d_in[4];   // [2048,2048]
    float* out = (float*)d_out;                   // [2,2048,2048]

    void *p_qkv, *p_x, *p_wq, *p_ao, *p_wo;
    cudaGetSymbolAddress(&p_qkv, g_qkv);
    cudaGetSymbolAddress(&p_x,   g_x);
    cudaGetSymbolAddress(&p_wq,  g_wq);
    cudaGetSymbolAddress(&p_ao,  g_ao);
    cudaGetSymbolAddress(&p_wo,  g_wo);

    cudaFuncSetAttribute(gemm_hmma_kernel,
                         cudaFuncAttributeMaxDynamicSharedMemorySize, GT_SMEM_BYTES);

    const int M = BSZ * SEQ;                      // 4096

    conv4h_kernel<<<(M * DIM / 4 + 255) / 256, 256>>>(x,
        (__half*)p_x, M * DIM / 4);
    conv4h_kernel<<<(QKV_N * DIM / 4 + 255) / 256, 256>>>(wqkv,
        (__half*)p_wq, QKV_N * DIM / 4);
    conv4h_kernel<<<(DIM * DIM / 4 + 255) / 256, 256>>>(wo,
        (__half*)p_wo, DIM * DIM / 4);

    // 1) QKV projection
    gemm_hmma_kernel<<<dim3(QKV_N / 128, M / 128), 256, GT_SMEM_BYTES>>>(
        (const __half*)p_x, (const __half*)p_wq,
        (float*)p_qkv, M, QKV_N, DIM);

    // 2) RoPE + V convert/transpose
    rope_q_kernel<<<(BSZ * SEQ * NH  * 32) / 256, 256>>>(fc);
    rope_k_kernel<<<(BSZ * SEQ * NKV * 32) / 256, 256>>>(fc);
    split_v_kernel<<<dim3(SEQ / 32, HD / 32, BSZ * NKV), 256>>>();

    // 3) causal flash attention -> g_ao [b,s,h*d] (fp16)
    flash_hmma_kernel<<<dim3(SEQ / 128, NH, BSZ), 256>>>();

    // 4) output projection
    gemm_hmma_kernel<<<dim3(DIM / 128, M / 128), 256, GT_SMEM_BYTES>>>(
        (const __half*)p_ao, (const __half*)p_wo,
        out, M, DIM, DIM);
}

// round 11
// speedup vs baseline: 6.9119x; 1.1243x over previous
#include <cuda_runtime.h>
#include <cuda_fp16.h>
#include <cstdint>
#include <cstddef>

#define BSZ 2
#define SEQ 2048
#define DIM 2048
#define NH 32
#define NKV 8
#define HD 64
#define QKV_N ((NH + 2*NKV)*HD)   // 3072

// ---------------- scratch (static device globals; no allocation) -----------
__device__ __half g_qkvh[(size_t)BSZ*SEQ*QKV_N];   // [4096, 3072] fp16

// fp16 operands (single precision-pass)
__device__ __half g_x  [(size_t)BSZ*SEQ*DIM];
__device__ __half g_wq [(size_t)QKV_N*DIM];
__device__ __half g_ao [(size_t)BSZ*SEQ*DIM];
__device__ __half g_wo [(size_t)DIM*DIM];

__device__ __half g_q  [(size_t)BSZ*NH *SEQ*HD];   // [b,h,s,d] (pre-scaled 1/8)
__device__ __half g_k  [(size_t)BSZ*NKV*SEQ*HD];   // [b,kv,s,d]
__device__ __half g_v  [(size_t)BSZ*NKV*HD*SEQ];   // [b,kv,d,s] transposed

// ---------------- small PTX helpers (sm_80-baseline ISA only) ---------------
__device__ __forceinline__ uint32_t smem_to_u32(const void* p) {
    uint32_t a;
    asm("{ .reg .u64 t; cvta.to.shared.u64 t, %1; cvt.u32.u64 %0, t; }"
        : "=r"(a) : "l"(p));
    return a;
}
__device__ __forceinline__ void cp_async16(uint32_t dst, const void* src) {
    asm volatile("cp.async.cg.shared.global [%0], [%1], 16;"
                 :: "r"(dst), "l"(src) : "memory");
}
#define CP_COMMIT() asm volatile("cp.async.commit_group;" ::: "memory")
#define CP_WAIT0()  asm volatile("cp.async.wait_group 0;" ::: "memory")

__device__ __forceinline__ void ldsm4(uint32_t* r, uint32_t addr) {
    asm volatile("ldmatrix.sync.aligned.m8n8.x4.shared.b16 {%0,%1,%2,%3}, [%4];"
        : "=r"(r[0]), "=r"(r[1]), "=r"(r[2]), "=r"(r[3]) : "r"(addr));
}

// D += A(16x16 fp16) * B(16x8 fp16), fp32 accum
__device__ __forceinline__ void mma16816(float* d, const uint32_t* a,
                                         const uint32_t* b) {
    asm volatile(
        "mma.sync.aligned.m16n8k16.row.col.f32.f16.f16.f32 "
        "{%0,%1,%2,%3}, {%4,%5,%6,%7}, {%8,%9}, {%0,%1,%2,%3};"
        : "+f"(d[0]), "+f"(d[1]), "+f"(d[2]), "+f"(d[3])
        : "r"(a[0]), "r"(a[1]), "r"(a[2]), "r"(a[3]), "r"(b[0]), "r"(b[1]));
}

// ---------------- conversion kernel ------------------------------------------
__global__ void conv4h_kernel(const float* __restrict__ src,
                              __half* __restrict__ dst, int n4)
{
    int i = blockIdx.x * 256 + threadIdx.x;
    if (i >= n4) return;
    float4 v = ((const float4*)src)[i];
    ((__half2*)dst)[2*i]   = __floats2half2_rn(v.x, v.y);
    ((__half2*)dst)[2*i+1] = __floats2half2_rn(v.z, v.w);
}

// ---------------- HMMA GEMM: C[M,N] = A[M,K] * B[N,K]^T ---------------------
// Single fp16 pass. K-chunk 64, 2-stage cp.async pipeline, 128x128 tiles,
// 8 warps, one barrier per chunk. Template selects fp16 or fp32 output.
#define GSTR 72
#define TILE_BYTES (128 * GSTR * 2)             // 18432
#define GT_SMEM_BYTES (2 * 2 * TILE_BYTES)      // 73728

template<bool HALF_OUT>
__global__ __launch_bounds__(256, 2)
void gemm_hmma_kernel(const __half* __restrict__ A,
                      const __half* __restrict__ B,
                      void* __restrict__ Cv, int M, int N, int K)
{
    extern __shared__ __half sm[];
    const uint32_t sbase = smem_to_u32(sm);
    const int t    = threadIdx.x;
    const int wid  = t >> 5, lane = t & 31;
    const int bm   = blockIdx.y * 128, bn = blockIdx.x * 128;
    const int wm   = (wid & 1) * 64;
    const int wn   = (wid >> 1) * 32;
    const int lr   = lane >> 2;
    const int lc   = lane & 3;

    // ldmatrix lane offsets
    const int arow = (lane & 7) + ((lane >> 3) & 1) * 8;
    const int acol = (lane >> 4) * 8;
    const uint32_t aoff = (uint32_t)(arow * GSTR + acol) * 2;
    const int brow = (lane & 7) + ((lane >> 4) & 1) * 8;
    const int bcol = ((lane >> 3) & 1) * 8;
    const uint32_t boff = (uint32_t)(brow * GSTR + bcol) * 2;

    float acc[4][4][4];
#pragma unroll
    for (int mi = 0; mi < 4; ++mi)
#pragma unroll
        for (int ni = 0; ni < 4; ++ni)
#pragma unroll
            for (int q = 0; q < 4; ++q) acc[mi][ni][q] = 0.f;

    const int nch = K / 64;

    auto load_chunk = [&](int buf, int kc) {
        const __half* gA = A + (size_t)bm * K + kc * 64;
        const __half* gB = B + (size_t)bn * K + kc * 64;
        const uint32_t sdA = sbase + buf * 2 * TILE_BYTES;
        const uint32_t sdB = sdA + TILE_BYTES;
#pragma unroll
        for (int i = 0; i < 4; ++i) {
            int c   = t + i * 256;
            int row = c >> 3, cc = c & 7;
            cp_async16(sdA + (uint32_t)(row * GSTR * 2) + cc * 16,
                       gA + (size_t)row * K + cc * 8);
            cp_async16(sdB + (uint32_t)(row * GSTR * 2) + cc * 16,
                       gB + (size_t)row * K + cc * 8);
        }
    };

    load_chunk(0, 0); CP_COMMIT();

    for (int c = 0; c < nch; ++c) {
        CP_WAIT0();
        __syncthreads();
        if (c + 1 < nch) { load_chunk((c + 1) & 1, c + 1); CP_COMMIT(); }

        const int buf = c & 1;
        const uint32_t uA = sbase + buf * 2 * TILE_BYTES;
        const uint32_t uB = uA + TILE_BYTES;

#pragma unroll
        for (int ks = 0; ks < 4; ++ks) {
            uint32_t a4[4][4], b4[2][4];
#pragma unroll
            for (int mi = 0; mi < 4; ++mi) {
                const uint32_t ra = (uint32_t)((wm + mi * 16) * GSTR) * 2 + ks * 32;
                ldsm4(a4[mi], uA + ra + aoff);
            }
#pragma unroll
            for (int p = 0; p < 2; ++p) {
                const uint32_t rb = (uint32_t)((wn + p * 16) * GSTR) * 2 + ks * 32;
                ldsm4(b4[p], uB + rb + boff);
            }
#pragma unroll
            for (int mi = 0; mi < 4; ++mi)
#pragma unroll
                for (int ni = 0; ni < 4; ++ni)
                    mma16816(acc[mi][ni], a4[mi], &b4[ni >> 1][(ni & 1) * 2]);
        }
    }

#pragma unroll
    for (int mi = 0; mi < 4; ++mi) {
        const int row = bm + wm + mi * 16 + lr;
#pragma unroll
        for (int ni = 0; ni < 4; ++ni) {
            const int col = bn + wn + ni * 8 + lc * 2;
            if (HALF_OUT) {
                __half* Ch = (__half*)Cv;
                *(__half2*)&Ch[(size_t)row * N + col] =
                    __floats2half2_rn(acc[mi][ni][0], acc[mi][ni][1]);
                *(__half2*)&Ch[(size_t)(row + 8) * N + col] =
                    __floats2half2_rn(acc[mi][ni][2], acc[mi][ni][3]);
            } else {
                float* Cf = (float*)Cv;
                *(float2*)&Cf[(size_t)row * N + col] =
                    make_float2(acc[mi][ni][0], acc[mi][ni][1]);
                *(float2*)&Cf[(size_t)(row + 8) * N + col] =
                    make_float2(acc[mi][ni][2], acc[mi][ni][3]);
            }
        }
    }
}

// ---------------- RoPE (reads fp16 qkv) --------------------------------------
__global__ void rope_q_kernel(const float* __restrict__ fc)
{
    int gid = blockIdx.x * 256 + threadIdx.x;
    int p = gid & 31;
    int h = (gid >> 5) & 31;
    int s = (gid >> 10) & 2047;
    int b = gid >> 21;
    __half2 xv = *(const __half2*)(g_qkvh + (size_t)(b * SEQ + s) * QKV_N + h * HD + 2 * p);
    float x0 = __half2float(xv.x), x1 = __half2float(xv.y);
    float c  = fc[s * HD + 2 * p];
    float sn = fc[s * HD + 2 * p + 1];
    size_t off = (((size_t)(b * NH + h)) * SEQ + s) * HD + 2 * p;
    *(__half2*)(g_q + off) = __floats2half2_rn(
        (x0 * c - x1 * sn) * 0.125f, (x1 * c + x0 * sn) * 0.125f);
}

__global__ void rope_k_kernel(const float* __restrict__ fc)
{
    int gid = blockIdx.x * 256 + threadIdx.x;
    int p  = gid & 31;
    int kv = (gid >> 5) & 7;
    int s  = (gid >> 8) & 2047;
    int b  = gid >> 19;
    __half2 xv = *(const __half2*)(g_qkvh + (size_t)(b * SEQ + s) * QKV_N
                                   + DIM + kv * HD + 2 * p);
    float x0 = __half2float(xv.x), x1 = __half2float(xv.y);
    float c  = fc[s * HD + 2 * p];
    float sn = fc[s * HD + 2 * p + 1];
    size_t off = (((size_t)(b * NKV + kv)) * SEQ + s) * HD + 2 * p;
    *(__half2*)(g_k + off) =
        __floats2half2_rn(x0 * c - x1 * sn, x1 * c + x0 * sn);
}

// V: transpose [s,d] -> [d,s] per (b,kv), fp16 passthrough
__global__ void split_v_kernel()
{
    __shared__ __half tile[32][33];
    const int bk = blockIdx.z;                 // b*NKV + kv
    const int b  = bk >> 3, kv = bk & 7;
    const int s0 = blockIdx.x * 32;
    const int d0 = blockIdx.y * 32;
    const int tx = threadIdx.x & 31, ty = threadIdx.x >> 5;   // 32x8

    const __half* src = g_qkvh + (size_t)(b * SEQ + s0) * QKV_N
                        + DIM + NKV * HD + kv * HD + d0;
#pragma unroll
    for (int i = 0; i < 4; ++i)
        tile[ty + i * 8][tx] = src[(size_t)(ty + i * 8) * QKV_N + tx];
    __syncthreads();

    const size_t obase = ((size_t)bk * HD + d0) * SEQ + s0;
#pragma unroll
    for (int i = 0; i < 4; ++i) {
        int d = ty + i * 8;
        g_v[obase + (size_t)d * SEQ + tx] = tile[tx][d];
    }
}

// ---------------- flash attention on HMMA ------------------------------------
// Block: 128 q rows (8 warps x 16), KV tile 64. fp16 P via ex2.approx.f16x2.
#define FSTR 72
#define FTILE_BYTES (64 * FSTR * 2)   // 9216

__global__ __launch_bounds__(256, 2)
void flash_hmma_kernel()
{
    __shared__ __half sK[2][64 * FSTR];
    __shared__ __half sV[2][64 * FSTR];   // [d][key]

    const int t = threadIdx.x;
    const int w = t >> 5, lane = t & 31;
    const int g = lane >> 2, tg = lane & 3;
    const int qb = blockIdx.x, h = blockIdx.y, b = blockIdx.z;
    const int kvh = h >> 2;
    const int qrow0 = qb * 128 + w * 16;

    const uint32_t uK0 = smem_to_u32(sK);
    const uint32_t uV0 = smem_to_u32(sV);

    const int brow = (lane & 7) + ((lane >> 4) & 1) * 8;
    const int bcol = ((lane >> 3) & 1) * 8;
    const uint32_t boff = (uint32_t)(brow * FSTR + bcol) * 2;

    // Q fragments, 4 k-chunks of 16 over d=64
    uint32_t qf[4][4];
    {
        const __half* gq = g_q + (((size_t)(b*NH+h))*SEQ + qrow0)*HD;
#pragma unroll
        for (int kk = 0; kk < 4; ++kk) {
            int d0 = kk * 16 + tg * 2;
            qf[kk][0] = *(const uint32_t*)&gq[(size_t)(g    ) * HD + d0];
            qf[kk][1] = *(const uint32_t*)&gq[(size_t)(g + 8) * HD + d0];
            qf[kk][2] = *(const uint32_t*)&gq[(size_t)(g    ) * HD + d0 + 8];
            qf[kk][3] = *(const uint32_t*)&gq[(size_t)(g + 8) * HD + d0 + 8];
        }
    }

    float m0 = -1e30f, m1 = -1e30f, l0 = 0.f, l1 = 0.f;
    float o[8][4];
#pragma unroll
    for (int ni = 0; ni < 8; ++ni)
#pragma unroll
        for (int q = 0; q < 4; ++q) o[ni][q] = 0.f;

    const __half* gk = g_k + ((size_t)(b * NKV + kvh)) * SEQ * HD;
    const __half* gv = g_v + ((size_t)(b * NKV + kvh)) * HD * SEQ;

    auto load_tile = [&](int buf, int jb) {
#pragma unroll
        for (int cc = 0; cc < 2; ++cc) {
            int c   = t + cc * 256;
            int row = c >> 3, col = (c & 7) * 8;
            uint32_t so = (uint32_t)buf * FTILE_BYTES + (uint32_t)(row * FSTR + col) * 2;
            cp_async16(uK0 + so, &gk[(size_t)(jb * 64 + row) * HD + col]);
            cp_async16(uV0 + so, &gv[(size_t)row * SEQ + jb * 64 + col]);
        }
    };

    const float L2E = 1.4426950408889634f;
    const int ntile = 2 * qb + 2;
    load_tile(0, 0); CP_COMMIT();

    for (int jb = 0; jb < ntile; ++jb) {
        const int buf = jb & 1;
        CP_WAIT0();
        __syncthreads();
        if (jb + 1 < ntile) { load_tile(buf ^ 1, jb + 1); CP_COMMIT(); }

        if (jb * 64 <= qrow0 + 15) {
            const uint32_t uK = uK0 + buf * FTILE_BYTES;
            const uint32_t uV = uV0 + buf * FTILE_BYTES;

            // S = Q K^T
            float s[8][4];
#pragma unroll
            for (int ni = 0; ni < 8; ++ni)
                s[ni][0] = s[ni][1] = s[ni][2] = s[ni][3] = 0.f;

#pragma unroll
            for (int kk = 0; kk < 4; ++kk)
#pragma unroll
                for (int p = 0; p < 4; ++p) {
                    const uint32_t rb = (uint32_t)(p * 16 * FSTR) * 2 + kk * 32;
                    uint32_t k4[4];
                    ldsm4(k4, uK + rb + boff);
                    mma16816(s[2*p],   qf[kk], k4 + 0);
                    mma16816(s[2*p+1], qf[kk], k4 + 2);
                }

            // causal mask (diagonal tiles only)
            if (jb * 64 + 63 > qrow0) {
                const int cb = jb * 64 + tg * 2;
                const int r0 = qrow0 + g, r1 = r0 + 8;
#pragma unroll
                for (int ni = 0; ni < 8; ++ni) {
                    int c0 = cb + ni * 8, c1 = c0 + 1;
                    if (c0 > r0) s[ni][0] = -1e30f;
                    if (c1 > r0) s[ni][1] = -1e30f;
                    if (c0 > r1) s[ni][2] = -1e30f;
                    if (c1 > r1) s[ni][3] = -1e30f;
                }
            }

            // online softmax: max in fp32, exp via ex2.approx.f16x2
            float mt0 = -1e30f, mt1 = -1e30f;
#pragma unroll
            for (int ni = 0; ni < 8; ++ni) {
                mt0 = fmaxf(mt0, fmaxf(s[ni][0], s[ni][1]));
                mt1 = fmaxf(mt1, fmaxf(s[ni][2], s[ni][3]));
            }
            mt0 = fmaxf(mt0, __shfl_xor_sync(0xffffffffu, mt0, 1));
            mt0 = fmaxf(mt0, __shfl_xor_sync(0xffffffffu, mt0, 2));
            mt1 = fmaxf(mt1, __shfl_xor_sync(0xffffffffu, mt1, 1));
            mt1 = fmaxf(mt1, __shfl_xor_sync(0xffffffffu, mt1, 2));
            float mn0 = fmaxf(m0, mt0), mn1 = fmaxf(m1, mt1);
            float a0 = __expf(m0 - mn0), a1 = __expf(m1 - mn1);
            m0 = mn0; m1 = mn1;
            const float b0 = mn0 * L2E, b1 = mn1 * L2E;

            uint32_t pe0[8], pe1[8];        // fp16x2 P: rows g / g+8
            float rs0 = 0.f, rs1 = 0.f;
#pragma unroll
            for (int ni = 0; ni < 8; ++ni) {
                __half2 e01 = h2exp2(__floats2half2_rn(
                    fmaf(s[ni][0], L2E, -b0), fmaf(s[ni][1], L2E, -b0)));
                __half2 e23 = h2exp2(__floats2half2_rn(
                    fmaf(s[ni][2], L2E, -b1), fmaf(s[ni][3], L2E, -b1)));
                pe0[ni] = *(uint32_t*)&e01;
                pe1[ni] = *(uint32_t*)&e23;
                float2 f01 = __half22float2(e01);
                float2 f23 = __half22float2(e23);
                rs0 += f01.x + f01.y;
                rs1 += f23.x + f23.y;
            }
            l0 = l0 * a0 + rs0;
            l1 = l1 * a1 + rs1;
#pragma unroll
            for (int ni = 0; ni < 8; ++ni) {
                o[ni][0] *= a0; o[ni][1] *= a0;
                o[ni][2] *= a1; o[ni][3] *= a1;
            }

            // O += P V (P fragments are the packed exp outputs)
#pragma unroll
            for (int kk = 0; kk < 4; ++kk) {
                uint32_t ph[4];
                ph[0] = pe0[2*kk];     ph[1] = pe1[2*kk];
                ph[2] = pe0[2*kk + 1]; ph[3] = pe1[2*kk + 1];
#pragma unroll
                for (int p = 0; p < 4; ++p) {
                    const uint32_t rb = (uint32_t)(p * 16 * FSTR) * 2 + kk * 32;
                    uint32_t v4[4];
                    ldsm4(v4, uV + rb + boff);
                    mma16816(o[2*p],   ph, v4 + 0);
                    mma16816(o[2*p+1], ph, v4 + 2);
                }
            }
        }
    }

    // finalize: write fp16 directly (feeds out-projection)
    l0 += __shfl_xor_sync(0xffffffffu, l0, 1);
    l0 += __shfl_xor_sync(0xffffffffu, l0, 2);
    l1 += __shfl_xor_sync(0xffffffffu, l1, 1);
    l1 += __shfl_xor_sync(0xffffffffu, l1, 2);
    const float inv0 = 1.f / l0, inv1 = 1.f / l1;

    const int r0 = qrow0 + g, r1 = r0 + 8;
#pragma unroll
    for (int ni = 0; ni < 8; ++ni) {
        const int col = h * HD + ni * 8 + tg * 2;
        *(__half2*)&g_ao[(size_t)(b * SEQ + r0) * DIM + col] =
            __floats2half2_rn(o[ni][0] * inv0, o[ni][1] * inv0);
        *(__half2*)&g_ao[(size_t)(b * SEQ + r1) * DIM + col] =
            __floats2half2_rn(o[ni][2] * inv1, o[ni][3] * inv1);
    }
}

// ---------------- launcher ---------------------------------------------------
extern "C" void kernel_launch(void* const* d_in, const int* in_sizes, int n_in,
                              void* d_out, int out_size)
{
    const float* x     = (const float*)d_in[0];   // [2,2048,2048]
    const float* fc    = (const float*)d_in[1];   // [2048,32,2]
    // d_in[2] = mask (causal, hardcoded)
    const float* wqkv  = (const float*)d_in[3];   // [3072,2048]
    const float* wo    = (const float*)d_in[4];   // [2048,2048]
    float* out = (float*)d_out;                   // [2,2048,2048]

    void *p_qkvh, *p_x, *p_wq, *p_ao, *p_wo;
    cudaGetSymbolAddress(&p_qkvh, g_qkvh);
    cudaGetSymbolAddress(&p_x,    g_x);
    cudaGetSymbolAddress(&p_wq,   g_wq);
    cudaGetSymbolAddress(&p_ao,   g_ao);
    cudaGetSymbolAddress(&p_wo,   g_wo);

    cudaFuncSetAttribute(gemm_hmma_kernel<true>,
                         cudaFuncAttributeMaxDynamicSharedMemorySize, GT_SMEM_BYTES);
    cudaFuncSetAttribute(gemm_hmma_kernel<false>,
                         cudaFuncAttributeMaxDynamicSharedMemorySize, GT_SMEM_BYTES);

    const int M = BSZ * SEQ;                      // 4096

    conv4h_kernel<<<(M * DIM / 4 + 255) / 256, 256>>>(x,
        (__half*)p_x, M * DIM / 4);
    conv4h_kernel<<<(QKV_N * DIM / 4 + 255) / 256, 256>>>(wqkv,
        (__half*)p_wq, QKV_N * DIM / 4);
    conv4h_kernel<<<(DIM * DIM / 4 + 255) / 256, 256>>>(wo,
        (__half*)p_wo, DIM * DIM / 4);

    // 1) QKV projection -> fp16
    gemm_hmma_kernel<true><<<dim3(QKV_N / 128, M / 128), 256, GT_SMEM_BYTES>>>(
        (const __half*)p_x, (const __half*)p_wq,
        p_qkvh, M, QKV_N, DIM);

    // 2) RoPE + V transpose
    rope_q_kernel<<<(BSZ * SEQ * NH  * 32) / 256, 256>>>(fc);
    rope_k_kernel<<<(BSZ * SEQ * NKV * 32) / 256, 256>>>(fc);
    split_v_kernel<<<dim3(SEQ / 32, HD / 32, BSZ * NKV), 256>>>();

    // 3) causal flash attention -> g_ao [b,s,h*d] (fp16)
    flash_hmma_kernel<<<dim3(SEQ / 128, NH, BSZ), 256>>>();

    // 4) output projection -> fp32
    gemm_hmma_kernel<false><<<dim3(DIM / 128, M / 128), 256, GT_SMEM_BYTES>>>(
        (const __half*)p_ao, (const __half*)p_wo,
        out, M, DIM, DIM);
}

// round 12
// speedup vs baseline: 7.0280x; 1.0168x over previous
#include <cuda_runtime.h>
#include <cuda_fp16.h>
#include <cstdint>
#include <cstddef>

#define BSZ 2
#define SEQ 2048
#define DIM 2048
#define NH 32
#define NKV 8
#define HD 64
#define QKV_N ((NH + 2*NKV)*HD)   // 3072

// ---------------- scratch (static device globals; no allocation) -----------
__device__ __half g_x  [(size_t)BSZ*SEQ*DIM];
__device__ __half g_wq [(size_t)QKV_N*DIM];
__device__ __half g_ao [(size_t)BSZ*SEQ*DIM];
__device__ __half g_wo [(size_t)DIM*DIM];

__device__ __half g_q  [(size_t)BSZ*NH *SEQ*HD];   // [b,h,s,d] (pre-scaled 1/8)
__device__ __half g_k  [(size_t)BSZ*NKV*SEQ*HD];   // [b,kv,s,d]
__device__ __half g_v  [(size_t)BSZ*NKV*HD*SEQ];   // [b,kv,d,s] transposed

// ---------------- small PTX helpers (sm_80-baseline ISA only) ---------------
__device__ __forceinline__ uint32_t smem_to_u32(const void* p) {
    uint32_t a;
    asm("{ .reg .u64 t; cvta.to.shared.u64 t, %1; cvt.u32.u64 %0, t; }"
        : "=r"(a) : "l"(p));
    return a;
}
__device__ __forceinline__ void cp_async16(uint32_t dst, const void* src) {
    asm volatile("cp.async.cg.shared.global [%0], [%1], 16;"
                 :: "r"(dst), "l"(src) : "memory");
}
#define CP_COMMIT() asm volatile("cp.async.commit_group;" ::: "memory")
#define CP_WAIT0()  asm volatile("cp.async.wait_group 0;" ::: "memory")

__device__ __forceinline__ void ldsm4(uint32_t* r, uint32_t addr) {
    asm volatile("ldmatrix.sync.aligned.m8n8.x4.shared.b16 {%0,%1,%2,%3}, [%4];"
        : "=r"(r[0]), "=r"(r[1]), "=r"(r[2]), "=r"(r[3]) : "r"(addr));
}

// D += A(16x16 fp16) * B(16x8 fp16), fp32 accum
__device__ __forceinline__ void mma16816(float* d, const uint32_t* a,
                                         const uint32_t* b) {
    asm volatile(
        "mma.sync.aligned.m16n8k16.row.col.f32.f16.f16.f32 "
        "{%0,%1,%2,%3}, {%4,%5,%6,%7}, {%8,%9}, {%0,%1,%2,%3};"
        : "+f"(d[0]), "+f"(d[1]), "+f"(d[2]), "+f"(d[3])
        : "r"(a[0]), "r"(a[1]), "r"(a[2]), "r"(a[3]), "r"(b[0]), "r"(b[1]));
}

// ---------------- conversion kernel ------------------------------------------
__global__ void conv4h_kernel(const float* __restrict__ src,
                              __half* __restrict__ dst, int n4)
{
    int i = blockIdx.x * 256 + threadIdx.x;
    if (i >= n4) return;
    float4 v = ((const float4*)src)[i];
    ((__half2*)dst)[2*i]   = __floats2half2_rn(v.x, v.y);
    ((__half2*)dst)[2*i+1] = __floats2half2_rn(v.z, v.w);
}

// ---------------- GEMM core (shared mainloop) --------------------------------
// K-chunk 64, 2-stage cp.async pipeline, 128x128 tiles, 8 warps.
#define GSTR 72
#define TILE_BYTES (128 * GSTR * 2)             // 18432
#define GT_SMEM_BYTES (2 * 2 * TILE_BYTES)      // 73728

struct GemmCtx {
    int wm, wn, lr, lc;
    float acc[4][4][4];
};

__device__ __forceinline__ void gemm_mainloop(
    GemmCtx& cx, const __half* A, const __half* B,
    uint32_t sbase, int bm, int bn, int K)
{
    const int t    = threadIdx.x;
    const int wid  = t >> 5, lane = t & 31;
    cx.wm = (wid & 1) * 64;
    cx.wn = (wid >> 1) * 32;
    cx.lr = lane >> 2;
    cx.lc = lane & 3;

    const int arow = (lane & 7) + ((lane >> 3) & 1) * 8;
    const int acol = (lane >> 4) * 8;
    const uint32_t aoff = (uint32_t)(arow * GSTR + acol) * 2;
    const int brow = (lane & 7) + ((lane >> 4) & 1) * 8;
    const int bcol = ((lane >> 3) & 1) * 8;
    const uint32_t boff = (uint32_t)(brow * GSTR + bcol) * 2;

#pragma unroll
    for (int mi = 0; mi < 4; ++mi)
#pragma unroll
        for (int ni = 0; ni < 4; ++ni)
#pragma unroll
            for (int q = 0; q < 4; ++q) cx.acc[mi][ni][q] = 0.f;

    const int nch = K / 64;

    auto load_chunk = [&](int buf, int kc) {
        const __half* gA = A + (size_t)bm * K + kc * 64;
        const __half* gB = B + (size_t)bn * K + kc * 64;
        const uint32_t sdA = sbase + buf * 2 * TILE_BYTES;
        const uint32_t sdB = sdA + TILE_BYTES;
#pragma unroll
        for (int i = 0; i < 4; ++i) {
            int c   = t + i * 256;
            int row = c >> 3, cc = c & 7;
            cp_async16(sdA + (uint32_t)(row * GSTR * 2) + cc * 16,
                       gA + (size_t)row * K + cc * 8);
            cp_async16(sdB + (uint32_t)(row * GSTR * 2) + cc * 16,
                       gB + (size_t)row * K + cc * 8);
        }
    };

    load_chunk(0, 0); CP_COMMIT();

    for (int c = 0; c < nch; ++c) {
        CP_WAIT0();
        __syncthreads();
        if (c + 1 < nch) { load_chunk((c + 1) & 1, c + 1); CP_COMMIT(); }

        const int buf = c & 1;
        const uint32_t uA = sbase + buf * 2 * TILE_BYTES;
        const uint32_t uB = uA + TILE_BYTES;

#pragma unroll
        for (int ks = 0; ks < 4; ++ks) {
            uint32_t a4[4][4], b4[2][4];
#pragma unroll
            for (int mi = 0; mi < 4; ++mi) {
                const uint32_t ra = (uint32_t)((cx.wm + mi * 16) * GSTR) * 2 + ks * 32;
                ldsm4(a4[mi], uA + ra + aoff);
            }
#pragma unroll
            for (int p = 0; p < 2; ++p) {
                const uint32_t rb = (uint32_t)((cx.wn + p * 16) * GSTR) * 2 + ks * 32;
                ldsm4(b4[p], uB + rb + boff);
            }
#pragma unroll
            for (int mi = 0; mi < 4; ++mi)
#pragma unroll
                for (int ni = 0; ni < 4; ++ni)
                    mma16816(cx.acc[mi][ni], a4[mi], &b4[ni >> 1][(ni & 1) * 2]);
        }
    }
}

// QKV GEMM with fused RoPE + Q/K/V scatter.
// Column tiles: bn in [0,2048) = Q (rope, scale 1/8), [2048,2560) = K (rope),
// [2560,3072) = V (transpose to [d,s]). Boundaries are multiples of 128.
__global__ __launch_bounds__(256, 2)
void gemm_qkv_kernel(const __half* __restrict__ A,
                     const __half* __restrict__ B,
                     const float* __restrict__ fc, int K)
{
    extern __shared__ __half sm[];
    const uint32_t sbase = smem_to_u32(sm);
    const int bm = blockIdx.y * 128, bn = blockIdx.x * 128;

    GemmCtx cx;
    gemm_mainloop(cx, A, B, sbase, bm, bn, K);

#pragma unroll
    for (int mi = 0; mi < 4; ++mi) {
        const int row = bm + cx.wm + mi * 16 + cx.lr;   // row and row+8
#pragma unroll
        for (int ni = 0; ni < 4; ++ni) {
            const int col = bn + cx.wn + ni * 8 + cx.lc * 2;
            const float* a = cx.acc[mi][ni];
            if (bn < DIM) {
                // Q: rope + 1/8 scale -> g_q[b,h,s,d]
                const int h = col >> 6, d = col & 63;
#pragma unroll
                for (int rh = 0; rh < 2; ++rh) {
                    const int r = row + rh * 8;
                    const int s = r & (SEQ - 1), b = r >> 11;
                    float2 cs = *(const float2*)&fc[s * HD + d];
                    float v0 = (a[rh*2+0] * cs.x - a[rh*2+1] * cs.y) * 0.125f;
                    float v1 = (a[rh*2+1] * cs.x + a[rh*2+0] * cs.y) * 0.125f;
                    *(__half2*)&g_q[(((size_t)(b*NH+h))*SEQ + s)*HD + d] =
                        __floats2half2_rn(v0, v1);
                }
            } else if (bn < DIM + NKV * HD) {
                // K: rope -> g_k[b,kv,s,d]
                const int c2 = col - DIM;
                const int kv = c2 >> 6, d = c2 & 63;
#pragma unroll
                for (int rh = 0; rh < 2; ++rh) {
                    const int r = row + rh * 8;
                    const int s = r & (SEQ - 1), b = r >> 11;
                    float2 cs = *(const float2*)&fc[s * HD + d];
                    float v0 = a[rh*2+0] * cs.x - a[rh*2+1] * cs.y;
                    float v1 = a[rh*2+1] * cs.x + a[rh*2+0] * cs.y;
                    *(__half2*)&g_k[(((size_t)(b*NKV+kv))*SEQ + s)*HD + d] =
                        __floats2half2_rn(v0, v1);
                }
            } else {
                // V: transpose -> g_v[b,kv,d,s]
                const int c2 = col - DIM - NKV * HD;
                const int kv = c2 >> 6, d = c2 & 63;
#pragma unroll
                for (int rh = 0; rh < 2; ++rh) {
                    const int r = row + rh * 8;
                    const int s = r & (SEQ - 1), b = r >> 11;
                    const size_t base = ((size_t)(b*NKV+kv))*HD*SEQ + s;
                    g_v[base + (size_t)d * SEQ]       = __float2half_rn(a[rh*2+0]);
                    g_v[base + (size_t)(d+1) * SEQ]   = __float2half_rn(a[rh*2+1]);
                }
            }
        }
    }
}

// Generic GEMM: C fp32 = A[M,K] * B[N,K]^T (out-projection)
__global__ __launch_bounds__(256, 2)
void gemm_hmma_kernel(const __half* __restrict__ A,
                      const __half* __restrict__ B,
                      float* __restrict__ C, int M, int N, int K)
{
    extern __shared__ __half sm[];
    const uint32_t sbase = smem_to_u32(sm);
    const int bm = blockIdx.y * 128, bn = blockIdx.x * 128;

    GemmCtx cx;
    gemm_mainloop(cx, A, B, sbase, bm, bn, K);

#pragma unroll
    for (int mi = 0; mi < 4; ++mi) {
        const int row = bm + cx.wm + mi * 16 + cx.lr;
#pragma unroll
        for (int ni = 0; ni < 4; ++ni) {
            const int col = bn + cx.wn + ni * 8 + cx.lc * 2;
            *(float2*)&C[(size_t)row * N + col] =
                make_float2(cx.acc[mi][ni][0], cx.acc[mi][ni][1]);
            *(float2*)&C[(size_t)(row + 8) * N + col] =
                make_float2(cx.acc[mi][ni][2], cx.acc[mi][ni][3]);
        }
    }
}

// ---------------- flash attention on HMMA ------------------------------------
// Block: 128 q rows (8 warps x 16), KV tile 64. fp16 P via ex2.approx.f16x2.
#define FSTR 72
#define FTILE_BYTES (64 * FSTR * 2)   // 9216

__global__ __launch_bounds__(256, 2)
void flash_hmma_kernel()
{
    __shared__ __half sK[2][64 * FSTR];
    __shared__ __half sV[2][64 * FSTR];   // [d][key]

    const int t = threadIdx.x;
    const int w = t >> 5, lane = t & 31;
    const int g = lane >> 2, tg = lane & 3;
    const int qb = blockIdx.x, h = blockIdx.y, b = blockIdx.z;
    const int kvh = h >> 2;
    const int qrow0 = qb * 128 + w * 16;

    const uint32_t uK0 = smem_to_u32(sK);
    const uint32_t uV0 = smem_to_u32(sV);

    const int brow = (lane & 7) + ((lane >> 4) & 1) * 8;
    const int bcol = ((lane >> 3) & 1) * 8;
    const uint32_t boff = (uint32_t)(brow * FSTR + bcol) * 2;

    // Q fragments, 4 k-chunks of 16 over d=64
    uint32_t qf[4][4];
    {
        const __half* gq = g_q + (((size_t)(b*NH+h))*SEQ + qrow0)*HD;
#pragma unroll
        for (int kk = 0; kk < 4; ++kk) {
            int d0 = kk * 16 + tg * 2;
            qf[kk][0] = *(const uint32_t*)&gq[(size_t)(g    ) * HD + d0];
            qf[kk][1] = *(const uint32_t*)&gq[(size_t)(g + 8) * HD + d0];
            qf[kk][2] = *(const uint32_t*)&gq[(size_t)(g    ) * HD + d0 + 8];
            qf[kk][3] = *(const uint32_t*)&gq[(size_t)(g + 8) * HD + d0 + 8];
        }
    }

    float m0 = -1e30f, m1 = -1e30f, l0 = 0.f, l1 = 0.f;
    float o[8][4];
#pragma unroll
    for (int ni = 0; ni < 8; ++ni)
#pragma unroll
        for (int q = 0; q < 4; ++q) o[ni][q] = 0.f;

    const __half* gk = g_k + ((size_t)(b * NKV + kvh)) * SEQ * HD;
    const __half* gv = g_v + ((size_t)(b * NKV + kvh)) * HD * SEQ;

    auto load_tile = [&](int buf, int jb) {
#pragma unroll
        for (int cc = 0; cc < 2; ++cc) {
            int c   = t + cc * 256;
            int row = c >> 3, col = (c & 7) * 8;
            uint32_t so = (uint32_t)buf * FTILE_BYTES + (uint32_t)(row * FSTR + col) * 2;
            cp_async16(uK0 + so, &gk[(size_t)(jb * 64 + row) * HD + col]);
            cp_async16(uV0 + so, &gv[(size_t)row * SEQ + jb * 64 + col]);
        }
    };

    const float L2E = 1.4426950408889634f;
    const int ntile = 2 * qb + 2;
    load_tile(0, 0); CP_COMMIT();

    for (int jb = 0; jb < ntile; ++jb) {
        const int buf = jb & 1;
        CP_WAIT0();
        __syncthreads();
        if (jb + 1 < ntile) { load_tile(buf ^ 1, jb + 1); CP_COMMIT(); }

        if (jb * 64 <= qrow0 + 15) {
            const uint32_t uK = uK0 + buf * FTILE_BYTES;
            const uint32_t uV = uV0 + buf * FTILE_BYTES;

            // S = Q K^T
            float s[8][4];
#pragma unroll
            for (int ni = 0; ni < 8; ++ni)
                s[ni][0] = s[ni][1] = s[ni][2] = s[ni][3] = 0.f;

#pragma unroll
            for (int kk = 0; kk < 4; ++kk)
#pragma unroll
                for (int p = 0; p < 4; ++p) {
                    const uint32_t rb = (uint32_t)(p * 16 * FSTR) * 2 + kk * 32;
                    uint32_t k4[4];
                    ldsm4(k4, uK + rb + boff);
                    mma16816(s[2*p],   qf[kk], k4 + 0);
                    mma16816(s[2*p+1], qf[kk], k4 + 2);
                }

            // causal mask (diagonal tiles only)
            if (jb * 64 + 63 > qrow0) {
                const int cb = jb * 64 + tg * 2;
                const int r0 = qrow0 + g, r1 = r0 + 8;
#pragma unroll
                for (int ni = 0; ni < 8; ++ni) {
                    int c0 = cb + ni * 8, c1 = c0 + 1;
                    if (c0 > r0) s[ni][0] = -1e30f;
                    if (c1 > r0) s[ni][1] = -1e30f;
                    if (c0 > r1) s[ni][2] = -1e30f;
                    if (c1 > r1) s[ni][3] = -1e30f;
                }
            }

            // online softmax: max in fp32, exp via ex2.approx.f16x2
            float mt0 = -1e30f, mt1 = -1e30f;
#pragma unroll
            for (int ni = 0; ni < 8; ++ni) {
                mt0 = fmaxf(mt0, fmaxf(s[ni][0], s[ni][1]));
                mt1 = fmaxf(mt1, fmaxf(s[ni][2], s[ni][3]));
            }
            mt0 = fmaxf(mt0, __shfl_xor_sync(0xffffffffu, mt0, 1));
            mt0 = fmaxf(mt0, __shfl_xor_sync(0xffffffffu, mt0, 2));
            mt1 = fmaxf(mt1, __shfl_xor_sync(0xffffffffu, mt1, 1));
            mt1 = fmaxf(mt1, __shfl_xor_sync(0xffffffffu, mt1, 2));
            float mn0 = fmaxf(m0, mt0), mn1 = fmaxf(m1, mt1);
            float a0 = __expf(m0 - mn0), a1 = __expf(m1 - mn1);
            m0 = mn0; m1 = mn1;
            const float b0 = mn0 * L2E, b1 = mn1 * L2E;

            uint32_t pe0[8], pe1[8];        // fp16x2 P: rows g / g+8
            float rs0 = 0.f, rs1 = 0.f;
#pragma unroll
            for (int ni = 0; ni < 8; ++ni) {
                __half2 e01 = h2exp2(__floats2half2_rn(
                    fmaf(s[ni][0], L2E, -b0), fmaf(s[ni][1], L2E, -b0)));
                __half2 e23 = h2exp2(__floats2half2_rn(
                    fmaf(s[ni][2], L2E, -b1), fmaf(s[ni][3], L2E, -b1)));
                pe0[ni] = *(uint32_t*)&e01;
                pe1[ni] = *(uint32_t*)&e23;
                float2 f01 = __half22float2(e01);
                float2 f23 = __half22float2(e23);
                rs0 += f01.x + f01.y;
                rs1 += f23.x + f23.y;
            }
            l0 = l0 * a0 + rs0;
            l1 = l1 * a1 + rs1;
#pragma unroll
            for (int ni = 0; ni < 8; ++ni) {
                o[ni][0] *= a0; o[ni][1] *= a0;
                o[ni][2] *= a1; o[ni][3] *= a1;
            }

            // O += P V (P fragments are the packed exp outputs)
#pragma unroll
            for (int kk = 0; kk < 4; ++kk) {
                uint32_t ph[4];
                ph[0] = pe0[2*kk];     ph[1] = pe1[2*kk];
                ph[2] = pe0[2*kk + 1]; ph[3] = pe1[2*kk + 1];
#pragma unroll
                for (int p = 0; p < 4; ++p) {
                    const uint32_t rb = (uint32_t)(p * 16 * FSTR) * 2 + kk * 32;
                    uint32_t v4[4];
                    ldsm4(v4, uV + rb + boff);
                    mma16816(o[2*p],   ph, v4 + 0);
                    mma16816(o[2*p+1], ph, v4 + 2);
                }
            }
        }
    }

    // finalize: write fp16 directly (feeds out-projection)
    l0 += __shfl_xor_sync(0xffffffffu, l0, 1);
    l0 += __shfl_xor_sync(0xffffffffu, l0, 2);
    l1 += __shfl_xor_sync(0xffffffffu, l1, 1);
    l1 += __shfl_xor_sync(0xffffffffu, l1, 2);
    const float inv0 = 1.f / l0, inv1 = 1.f / l1;

    const int r0 = qrow0 + g, r1 = r0 + 8;
#pragma unroll
    for (int ni = 0; ni < 8; ++ni) {
        const int col = h * HD + ni * 8 + tg * 2;
        *(__half2*)&g_ao[(size_t)(b * SEQ + r0) * DIM + col] =
            __floats2half2_rn(o[ni][0] * inv0, o[ni][1] * inv0);
        *(__half2*)&g_ao[(size_t)(b * SEQ + r1) * DIM + col] =
            __floats2half2_rn(o[ni][2] * inv1, o[ni][3] * inv1);
    }
}

// ---------------- launcher ---------------------------------------------------
extern "C" void kernel_launch(void* const* d_in, const int* in_sizes, int n_in,
                              void* d_out, int out_size)
{
    const float* x     = (const float*)d_in[0];   // [2,2048,2048]
    const float* fc    = (const float*)d_in[1];   // [2048,32,2]
    // d_in[2] = mask (causal, hardcoded)
    const float* wqkv  = (const float*)d_in[3];   // [3072,2048]
    const float* wo    = (const float*)d_in[4];   // [2048,2048]
    float* out = (float*)d_out;                   // [2,2048,2048]

    void *p_x, *p_wq, *p_ao, *p_wo;
    cudaGetSymbolAddress(&p_x,  g_x);
    cudaGetSymbolAddress(&p_wq, g_wq);
    cudaGetSymbolAddress(&p_ao, g_ao);
    cudaGetSymbolAddress(&p_wo, g_wo);

    cudaFuncSetAttribute(gemm_qkv_kernel,
                         cudaFuncAttributeMaxDynamicSharedMemorySize, GT_SMEM_BYTES);
    cudaFuncSetAttribute(gemm_hmma_kernel,
                         cudaFuncAttributeMaxDynamicSharedMemorySize, GT_SMEM_BYTES);

    const int M = BSZ * SEQ;                      // 4096

    conv4h_kernel<<<(M * DIM / 4 + 255) / 256, 256>>>(x,
        (__half*)p_x, M * DIM / 4);
    conv4h_kernel<<<(QKV_N * DIM / 4 + 255) / 256, 256>>>(wqkv,
        (__half*)p_wq, QKV_N * DIM / 4);
    conv4h_kernel<<<(DIM * DIM / 4 + 255) / 256, 256>>>(wo,
        (__half*)p_wo, DIM * DIM / 4);

    // 1) QKV projection with fused RoPE + scatter -> g_q / g_k / g_v
    gemm_qkv_kernel<<<dim3(QKV_N / 128, M / 128), 256, GT_SMEM_BYTES>>>(
        (const __half*)p_x, (const __half*)p_wq, fc, DIM);

    // 2) causal flash attention -> g_ao [b,s,h*d] (fp16)
    flash_hmma_kernel<<<dim3(SEQ / 128, NH, BSZ), 256>>>();

    // 3) output projection -> fp32
    gemm_hmma_kernel<<<dim3(DIM / 128, M / 128), 256, GT_SMEM_BYTES>>>(
        (const __half*)p_ao, (const __half*)p_wo,
        out, M, DIM, DIM);
}

// round 13
// speedup vs baseline: 7.1322x; 1.0148x over previous
#include <cuda_runtime.h>
#include <cuda_fp16.h>
#include <cstdint>
#include <cstddef>

#define BSZ 2
#define SEQ 2048
#define DIM 2048
#define NH 32
#define NKV 8
#define HD 64
#define QKV_N ((NH + 2*NKV)*HD)   // 3072

// ---------------- scratch (static device globals; no allocation) -----------
__device__ __half g_x  [(size_t)BSZ*SEQ*DIM];
__device__ __half g_wq [(size_t)QKV_N*DIM];
__device__ __half g_ao [(size_t)BSZ*SEQ*DIM];
__device__ __half g_wo [(size_t)DIM*DIM];

__device__ __half g_q  [(size_t)BSZ*NH *SEQ*HD];   // [b,h,s,d] (pre-scaled 1/8)
__device__ __half g_k  [(size_t)BSZ*NKV*SEQ*HD];   // [b,kv,s,d]
__device__ __half g_v  [(size_t)BSZ*NKV*HD*SEQ];   // [b,kv,d,s] transposed

// ---------------- small PTX helpers (sm_80-baseline ISA only) ---------------
__device__ __forceinline__ uint32_t smem_to_u32(const void* p) {
    uint32_t a;
    asm("{ .reg .u64 t; cvta.to.shared.u64 t, %1; cvt.u32.u64 %0, t; }"
        : "=r"(a) : "l"(p));
    return a;
}
__device__ __forceinline__ void cp_async16(uint32_t dst, const void* src) {
    asm volatile("cp.async.cg.shared.global [%0], [%1], 16;"
                 :: "r"(dst), "l"(src) : "memory");
}
#define CP_COMMIT() asm volatile("cp.async.commit_group;" ::: "memory")
#define CP_WAIT0()  asm volatile("cp.async.wait_group 0;" ::: "memory")

__device__ __forceinline__ void ldsm4(uint32_t* r, uint32_t addr) {
    asm volatile("ldmatrix.sync.aligned.m8n8.x4.shared.b16 {%0,%1,%2,%3}, [%4];"
        : "=r"(r[0]), "=r"(r[1]), "=r"(r[2]), "=r"(r[3]) : "r"(addr));
}

// D += A(16x16 fp16) * B(16x8 fp16), fp32 accum
__device__ __forceinline__ void mma16816(float* d, const uint32_t* a,
                                         const uint32_t* b) {
    asm volatile(
        "mma.sync.aligned.m16n8k16.row.col.f32.f16.f16.f32 "
        "{%0,%1,%2,%3}, {%4,%5,%6,%7}, {%8,%9}, {%0,%1,%2,%3};"
        : "+f"(d[0]), "+f"(d[1]), "+f"(d[2]), "+f"(d[3])
        : "r"(a[0]), "r"(a[1]), "r"(a[2]), "r"(a[3]), "r"(b[0]), "r"(b[1]));
}

// ---------------- fused conversion kernel (x, wqkv, wo in one launch) --------
#define CN1 (BSZ*SEQ*DIM/4)        // 2097152
#define CN2 (QKV_N*DIM/4)          // 1572864
#define CN3 (DIM*DIM/4)            // 1048576

__global__ void conv_all_kernel(const float* __restrict__ x,
                                const float* __restrict__ wq,
                                const float* __restrict__ wo)
{
    int i = blockIdx.x * 256 + threadIdx.x;
    const float* src;
    __half* dst;
    int j;
    if (i < CN1)              { src = x;  dst = g_x;  j = i; }
    else if (i < CN1 + CN2)   { src = wq; dst = g_wq; j = i - CN1; }
    else                      { src = wo; dst = g_wo; j = i - CN1 - CN2; }
    float4 v = ((const float4*)src)[j];
    ((__half2*)dst)[2*j]   = __floats2half2_rn(v.x, v.y);
    ((__half2*)dst)[2*j+1] = __floats2half2_rn(v.z, v.w);
}

// ---------------- GEMM core (shared mainloop) --------------------------------
// K-chunk 64, 2-stage cp.async pipeline, 128x128 tiles, 8 warps.
#define GSTR 72
#define TILE_BYTES (128 * GSTR * 2)             // 18432
#define GT_SMEM_BYTES (2 * 2 * TILE_BYTES)      // 73728

struct GemmCtx {
    int wm, wn, lr, lc;
    float acc[4][4][4];
};

__device__ __forceinline__ void gemm_mainloop(
    GemmCtx& cx, const __half* A, const __half* B,
    uint32_t sbase, int bm, int bn, int K)
{
    const int t    = threadIdx.x;
    const int wid  = t >> 5, lane = t & 31;
    cx.wm = (wid & 1) * 64;
    cx.wn = (wid >> 1) * 32;
    cx.lr = lane >> 2;
    cx.lc = lane & 3;

    const int arow = (lane & 7) + ((lane >> 3) & 1) * 8;
    const int acol = (lane >> 4) * 8;
    const uint32_t aoff = (uint32_t)(arow * GSTR + acol) * 2;
    const int brow = (lane & 7) + ((lane >> 4) & 1) * 8;
    const int bcol = ((lane >> 3) & 1) * 8;
    const uint32_t boff = (uint32_t)(brow * GSTR + bcol) * 2;

#pragma unroll
    for (int mi = 0; mi < 4; ++mi)
#pragma unroll
        for (int ni = 0; ni < 4; ++ni)
#pragma unroll
            for (int q = 0; q < 4; ++q) cx.acc[mi][ni][q] = 0.f;

    const int nch = K / 64;

    auto load_chunk = [&](int buf, int kc) {
        const __half* gA = A + (size_t)bm * K + kc * 64;
        const __half* gB = B + (size_t)bn * K + kc * 64;
        const uint32_t sdA = sbase + buf * 2 * TILE_BYTES;
        const uint32_t sdB = sdA + TILE_BYTES;
#pragma unroll
        for (int i = 0; i < 4; ++i) {
            int c   = t + i * 256;
            int row = c >> 3, cc = c & 7;
            cp_async16(sdA + (uint32_t)(row * GSTR * 2) + cc * 16,
                       gA + (size_t)row * K + cc * 8);
            cp_async16(sdB + (uint32_t)(row * GSTR * 2) + cc * 16,
                       gB + (size_t)row * K + cc * 8);
        }
    };

    load_chunk(0, 0); CP_COMMIT();

    for (int c = 0; c < nch; ++c) {
        CP_WAIT0();
        __syncthreads();
        if (c + 1 < nch) { load_chunk((c + 1) & 1, c + 1); CP_COMMIT(); }

        const int buf = c & 1;
        const uint32_t uA = sbase + buf * 2 * TILE_BYTES;
        const uint32_t uB = uA + TILE_BYTES;

#pragma unroll
        for (int ks = 0; ks < 4; ++ks) {
            uint32_t a4[4][4], b4[2][4];
#pragma unroll
            for (int mi = 0; mi < 4; ++mi) {
                const uint32_t ra = (uint32_t)((cx.wm + mi * 16) * GSTR) * 2 + ks * 32;
                ldsm4(a4[mi], uA + ra + aoff);
            }
#pragma unroll
            for (int p = 0; p < 2; ++p) {
                const uint32_t rb = (uint32_t)((cx.wn + p * 16) * GSTR) * 2 + ks * 32;
                ldsm4(b4[p], uB + rb + boff);
            }
#pragma unroll
            for (int mi = 0; mi < 4; ++mi)
#pragma unroll
                for (int ni = 0; ni < 4; ++ni)
                    mma16816(cx.acc[mi][ni], a4[mi], &b4[ni >> 1][(ni & 1) * 2]);
        }
    }
}

// QKV GEMM with fused RoPE + Q/K/V scatter.
// Column tiles: bn in [0,2048) = Q (rope, scale 1/8), [2048,2560) = K (rope),
// [2560,3072) = V (transpose to [d,s] via smem staging).
__global__ __launch_bounds__(256, 2)
void gemm_qkv_kernel(const __half* __restrict__ A,
                     const __half* __restrict__ B,
                     const float* __restrict__ fc, int K)
{
    extern __shared__ __half sm[];
    const uint32_t sbase = smem_to_u32(sm);
    const int bm = blockIdx.y * 128, bn = blockIdx.x * 128;
    const int t  = threadIdx.x;

    GemmCtx cx;
    gemm_mainloop(cx, A, B, sbase, bm, bn, K);

    if (bn >= DIM + NKV * HD) {
        // ---- V: stage acc into smem as [d][s], then coalesced store ----
        __syncthreads();   // mainloop smem reads complete in all warps
#pragma unroll
        for (int mi = 0; mi < 4; ++mi) {
#pragma unroll
            for (int ni = 0; ni < 4; ++ni) {
                const int d = cx.wn + ni * 8 + cx.lc * 2;
                const float* a = cx.acc[mi][ni];
#pragma unroll
                for (int rh = 0; rh < 2; ++rh) {
                    const int s = cx.wm + mi * 16 + cx.lr + rh * 8;
                    sm[(d    ) * 136 + s] = __float2half_rn(a[rh*2+0]);
                    sm[(d + 1) * 136 + s] = __float2half_rn(a[rh*2+1]);
                }
            }
        }
        __syncthreads();
        const int c2b = bn - DIM - NKV * HD;
        const int b = bm >> 11;
        const int s0 = bm & (SEQ - 1);
#pragma unroll
        for (int it = 0; it < 8; ++it) {
            int idx = t + it * 256;          // 2048 = 128 d x 16 chunks
            int d  = idx >> 4, sc = (idx & 15) * 8;
            int kv = (c2b + d) >> 6, dd = (c2b + d) & 63;
            uint4 val = *(const uint4*)&sm[d * 136 + sc];
            *(uint4*)&g_v[(((size_t)(b * NKV + kv)) * HD + dd) * SEQ + s0 + sc] = val;
        }
        return;
    }

#pragma unroll
    for (int mi = 0; mi < 4; ++mi) {
        const int row = bm + cx.wm + mi * 16 + cx.lr;   // row and row+8
#pragma unroll
        for (int ni = 0; ni < 4; ++ni) {
            const int col = bn + cx.wn + ni * 8 + cx.lc * 2;
            const float* a = cx.acc[mi][ni];
            if (bn < DIM) {
                // Q: rope + 1/8 scale -> g_q[b,h,s,d]
                const int h = col >> 6, d = col & 63;
#pragma unroll
                for (int rh = 0; rh < 2; ++rh) {
                    const int r = row + rh * 8;
                    const int s = r & (SEQ - 1), b = r >> 11;
                    float2 cs = *(const float2*)&fc[s * HD + d];
                    float v0 = (a[rh*2+0] * cs.x - a[rh*2+1] * cs.y) * 0.125f;
                    float v1 = (a[rh*2+1] * cs.x + a[rh*2+0] * cs.y) * 0.125f;
                    *(__half2*)&g_q[(((size_t)(b*NH+h))*SEQ + s)*HD + d] =
                        __floats2half2_rn(v0, v1);
                }
            } else {
                // K: rope -> g_k[b,kv,s,d]
                const int c2 = col - DIM;
                const int kv = c2 >> 6, d = c2 & 63;
#pragma unroll
                for (int rh = 0; rh < 2; ++rh) {
                    const int r = row + rh * 8;
                    const int s = r & (SEQ - 1), b = r >> 11;
                    float2 cs = *(const float2*)&fc[s * HD + d];
                    float v0 = a[rh*2+0] * cs.x - a[rh*2+1] * cs.y;
                    float v1 = a[rh*2+1] * cs.x + a[rh*2+0] * cs.y;
                    *(__half2*)&g_k[(((size_t)(b*NKV+kv))*SEQ + s)*HD + d] =
                        __floats2half2_rn(v0, v1);
                }
            }
        }
    }
}

// Generic GEMM: C fp32 = A[M,K] * B[N,K]^T (out-projection)
__global__ __launch_bounds__(256, 2)
void gemm_hmma_kernel(const __half* __restrict__ A,
                      const __half* __restrict__ B,
                      float* __restrict__ C, int M, int N, int K)
{
    extern __shared__ __half sm[];
    const uint32_t sbase = smem_to_u32(sm);
    const int bm = blockIdx.y * 128, bn = blockIdx.x * 128;

    GemmCtx cx;
    gemm_mainloop(cx, A, B, sbase, bm, bn, K);

#pragma unroll
    for (int mi = 0; mi < 4; ++mi) {
        const int row = bm + cx.wm + mi * 16 + cx.lr;
#pragma unroll
        for (int ni = 0; ni < 4; ++ni) {
            const int col = bn + cx.wn + ni * 8 + cx.lc * 2;
            *(float2*)&C[(size_t)row * N + col] =
                make_float2(cx.acc[mi][ni][0], cx.acc[mi][ni][1]);
            *(float2*)&C[(size_t)(row + 8) * N + col] =
                make_float2(cx.acc[mi][ni][2], cx.acc[mi][ni][3]);
        }
    }
}

// ---------------- flash attention on HMMA ------------------------------------
// Block: 128 q rows (8 warps x 16), KV tile 64. fp16 P via ex2.approx.f16x2.
#define FSTR 72
#define FTILE_BYTES (64 * FSTR * 2)   // 9216

__global__ __launch_bounds__(256, 2)
void flash_hmma_kernel()
{
    __shared__ __half sK[2][64 * FSTR];
    __shared__ __half sV[2][64 * FSTR];   // [d][key]

    const int t = threadIdx.x;
    const int w = t >> 5, lane = t & 31;
    const int g = lane >> 2, tg = lane & 3;
    const int qb = blockIdx.x, h = blockIdx.y, b = blockIdx.z;
    const int kvh = h >> 2;
    const int qrow0 = qb * 128 + w * 16;

    const uint32_t uK0 = smem_to_u32(sK);
    const uint32_t uV0 = smem_to_u32(sV);

    const int brow = (lane & 7) + ((lane >> 4) & 1) * 8;
    const int bcol = ((lane >> 3) & 1) * 8;
    const uint32_t boff = (uint32_t)(brow * FSTR + bcol) * 2;

    // Q fragments, 4 k-chunks of 16 over d=64
    uint32_t qf[4][4];
    {
        const __half* gq = g_q + (((size_t)(b*NH+h))*SEQ + qrow0)*HD;
#pragma unroll
        for (int kk = 0; kk < 4; ++kk) {
            int d0 = kk * 16 + tg * 2;
            qf[kk][0] = *(const uint32_t*)&gq[(size_t)(g    ) * HD + d0];
            qf[kk][1] = *(const uint32_t*)&gq[(size_t)(g + 8) * HD + d0];
            qf[kk][2] = *(const uint32_t*)&gq[(size_t)(g    ) * HD + d0 + 8];
            qf[kk][3] = *(const uint32_t*)&gq[(size_t)(g + 8) * HD + d0 + 8];
        }
    }

    float m0 = -1e30f, m1 = -1e30f, l0 = 0.f, l1 = 0.f;
    float o[8][4];
#pragma unroll
    for (int ni = 0; ni < 8; ++ni)
#pragma unroll
        for (int q = 0; q < 4; ++q) o[ni][q] = 0.f;

    const __half* gk = g_k + ((size_t)(b * NKV + kvh)) * SEQ * HD;
    const __half* gv = g_v + ((size_t)(b * NKV + kvh)) * HD * SEQ;

    auto load_tile = [&](int buf, int jb) {
#pragma unroll
        for (int cc = 0; cc < 2; ++cc) {
            int c   = t + cc * 256;
            int row = c >> 3, col = (c & 7) * 8;
            uint32_t so = (uint32_t)buf * FTILE_BYTES + (uint32_t)(row * FSTR + col) * 2;
            cp_async16(uK0 + so, &gk[(size_t)(jb * 64 + row) * HD + col]);
            cp_async16(uV0 + so, &gv[(size_t)row * SEQ + jb * 64 + col]);
        }
    };

    const float L2E = 1.4426950408889634f;
    const int ntile = 2 * qb + 2;
    load_tile(0, 0); CP_COMMIT();

    for (int jb = 0; jb < ntile; ++jb) {
        const int buf = jb & 1;
        CP_WAIT0();
        __syncthreads();
        if (jb + 1 < ntile) { load_tile(buf ^ 1, jb + 1); CP_COMMIT(); }

        if (jb * 64 <= qrow0 + 15) {
            const uint32_t uK = uK0 + buf * FTILE_BYTES;
            const uint32_t uV = uV0 + buf * FTILE_BYTES;

            // S = Q K^T
            float s[8][4];
#pragma unroll
            for (int ni = 0; ni < 8; ++ni)
                s[ni][0] = s[ni][1] = s[ni][2] = s[ni][3] = 0.f;

#pragma unroll
            for (int kk = 0; kk < 4; ++kk)
#pragma unroll
                for (int p = 0; p < 4; ++p) {
                    const uint32_t rb = (uint32_t)(p * 16 * FSTR) * 2 + kk * 32;
                    uint32_t k4[4];
                    ldsm4(k4, uK + rb + boff);
                    mma16816(s[2*p],   qf[kk], k4 + 0);
                    mma16816(s[2*p+1], qf[kk], k4 + 2);
                }

            // causal mask (diagonal tiles only)
            if (jb * 64 + 63 > qrow0) {
                const int cb = jb * 64 + tg * 2;
                const int r0 = qrow0 + g, r1 = r0 + 8;
#pragma unroll
                for (int ni = 0; ni < 8; ++ni) {
                    int c0 = cb + ni * 8, c1 = c0 + 1;
                    if (c0 > r0) s[ni][0] = -1e30f;
                    if (c1 > r0) s[ni][1] = -1e30f;
                    if (c0 > r1) s[ni][2] = -1e30f;
                    if (c1 > r1) s[ni][3] = -1e30f;
                }
            }

            // online softmax: max in fp32, exp via ex2.approx.f16x2
            float mt0 = -1e30f, mt1 = -1e30f;
#pragma unroll
            for (int ni = 0; ni < 8; ++ni) {
                mt0 = fmaxf(mt0, fmaxf(s[ni][0], s[ni][1]));
                mt1 = fmaxf(mt1, fmaxf(s[ni][2], s[ni][3]));
            }
            mt0 = fmaxf(mt0, __shfl_xor_sync(0xffffffffu, mt0, 1));
            mt0 = fmaxf(mt0, __shfl_xor_sync(0xffffffffu, mt0, 2));
            mt1 = fmaxf(mt1, __shfl_xor_sync(0xffffffffu, mt1, 1));
            mt1 = fmaxf(mt1, __shfl_xor_sync(0xffffffffu, mt1, 2));
            float mn0 = fmaxf(m0, mt0), mn1 = fmaxf(m1, mt1);
            float a0 = __expf(m0 - mn0), a1 = __expf(m1 - mn1);
            m0 = mn0; m1 = mn1;
            const float b0 = mn0 * L2E, b1 = mn1 * L2E;

            uint32_t pe0[8], pe1[8];        // fp16x2 P: rows g / g+8
            float rs0 = 0.f, rs1 = 0.f;
#pragma unroll
            for (int ni = 0; ni < 8; ++ni) {
                __half2 e01 = h2exp2(__floats2half2_rn(
                    fmaf(s[ni][0], L2E, -b0), fmaf(s[ni][1], L2E, -b0)));
                __half2 e23 = h2exp2(__floats2half2_rn(
                    fmaf(s[ni][2], L2E, -b1), fmaf(s[ni][3], L2E, -b1)));
                pe0[ni] = *(uint32_t*)&e01;
                pe1[ni] = *(uint32_t*)&e23;
                float2 f01 = __half22float2(e01);
                float2 f23 = __half22float2(e23);
                rs0 += f01.x + f01.y;
                rs1 += f23.x + f23.y;
            }
            l0 = l0 * a0 + rs0;
            l1 = l1 * a1 + rs1;
#pragma unroll
            for (int ni = 0; ni < 8; ++ni) {
                o[ni][0] *= a0; o[ni][1] *= a0;
                o[ni][2] *= a1; o[ni][3] *= a1;
            }

            // O += P V (P fragments are the packed exp outputs)
#pragma unroll
            for (int kk = 0; kk < 4; ++kk) {
                uint32_t ph[4];
                ph[0] = pe0[2*kk];     ph[1] = pe1[2*kk];
                ph[2] = pe0[2*kk + 1]; ph[3] = pe1[2*kk + 1];
#pragma unroll
                for (int p = 0; p < 4; ++p) {
                    const uint32_t rb = (uint32_t)(p * 16 * FSTR) * 2 + kk * 32;
                    uint32_t v4[4];
                    ldsm4(v4, uV + rb + boff);
                    mma16816(o[2*p],   ph, v4 + 0);
                    mma16816(o[2*p+1], ph, v4 + 2);
                }
            }
        }
    }

    // finalize: write fp16 directly (feeds out-projection)
    l0 += __shfl_xor_sync(0xffffffffu, l0, 1);
    l0 += __shfl_xor_sync(0xffffffffu, l0, 2);
    l1 += __shfl_xor_sync(0xffffffffu, l1, 1);
    l1 += __shfl_xor_sync(0xffffffffu, l1, 2);
    const float inv0 = 1.f / l0, inv1 = 1.f / l1;

    const int r0 = qrow0 + g, r1 = r0 + 8;
#pragma unroll
    for (int ni = 0; ni < 8; ++ni) {
        const int col = h * HD + ni * 8 + tg * 2;
        *(__half2*)&g_ao[(size_t)(b * SEQ + r0) * DIM + col] =
            __floats2half2_rn(o[ni][0] * inv0, o[ni][1] * inv0);
        *(__half2*)&g_ao[(size_t)(b * SEQ + r1) * DIM + col] =
            __floats2half2_rn(o[ni][2] * inv1, o[ni][3] * inv1);
    }
}

// ---------------- launcher ---------------------------------------------------
extern "C" void kernel_launch(void* const* d_in, const int* in_sizes, int n_in,
                              void* d_out, int out_size)
{
    const float* x     = (const float*)d_in[0];   // [2,2048,2048]
    const float* fc    = (const float*)d_in[1];   // [2048,32,2]
    // d_in[2] = mask (causal, hardcoded)
    const float* wqkv  = (const float*)d_in[3];   // [3072,2048]
    const float* wo    = (const float*)d_in[4];   // [2048,2048]
    float* out = (float*)d_out;                   // [2,2048,2048]

    void *p_x, *p_wq, *p_ao, *p_wo;
    cudaGetSymbolAddress(&p_x,  g_x);
    cudaGetSymbolAddress(&p_wq, g_wq);
    cudaGetSymbolAddress(&p_ao, g_ao);
    cudaGetSymbolAddress(&p_wo, g_wo);

    cudaFuncSetAttribute(gemm_qkv_kernel,
                         cudaFuncAttributeMaxDynamicSharedMemorySize, GT_SMEM_BYTES);
    cudaFuncSetAttribute(gemm_hmma_kernel,
                         cudaFuncAttributeMaxDynamicSharedMemorySize, GT_SMEM_BYTES);

    const int M = BSZ * SEQ;                      // 4096

    // 0) all fp32 -> fp16 conversions in one launch
    conv_all_kernel<<<(CN1 + CN2 + CN3) / 256, 256>>>(x, wqkv, wo);

    // 1) QKV projection with fused RoPE + scatter -> g_q / g_k / g_v
    gemm_qkv_kernel<<<dim3(QKV_N / 128, M / 128), 256, GT_SMEM_BYTES>>>(
        (const __half*)p_x, (const __half*)p_wq, fc, DIM);

    // 2) causal flash attention -> g_ao [b,s,h*d] (fp16)
    flash_hmma_kernel<<<dim3(SEQ / 128, NH, BSZ), 256>>>();

    // 3) output projection -> fp32
    gemm_hmma_kernel<<<dim3(DIM / 128, M / 128), 256, GT_SMEM_BYTES>>>(
        (const __half*)p_ao, (const __half*)p_wo,
        out, M, DIM, DIM);
}

// round 14
// speedup vs baseline: 7.2006x; 1.0096x over previous
#include <cuda_runtime.h>
#include <cuda_fp16.h>
#include <cstdint>
#include <cstddef>

#define BSZ 2
#define SEQ 2048
#define DIM 2048
#define NH 32
#define NKV 8
#define HD 64
#define QKV_N ((NH + 2*NKV)*HD)   // 3072

// ---------------- scratch (static device globals; no allocation) -----------
__device__ __half g_x  [(size_t)BSZ*SEQ*DIM];
__device__ __half g_wq [(size_t)QKV_N*DIM];
__device__ __half g_ao [(size_t)BSZ*SEQ*DIM];
__device__ __half g_wo [(size_t)DIM*DIM];

__device__ __half g_q  [(size_t)BSZ*NH *SEQ*HD];   // [b,h,s,d] (pre-scaled 1/8)
__device__ __half g_k  [(size_t)BSZ*NKV*SEQ*HD];   // [b,kv,s,d]
__device__ __half g_v  [(size_t)BSZ*NKV*HD*SEQ];   // [b,kv,d,s] transposed

// ---------------- small PTX helpers (sm_80-baseline ISA only) ---------------
__device__ __forceinline__ uint32_t smem_to_u32(const void* p) {
    uint32_t a;
    asm("{ .reg .u64 t; cvta.to.shared.u64 t, %1; cvt.u32.u64 %0, t; }"
        : "=r"(a) : "l"(p));
    return a;
}
__device__ __forceinline__ void cp_async16(uint32_t dst, const void* src) {
    asm volatile("cp.async.cg.shared.global [%0], [%1], 16;"
                 :: "r"(dst), "l"(src) : "memory");
}
#define CP_COMMIT() asm volatile("cp.async.commit_group;" ::: "memory")
#define CP_WAIT0()  asm volatile("cp.async.wait_group 0;" ::: "memory")

__device__ __forceinline__ void ldsm4(uint32_t* r, uint32_t addr) {
    asm volatile("ldmatrix.sync.aligned.m8n8.x4.shared.b16 {%0,%1,%2,%3}, [%4];"
        : "=r"(r[0]), "=r"(r[1]), "=r"(r[2]), "=r"(r[3]) : "r"(addr));
}

// D += A(16x16 fp16) * B(16x8 fp16), fp32 accum
__device__ __forceinline__ void mma16816(float* d, const uint32_t* a,
                                         const uint32_t* b) {
    asm volatile(
        "mma.sync.aligned.m16n8k16.row.col.f32.f16.f16.f32 "
        "{%0,%1,%2,%3}, {%4,%5,%6,%7}, {%8,%9}, {%0,%1,%2,%3};"
        : "+f"(d[0]), "+f"(d[1]), "+f"(d[2]), "+f"(d[3])
        : "r"(a[0]), "r"(a[1]), "r"(a[2]), "r"(a[3]), "r"(b[0]), "r"(b[1]));
}

// ---------------- fused conversion kernel (x, wqkv, wo in one launch) --------
#define CN1 (BSZ*SEQ*DIM/4)        // 2097152
#define CN2 (QKV_N*DIM/4)          // 1572864
#define CN3 (DIM*DIM/4)            // 1048576

__global__ void conv_all_kernel(const float* __restrict__ x,
                                const float* __restrict__ wq,
                                const float* __restrict__ wo)
{
    int i = blockIdx.x * 256 + threadIdx.x;
    const float* src;
    __half* dst;
    int j;
    if (i < CN1)              { src = x;  dst = g_x;  j = i; }
    else if (i < CN1 + CN2)   { src = wq; dst = g_wq; j = i - CN1; }
    else                      { src = wo; dst = g_wo; j = i - CN1 - CN2; }
    float4 v = ((const float4*)src)[j];
    ((__half2*)dst)[2*j]   = __floats2half2_rn(v.x, v.y);
    ((__half2*)dst)[2*j+1] = __floats2half2_rn(v.z, v.w);
}

// ---------------- GEMM core (shared mainloop) --------------------------------
// K-chunk 64, 2-stage cp.async pipeline, 128x128 tiles, 8 warps.
#define GSTR 72
#define TILE_BYTES (128 * GSTR * 2)             // 18432
#define GT_SMEM_BYTES (2 * 2 * TILE_BYTES)      // 73728

struct GemmCtx {
    int wm, wn, lr, lc;
    float acc[4][4][4];
};

__device__ __forceinline__ void gemm_mainloop(
    GemmCtx& cx, const __half* A, const __half* B,
    uint32_t sbase, int bm, int bn, int K)
{
    const int t    = threadIdx.x;
    const int wid  = t >> 5, lane = t & 31;
    cx.wm = (wid & 1) * 64;
    cx.wn = (wid >> 1) * 32;
    cx.lr = lane >> 2;
    cx.lc = lane & 3;

    const int arow = (lane & 7) + ((lane >> 3) & 1) * 8;
    const int acol = (lane >> 4) * 8;
    const uint32_t aoff = (uint32_t)(arow * GSTR + acol) * 2;
    const int brow = (lane & 7) + ((lane >> 4) & 1) * 8;
    const int bcol = ((lane >> 3) & 1) * 8;
    const uint32_t boff = (uint32_t)(brow * GSTR + bcol) * 2;

#pragma unroll
    for (int mi = 0; mi < 4; ++mi)
#pragma unroll
        for (int ni = 0; ni < 4; ++ni)
#pragma unroll
            for (int q = 0; q < 4; ++q) cx.acc[mi][ni][q] = 0.f;

    const int nch = K / 64;

    auto load_chunk = [&](int buf, int kc) {
        const __half* gA = A + (size_t)bm * K + kc * 64;
        const __half* gB = B + (size_t)bn * K + kc * 64;
        const uint32_t sdA = sbase + buf * 2 * TILE_BYTES;
        const uint32_t sdB = sdA + TILE_BYTES;
#pragma unroll
        for (int i = 0; i < 4; ++i) {
            int c   = t + i * 256;
            int row = c >> 3, cc = c & 7;
            cp_async16(sdA + (uint32_t)(row * GSTR * 2) + cc * 16,
                       gA + (size_t)row * K + cc * 8);
            cp_async16(sdB + (uint32_t)(row * GSTR * 2) + cc * 16,
                       gB + (size_t)row * K + cc * 8);
        }
    };

    load_chunk(0, 0); CP_COMMIT();

    for (int c = 0; c < nch; ++c) {
        CP_WAIT0();
        __syncthreads();
        if (c + 1 < nch) { load_chunk((c + 1) & 1, c + 1); CP_COMMIT(); }

        const int buf = c & 1;
        const uint32_t uA = sbase + buf * 2 * TILE_BYTES;
        const uint32_t uB = uA + TILE_BYTES;

#pragma unroll
        for (int ks = 0; ks < 4; ++ks) {
            uint32_t a4[4][4], b4[2][4];
#pragma unroll
            for (int mi = 0; mi < 4; ++mi) {
                const uint32_t ra = (uint32_t)((cx.wm + mi * 16) * GSTR) * 2 + ks * 32;
                ldsm4(a4[mi], uA + ra + aoff);
            }
#pragma unroll
            for (int p = 0; p < 2; ++p) {
                const uint32_t rb = (uint32_t)((cx.wn + p * 16) * GSTR) * 2 + ks * 32;
                ldsm4(b4[p], uB + rb + boff);
            }
#pragma unroll
            for (int mi = 0; mi < 4; ++mi)
#pragma unroll
                for (int ni = 0; ni < 4; ++ni)
                    mma16816(cx.acc[mi][ni], a4[mi], &b4[ni >> 1][(ni & 1) * 2]);
        }
    }
}

// QKV GEMM with fused RoPE + Q/K/V scatter.
// Column tiles: bn in [0,2048) = Q (rope, scale 1/8), [2048,2560) = K (rope),
// [2560,3072) = V (transpose to [d,s] via smem staging).
__global__ __launch_bounds__(256, 2)
void gemm_qkv_kernel(const __half* __restrict__ A,
                     const __half* __restrict__ B,
                     const float* __restrict__ fc, int K)
{
    extern __shared__ __half sm[];
    const uint32_t sbase = smem_to_u32(sm);
    const int bm = blockIdx.y * 128, bn = blockIdx.x * 128;
    const int t  = threadIdx.x;

    GemmCtx cx;
    gemm_mainloop(cx, A, B, sbase, bm, bn, K);

    if (bn >= DIM + NKV * HD) {
        // ---- V: stage acc into smem as [d][s], then coalesced store ----
        __syncthreads();   // mainloop smem reads complete in all warps
#pragma unroll
        for (int mi = 0; mi < 4; ++mi) {
#pragma unroll
            for (int ni = 0; ni < 4; ++ni) {
                const int d = cx.wn + ni * 8 + cx.lc * 2;
                const float* a = cx.acc[mi][ni];
#pragma unroll
                for (int rh = 0; rh < 2; ++rh) {
                    const int s = cx.wm + mi * 16 + cx.lr + rh * 8;
                    sm[(d    ) * 136 + s] = __float2half_rn(a[rh*2+0]);
                    sm[(d + 1) * 136 + s] = __float2half_rn(a[rh*2+1]);
                }
            }
        }
        __syncthreads();
        const int c2b = bn - DIM - NKV * HD;
        const int b = bm >> 11;
        const int s0 = bm & (SEQ - 1);
#pragma unroll
        for (int it = 0; it < 8; ++it) {
            int idx = t + it * 256;          // 2048 = 128 d x 16 chunks
            int d  = idx >> 4, sc = (idx & 15) * 8;
            int kv = (c2b + d) >> 6, dd = (c2b + d) & 63;
            uint4 val = *(const uint4*)&sm[d * 136 + sc];
            *(uint4*)&g_v[(((size_t)(b * NKV + kv)) * HD + dd) * SEQ + s0 + sc] = val;
        }
        return;
    }

#pragma unroll
    for (int mi = 0; mi < 4; ++mi) {
        const int row = bm + cx.wm + mi * 16 + cx.lr;   // row and row+8
#pragma unroll
        for (int ni = 0; ni < 4; ++ni) {
            const int col = bn + cx.wn + ni * 8 + cx.lc * 2;
            const float* a = cx.acc[mi][ni];
            if (bn < DIM) {
                // Q: rope + 1/8 scale -> g_q[b,h,s,d]
                const int h = col >> 6, d = col & 63;
#pragma unroll
                for (int rh = 0; rh < 2; ++rh) {
                    const int r = row + rh * 8;
                    const int s = r & (SEQ - 1), b = r >> 11;
                    float2 cs = *(const float2*)&fc[s * HD + d];
                    float v0 = (a[rh*2+0] * cs.x - a[rh*2+1] * cs.y) * 0.125f;
                    float v1 = (a[rh*2+1] * cs.x + a[rh*2+0] * cs.y) * 0.125f;
                    *(__half2*)&g_q[(((size_t)(b*NH+h))*SEQ + s)*HD + d] =
                        __floats2half2_rn(v0, v1);
                }
            } else {
                // K: rope -> g_k[b,kv,s,d]
                const int c2 = col - DIM;
                const int kv = c2 >> 6, d = c2 & 63;
#pragma unroll
                for (int rh = 0; rh < 2; ++rh) {
                    const int r = row + rh * 8;
                    const int s = r & (SEQ - 1), b = r >> 11;
                    float2 cs = *(const float2*)&fc[s * HD + d];
                    float v0 = a[rh*2+0] * cs.x - a[rh*2+1] * cs.y;
                    float v1 = a[rh*2+1] * cs.x + a[rh*2+0] * cs.y;
                    *(__half2*)&g_k[(((size_t)(b*NKV+kv))*SEQ + s)*HD + d] =
                        __floats2half2_rn(v0, v1);
                }
            }
        }
    }
}

// Generic GEMM: C fp32 = A[M,K] * B[N,K]^T (out-projection)
__global__ __launch_bounds__(256, 2)
void gemm_hmma_kernel(const __half* __restrict__ A,
                      const __half* __restrict__ B,
                      float* __restrict__ C, int M, int N, int K)
{
    extern __shared__ __half sm[];
    const uint32_t sbase = smem_to_u32(sm);
    const int bm = blockIdx.y * 128, bn = blockIdx.x * 128;

    GemmCtx cx;
    gemm_mainloop(cx, A, B, sbase, bm, bn, K);

#pragma unroll
    for (int mi = 0; mi < 4; ++mi) {
        const int row = bm + cx.wm + mi * 16 + cx.lr;
#pragma unroll
        for (int ni = 0; ni < 4; ++ni) {
            const int col = bn + cx.wn + ni * 8 + cx.lc * 2;
            *(float2*)&C[(size_t)row * N + col] =
                make_float2(cx.acc[mi][ni][0], cx.acc[mi][ni][1]);
            *(float2*)&C[(size_t)(row + 8) * N + col] =
                make_float2(cx.acc[mi][ni][2], cx.acc[mi][ni][3]);
        }
    }
}

// ---------------- flash attention on HMMA ------------------------------------
// Paired Q-tiles: each CTA processes qb = bx and qb = 15-bx sequentially,
// giving every CTA exactly 34 KV-tiles (uniform work, 512 CTAs).
#define FSTR 72
#define FTILE_BYTES (64 * FSTR * 2)   // 9216

__global__ __launch_bounds__(256, 2)
void flash_hmma_kernel()
{
    __shared__ __half sK[2][64 * FSTR];
    __shared__ __half sV[2][64 * FSTR];   // [d][key]

    const int t = threadIdx.x;
    const int w = t >> 5, lane = t & 31;
    const int g = lane >> 2, tg = lane & 3;
    const int bx = blockIdx.x, h = blockIdx.y, b = blockIdx.z;
    const int kvh = h >> 2;

    const uint32_t uK0 = smem_to_u32(sK);
    const uint32_t uV0 = smem_to_u32(sV);

    const int brow = (lane & 7) + ((lane >> 4) & 1) * 8;
    const int bcol = ((lane >> 3) & 1) * 8;
    const uint32_t boff = (uint32_t)(brow * FSTR + bcol) * 2;

    const __half* gk = g_k + ((size_t)(b * NKV + kvh)) * SEQ * HD;
    const __half* gv = g_v + ((size_t)(b * NKV + kvh)) * HD * SEQ;

    auto load_tile = [&](int buf, int jb) {
#pragma unroll
        for (int cc = 0; cc < 2; ++cc) {
            int c   = t + cc * 256;
            int row = c >> 3, col = (c & 7) * 8;
            uint32_t so = (uint32_t)buf * FTILE_BYTES + (uint32_t)(row * FSTR + col) * 2;
            cp_async16(uK0 + so, &gk[(size_t)(jb * 64 + row) * HD + col]);
            cp_async16(uV0 + so, &gv[(size_t)row * SEQ + jb * 64 + col]);
        }
    };

    const float L2E = 1.4426950408889634f;

#pragma unroll 1
    for (int pass = 0; pass < 2; ++pass) {
        const int qb = pass ? (15 - bx) : bx;
        const int qrow0 = qb * 128 + w * 16;

        // Q fragments, 4 k-chunks of 16 over d=64
        uint32_t qf[4][4];
        {
            const __half* gq = g_q + (((size_t)(b*NH+h))*SEQ + qrow0)*HD;
#pragma unroll
            for (int kk = 0; kk < 4; ++kk) {
                int d0 = kk * 16 + tg * 2;
                qf[kk][0] = *(const uint32_t*)&gq[(size_t)(g    ) * HD + d0];
                qf[kk][1] = *(const uint32_t*)&gq[(size_t)(g + 8) * HD + d0];
                qf[kk][2] = *(const uint32_t*)&gq[(size_t)(g    ) * HD + d0 + 8];
                qf[kk][3] = *(const uint32_t*)&gq[(size_t)(g + 8) * HD + d0 + 8];
            }
        }

        float m0 = -1e30f, m1 = -1e30f, l0 = 0.f, l1 = 0.f;
        float o[8][4];
#pragma unroll
        for (int ni = 0; ni < 8; ++ni)
#pragma unroll
            for (int q = 0; q < 4; ++q) o[ni][q] = 0.f;

        const int ntile = 2 * qb + 2;
        load_tile(0, 0); CP_COMMIT();

        for (int jb = 0; jb < ntile; ++jb) {
            const int buf = jb & 1;
            CP_WAIT0();
            __syncthreads();
            if (jb + 1 < ntile) { load_tile(buf ^ 1, jb + 1); CP_COMMIT(); }

            if (jb * 64 <= qrow0 + 15) {
                const uint32_t uK = uK0 + buf * FTILE_BYTES;
                const uint32_t uV = uV0 + buf * FTILE_BYTES;

                // S = Q K^T
                float s[8][4];
#pragma unroll
                for (int ni = 0; ni < 8; ++ni)
                    s[ni][0] = s[ni][1] = s[ni][2] = s[ni][3] = 0.f;

#pragma unroll
                for (int kk = 0; kk < 4; ++kk)
#pragma unroll
                    for (int p = 0; p < 4; ++p) {
                        const uint32_t rb = (uint32_t)(p * 16 * FSTR) * 2 + kk * 32;
                        uint32_t k4[4];
                        ldsm4(k4, uK + rb + boff);
                        mma16816(s[2*p],   qf[kk], k4 + 0);
                        mma16816(s[2*p+1], qf[kk], k4 + 2);
                    }

                // causal mask (diagonal tiles only)
                if (jb * 64 + 63 > qrow0) {
                    const int cb = jb * 64 + tg * 2;
                    const int r0 = qrow0 + g, r1 = r0 + 8;
#pragma unroll
                    for (int ni = 0; ni < 8; ++ni) {
                        int c0 = cb + ni * 8, c1 = c0 + 1;
                        if (c0 > r0) s[ni][0] = -1e30f;
                        if (c1 > r0) s[ni][1] = -1e30f;
                        if (c0 > r1) s[ni][2] = -1e30f;
                        if (c1 > r1) s[ni][3] = -1e30f;
                    }
                }

                // online softmax: max in fp32, exp via ex2.approx.f16x2
                float mt0 = -1e30f, mt1 = -1e30f;
#pragma unroll
                for (int ni = 0; ni < 8; ++ni) {
                    mt0 = fmaxf(mt0, fmaxf(s[ni][0], s[ni][1]));
                    mt1 = fmaxf(mt1, fmaxf(s[ni][2], s[ni][3]));
                }
                mt0 = fmaxf(mt0, __shfl_xor_sync(0xffffffffu, mt0, 1));
                mt0 = fmaxf(mt0, __shfl_xor_sync(0xffffffffu, mt0, 2));
                mt1 = fmaxf(mt1, __shfl_xor_sync(0xffffffffu, mt1, 1));
                mt1 = fmaxf(mt1, __shfl_xor_sync(0xffffffffu, mt1, 2));
                float mn0 = fmaxf(m0, mt0), mn1 = fmaxf(m1, mt1);
                float a0 = __expf(m0 - mn0), a1 = __expf(m1 - mn1);
                m0 = mn0; m1 = mn1;
                const float b0 = mn0 * L2E, b1 = mn1 * L2E;

                uint32_t pe0[8], pe1[8];        // fp16x2 P: rows g / g+8
                float rs0 = 0.f, rs1 = 0.f;
#pragma unroll
                for (int ni = 0; ni < 8; ++ni) {
                    __half2 e01 = h2exp2(__floats2half2_rn(
                        fmaf(s[ni][0], L2E, -b0), fmaf(s[ni][1], L2E, -b0)));
                    __half2 e23 = h2exp2(__floats2half2_rn(
                        fmaf(s[ni][2], L2E, -b1), fmaf(s[ni][3], L2E, -b1)));
                    pe0[ni] = *(uint32_t*)&e01;
                    pe1[ni] = *(uint32_t*)&e23;
                    float2 f01 = __half22float2(e01);
                    float2 f23 = __half22float2(e23);
                    rs0 += f01.x + f01.y;
                    rs1 += f23.x + f23.y;
                }
                l0 = l0 * a0 + rs0;
                l1 = l1 * a1 + rs1;
#pragma unroll
                for (int ni = 0; ni < 8; ++ni) {
                    o[ni][0] *= a0; o[ni][1] *= a0;
                    o[ni][2] *= a1; o[ni][3] *= a1;
                }

                // O += P V (P fragments are the packed exp outputs)
#pragma unroll
                for (int kk = 0; kk < 4; ++kk) {
                    uint32_t ph[4];
                    ph[0] = pe0[2*kk];     ph[1] = pe1[2*kk];
                    ph[2] = pe0[2*kk + 1]; ph[3] = pe1[2*kk + 1];
#pragma unroll
                    for (int p = 0; p < 4; ++p) {
                        const uint32_t rb = (uint32_t)(p * 16 * FSTR) * 2 + kk * 32;
                        uint32_t v4[4];
                        ldsm4(v4, uV + rb + boff);
                        mma16816(o[2*p],   ph, v4 + 0);
                        mma16816(o[2*p+1], ph, v4 + 2);
                    }
                }
            }
        }

        // finalize this pass: write fp16 (feeds out-projection)
        l0 += __shfl_xor_sync(0xffffffffu, l0, 1);
        l0 += __shfl_xor_sync(0xffffffffu, l0, 2);
        l1 += __shfl_xor_sync(0xffffffffu, l1, 1);
        l1 += __shfl_xor_sync(0xffffffffu, l1, 2);
        const float inv0 = 1.f / l0, inv1 = 1.f / l1;

        const int r0 = qrow0 + g, r1 = r0 + 8;
#pragma unroll
        for (int ni = 0; ni < 8; ++ni) {
            const int col = h * HD + ni * 8 + tg * 2;
            *(__half2*)&g_ao[(size_t)(b * SEQ + r0) * DIM + col] =
                __floats2half2_rn(o[ni][0] * inv0, o[ni][1] * inv0);
            *(__half2*)&g_ao[(size_t)(b * SEQ + r1) * DIM + col] =
                __floats2half2_rn(o[ni][2] * inv1, o[ni][3] * inv1);
        }
        __syncthreads();   // pass state / smem reuse boundary
    }
}

// ---------------- launcher ---------------------------------------------------
extern "C" void kernel_launch(void* const* d_in, const int* in_sizes, int n_in,
                              void* d_out, int out_size)
{
    const float* x     = (const float*)d_in[0];   // [2,2048,2048]
    const float* fc    = (const float*)d_in[1];   // [2048,32,2]
    // d_in[2] = mask (causal, hardcoded)
    const float* wqkv  = (const float*)d_in[3];   // [3072,2048]
    const float* wo    = (const float*)d_in[4];   // [2048,2048]
    float* out = (float*)d_out;                   // [2,2048,2048]

    void *p_x, *p_wq, *p_ao, *p_wo;
    cudaGetSymbolAddress(&p_x,  g_x);
    cudaGetSymbolAddress(&p_wq, g_wq);
    cudaGetSymbolAddress(&p_ao, g_ao);
    cudaGetSymbolAddress(&p_wo, g_wo);

    cudaFuncSetAttribute(gemm_qkv_kernel,
                         cudaFuncAttributeMaxDynamicSharedMemorySize, GT_SMEM_BYTES);
    cudaFuncSetAttribute(gemm_hmma_kernel,
                         cudaFuncAttributeMaxDynamicSharedMemorySize, GT_SMEM_BYTES);

    const int M = BSZ * SEQ;                      // 4096

    // 0) all fp32 -> fp16 conversions in one launch
    conv_all_kernel<<<(CN1 + CN2 + CN3) / 256, 256>>>(x, wqkv, wo);

    // 1) QKV projection with fused RoPE + scatter -> g_q / g_k / g_v
    gemm_qkv_kernel<<<dim3(QKV_N / 128, M / 128), 256, GT_SMEM_BYTES>>>(
        (const __half*)p_x, (const __half*)p_wq, fc, DIM);

    // 2) causal flash attention (paired Q-tiles) -> g_ao [b,s,h*d] (fp16)
    flash_hmma_kernel<<<dim3(SEQ / 256, NH, BSZ), 256>>>();

    // 3) output projection -> fp32
    gemm_hmma_kernel<<<dim3(DIM / 128, M / 128), 256, GT_SMEM_BYTES>>>(
        (const __half*)p_ao, (const __half*)p_wo,
        out, M, DIM, DIM);
}